// round 1
// baseline (speedup 1.0000x reference)
#include <cuda_runtime.h>
#include <cuda_bf16.h>
#include <math.h>

#define B_    8
#define CIN   512
#define COUT  1024
#define PDIM  2048
#define Hh    8
#define Dd    128
#define NG    32
#define Gc    8

// Scratch (static device globals: allowed; no runtime allocation)
__device__ float g_Q[(size_t)B_ * COUT * PDIM];
__device__ float g_K[(size_t)B_ * COUT * PDIM];
__device__ float g_V[(size_t)B_ * COUT * PDIM];
__device__ float g_S[(size_t)B_ * Hh * PDIM * PDIM];   // 1 GB scores / probs

// ---------------------------------------------------------------------------
// Kernel 1: grouped 1x1 conv + bias -> GroupNorm stats -> normalize+affine+
// LeakyReLU, one block per (ng, b). which selects Q/K/V output buffer.
// ---------------------------------------------------------------------------
__global__ __launch_bounds__(256) void qkv_gn_kernel(
    const float* __restrict__ x, const float* __restrict__ w,
    const float* __restrict__ bias, const float* __restrict__ gw,
    const float* __restrict__ gb, int which)
{
    float* out = (which == 0) ? g_Q : (which == 1) ? g_K : g_V;

    const int ng = blockIdx.x;          // 0..31
    const int b  = blockIdx.y;          // 0..7
    const int c0 = ng * 32;             // first out channel of this norm group
    const int g  = c0 >> 7;             // conv group (128 out-ch per group)
    const int f0 = g * 64;              // first input channel

    __shared__ float xs[64][128];       // input tile [f][p]
    __shared__ float ws[32][64];        // weights for 32 channels
    __shared__ float bs[32], gws[32], gbs[32];
    __shared__ float red[256];
    __shared__ float stats[2];

    const int t = threadIdx.x;

    for (int i = t; i < 32 * 64; i += 256) {
        int c = i >> 6, f = i & 63;
        ws[c][f] = w[(size_t)(c0 + c) * 64 + f];
    }
    if (t < 32) { bs[t] = bias[c0 + t]; gws[t] = gw[c0 + t]; gbs[t] = gb[c0 + t]; }

    const int pl = t & 31;              // p lane
    const int cq = t >> 5;              // channel quad 0..7

    const float* xb = x + (size_t)b * CIN * PDIM + (size_t)f0 * PDIM;
    float* ob = out + (size_t)b * COUT * PDIM + (size_t)c0 * PDIM;

    float sum = 0.f, sumsq = 0.f;

    for (int pt = 0; pt < 16; pt++) {
        __syncthreads();
        for (int i = t; i < 64 * 128; i += 256) {
            int r = i >> 7, cc = i & 127;
            xs[r][cc] = xb[(size_t)r * PDIM + pt * 128 + cc];
        }
        __syncthreads();

        float acc[4][4];
        #pragma unroll
        for (int v = 0; v < 4; v++)
            #pragma unroll
            for (int u = 0; u < 4; u++) acc[v][u] = bs[cq * 4 + v];

        #pragma unroll
        for (int f = 0; f < 64; f++) {
            float xv[4];
            #pragma unroll
            for (int u = 0; u < 4; u++) xv[u] = xs[f][pl + 32 * u];
            #pragma unroll
            for (int v = 0; v < 4; v++) {
                float wv = ws[cq * 4 + v][f];
                #pragma unroll
                for (int u = 0; u < 4; u++) acc[v][u] += wv * xv[u];
            }
        }

        #pragma unroll
        for (int v = 0; v < 4; v++) {
            int c = cq * 4 + v;
            #pragma unroll
            for (int u = 0; u < 4; u++) {
                float a = acc[v][u];
                sum += a; sumsq += a * a;
                ob[(size_t)c * PDIM + pt * 128 + pl + 32 * u] = a;
            }
        }
    }

    // block reduce sum
    red[t] = sum; __syncthreads();
    for (int s = 128; s > 0; s >>= 1) { if (t < s) red[t] += red[t + s]; __syncthreads(); }
    if (t == 0) stats[0] = red[0] * (1.0f / 65536.0f);
    __syncthreads();
    red[t] = sumsq; __syncthreads();
    for (int s = 128; s > 0; s >>= 1) { if (t < s) red[t] += red[t + s]; __syncthreads(); }
    if (t == 0) {
        float mu = stats[0];
        float var = red[0] * (1.0f / 65536.0f) - mu * mu;
        stats[1] = rsqrtf(var + 1e-5f);
    }
    __syncthreads();
    const float mu = stats[0], inv = stats[1];

    // normalize + affine + LeakyReLU (re-read raw y, own block's region)
    for (int i = t; i < 32 * PDIM; i += 256) {
        int c = i >> 11, p = i & (PDIM - 1);
        float y = ob[(size_t)c * PDIM + p];
        float z = (y - mu) * inv * gws[c] + gbs[c];
        ob[(size_t)c * PDIM + p] = (z >= 0.f) ? z : 0.1f * z;
    }
}

// ---------------------------------------------------------------------------
// Kernel 2: scores S[bh][i][j] = scale * sum_c K[c,i] V[c,j]
// 128x128 output tile, k = c (128), 8x8 microtile per thread.
// ---------------------------------------------------------------------------
__global__ __launch_bounds__(256) void scores_kernel()
{
    const int bh = blockIdx.z;
    const int b = bh >> 3, h = bh & 7;
    const int j0 = blockIdx.x * 128;
    const int i0 = blockIdx.y * 128;

    const float* Kb = g_K + ((size_t)b * COUT + h * Dd) * PDIM;
    const float* Vb = g_V + ((size_t)b * COUT + h * Dd) * PDIM;
    float* Sb = g_S + (size_t)bh * PDIM * PDIM;

    __shared__ float as[16][128];   // [kc][i]
    __shared__ float bs2[16][128];  // [kc][j]

    const int t = threadIdx.x;
    const int tx = t & 15, ty = t >> 4;

    float acc[8][8];
    #pragma unroll
    for (int m = 0; m < 8; m++)
        #pragma unroll
        for (int n = 0; n < 8; n++) acc[m][n] = 0.f;

    for (int kc0 = 0; kc0 < Dd; kc0 += 16) {
        __syncthreads();
        #pragma unroll
        for (int r = 0; r < 8; r++) {
            int idx = t + 256 * r;
            int kc = idx >> 7, ii = idx & 127;
            as[kc][ii]  = Kb[(size_t)(kc0 + kc) * PDIM + i0 + ii];
            bs2[kc][ii] = Vb[(size_t)(kc0 + kc) * PDIM + j0 + ii];
        }
        __syncthreads();

        #pragma unroll
        for (int kc = 0; kc < 16; kc++) {
            float af[8], bf[8];
            #pragma unroll
            for (int m = 0; m < 8; m++) af[m] = as[kc][ty + 16 * m];
            #pragma unroll
            for (int n = 0; n < 8; n++) bf[n] = bs2[kc][tx + 16 * n];
            #pragma unroll
            for (int m = 0; m < 8; m++)
                #pragma unroll
                for (int n = 0; n < 8; n++) acc[m][n] += af[m] * bf[n];
        }
    }

    const float scale = 0.088388347648318447f;  // 1/sqrt(128)
    #pragma unroll
    for (int m = 0; m < 8; m++) {
        size_t row = (size_t)(i0 + ty + 16 * m) * PDIM;
        #pragma unroll
        for (int n = 0; n < 8; n++)
            Sb[row + j0 + tx + 16 * n] = acc[m][n] * scale;
    }
}

// ---------------------------------------------------------------------------
// Kernel 3: softmax over last axis of S (rows of 2048). One block per row.
// ---------------------------------------------------------------------------
__global__ __launch_bounds__(256) void softmax_kernel()
{
    float* row = g_S + (size_t)blockIdx.x * PDIM;
    const int t = threadIdx.x;
    __shared__ float red[256];
    __shared__ float bc;

    float v[8];
    float m = -1e30f;
    #pragma unroll
    for (int k = 0; k < 8; k++) { v[k] = row[t + 256 * k]; m = fmaxf(m, v[k]); }
    red[t] = m; __syncthreads();
    for (int s = 128; s > 0; s >>= 1) { if (t < s) red[t] = fmaxf(red[t], red[t + s]); __syncthreads(); }
    if (t == 0) bc = red[0];
    __syncthreads();
    const float M = bc;

    float sum = 0.f;
    #pragma unroll
    for (int k = 0; k < 8; k++) { v[k] = __expf(v[k] - M); sum += v[k]; }
    __syncthreads();
    red[t] = sum; __syncthreads();
    for (int s = 128; s > 0; s >>= 1) { if (t < s) red[t] += red[t + s]; __syncthreads(); }
    if (t == 0) bc = 1.0f / red[0];
    __syncthreads();
    const float inv = bc;
    #pragma unroll
    for (int k = 0; k < 8; k++) row[t + 256 * k] = v[k] * inv;
}

// ---------------------------------------------------------------------------
// Kernel 4: out[c,i] = sum_j A[i,j] Q[c,j].  BM=128 (c, all), BN=128 (i),
// BK=16 (j). Transposed smem staging for coalesced global reads.
// ---------------------------------------------------------------------------
__global__ __launch_bounds__(256) void out_kernel(float* __restrict__ out)
{
    const int bh = blockIdx.y;
    const int b = bh >> 3, h = bh & 7;
    const int i0 = blockIdx.x * 128;

    const float* Qb = g_Q + ((size_t)b * COUT + h * Dd) * PDIM;
    const float* Ab = g_S + (size_t)bh * PDIM * PDIM;
    float* Ob = out + ((size_t)b * COUT + h * Dd) * PDIM;

    __shared__ float qs[16][129];   // [jj][c]
    __shared__ float as4[16][129];  // [jj][i]

    const int t = threadIdx.x;
    const int tx = t & 15, ty = t >> 4;
    const int lr = t >> 1;          // row index for staging loads (0..127)
    const int lj = (t & 1) * 8;     // jj base

    float acc[8][8];
    #pragma unroll
    for (int m = 0; m < 8; m++)
        #pragma unroll
        for (int n = 0; n < 8; n++) acc[m][n] = 0.f;

    for (int j0 = 0; j0 < PDIM; j0 += 16) {
        __syncthreads();
        // Q[c][j0+jj] -> qs[jj][c]
        #pragma unroll
        for (int r = 0; r < 8; r++)
            qs[lj + r][lr] = Qb[(size_t)lr * PDIM + j0 + lj + r];
        // A[i0+ii][j0+jj] -> as4[jj][ii]
        #pragma unroll
        for (int r = 0; r < 8; r++)
            as4[lj + r][lr] = Ab[(size_t)(i0 + lr) * PDIM + j0 + lj + r];
        __syncthreads();

        #pragma unroll
        for (int jj = 0; jj < 16; jj++) {
            float qf[8], af[8];
            #pragma unroll
            for (int m = 0; m < 8; m++) qf[m] = qs[jj][ty + 16 * m];
            #pragma unroll
            for (int n = 0; n < 8; n++) af[n] = as4[jj][tx + 16 * n];
            #pragma unroll
            for (int m = 0; m < 8; m++)
                #pragma unroll
                for (int n = 0; n < 8; n++) acc[m][n] += qf[m] * af[n];
        }
    }

    #pragma unroll
    for (int m = 0; m < 8; m++) {
        size_t row = (size_t)(ty + 16 * m) * PDIM;
        #pragma unroll
        for (int n = 0; n < 8; n++)
            Ob[row + i0 + tx + 16 * n] = acc[m][n];
    }
}

// ---------------------------------------------------------------------------
extern "C" void kernel_launch(void* const* d_in, const int* in_sizes, int n_in,
                              void* d_out, int out_size)
{
    const float* x   = (const float*)d_in[0];
    const float* wq  = (const float*)d_in[1];
    const float* bq  = (const float*)d_in[2];
    const float* gw1 = (const float*)d_in[3];
    const float* gb1 = (const float*)d_in[4];
    const float* wk  = (const float*)d_in[5];
    const float* bk  = (const float*)d_in[6];
    const float* gw2 = (const float*)d_in[7];
    const float* gb2 = (const float*)d_in[8];
    const float* wv  = (const float*)d_in[9];
    const float* bv  = (const float*)d_in[10];
    const float* gw3 = (const float*)d_in[11];
    const float* gb3 = (const float*)d_in[12];
    float* out = (float*)d_out;

    dim3 g1(NG, B_);
    qkv_gn_kernel<<<g1, 256>>>(x, wq, bq, gw1, gb1, 0);
    qkv_gn_kernel<<<g1, 256>>>(x, wk, bk, gw2, gb2, 1);
    qkv_gn_kernel<<<g1, 256>>>(x, wv, bv, gw3, gb3, 2);

    dim3 g2(PDIM / 128, PDIM / 128, B_ * Hh);
    scores_kernel<<<g2, 256>>>();

    softmax_kernel<<<B_ * Hh * PDIM, 256>>>();

    dim3 g4(PDIM / 128, B_ * Hh);
    out_kernel<<<g4, 256>>>(out);
}

// round 2
// speedup vs baseline: 1.2550x; 1.2550x over previous
#include <cuda_runtime.h>
#include <cuda_bf16.h>
#include <math.h>
#include <stdint.h>

#define B_    8
#define CIN   512
#define COUT  1024
#define PDIM  2048
#define Hh    8
#define Dd    128
#define NG    32
#define Gc    8

// Scratch (static device globals: allowed; no runtime allocation)
__device__ float g_Q[(size_t)B_ * COUT * PDIM];
__device__ float g_K[(size_t)B_ * COUT * PDIM];
__device__ float g_V[(size_t)B_ * COUT * PDIM];
__device__ float g_S[(size_t)B_ * Hh * PDIM * PDIM];   // 1 GB scores / probs

// ---------------------------------------------------------------------------
// tf32 helpers
// ---------------------------------------------------------------------------
__device__ __forceinline__ unsigned f2tf32(float x) {
    unsigned r;
    asm("cvt.rna.tf32.f32 %0, %1;" : "=r"(r) : "f"(x));
    return r;
}
__device__ __forceinline__ void tf32_split(float x, unsigned& hi, unsigned& lo) {
    unsigned h;
    asm("cvt.rna.tf32.f32 %0, %1;" : "=r"(h) : "f"(x));
    float r = x - __uint_as_float(h);
    unsigned l;
    asm("cvt.rna.tf32.f32 %0, %1;" : "=r"(l) : "f"(r));
    hi = h; lo = l;
}
__device__ __forceinline__ void mma_tf32(float (&c)[4], const unsigned (&a)[4],
                                          const unsigned (&b)[2]) {
    asm volatile(
        "mma.sync.aligned.m16n8k8.row.col.f32.tf32.tf32.f32 "
        "{%0,%1,%2,%3}, {%4,%5,%6,%7}, {%8,%9}, {%0,%1,%2,%3};\n"
        : "+f"(c[0]), "+f"(c[1]), "+f"(c[2]), "+f"(c[3])
        : "r"(a[0]), "r"(a[1]), "r"(a[2]), "r"(a[3]), "r"(b[0]), "r"(b[1]));
}

// ---------------------------------------------------------------------------
// Kernel 1: grouped 1x1 conv + bias -> GroupNorm -> LeakyReLU (unchanged)
// ---------------------------------------------------------------------------
__global__ __launch_bounds__(256) void qkv_gn_kernel(
    const float* __restrict__ x, const float* __restrict__ w,
    const float* __restrict__ bias, const float* __restrict__ gw,
    const float* __restrict__ gb, int which)
{
    float* out = (which == 0) ? g_Q : (which == 1) ? g_K : g_V;

    const int ng = blockIdx.x;
    const int b  = blockIdx.y;
    const int c0 = ng * 32;
    const int g  = c0 >> 7;
    const int f0 = g * 64;

    __shared__ float xs[64][128];
    __shared__ float ws[32][64];
    __shared__ float bs[32], gws[32], gbs[32];
    __shared__ float red[256];
    __shared__ float stats[2];

    const int t = threadIdx.x;

    for (int i = t; i < 32 * 64; i += 256) {
        int c = i >> 6, f = i & 63;
        ws[c][f] = w[(size_t)(c0 + c) * 64 + f];
    }
    if (t < 32) { bs[t] = bias[c0 + t]; gws[t] = gw[c0 + t]; gbs[t] = gb[c0 + t]; }

    const int pl = t & 31;
    const int cq = t >> 5;

    const float* xb = x + (size_t)b * CIN * PDIM + (size_t)f0 * PDIM;
    float* ob = out + (size_t)b * COUT * PDIM + (size_t)c0 * PDIM;

    float sum = 0.f, sumsq = 0.f;

    for (int pt = 0; pt < 16; pt++) {
        __syncthreads();
        for (int i = t; i < 64 * 128; i += 256) {
            int r = i >> 7, cc = i & 127;
            xs[r][cc] = xb[(size_t)r * PDIM + pt * 128 + cc];
        }
        __syncthreads();

        float acc[4][4];
        #pragma unroll
        for (int v = 0; v < 4; v++)
            #pragma unroll
            for (int u = 0; u < 4; u++) acc[v][u] = bs[cq * 4 + v];

        #pragma unroll
        for (int f = 0; f < 64; f++) {
            float xv[4];
            #pragma unroll
            for (int u = 0; u < 4; u++) xv[u] = xs[f][pl + 32 * u];
            #pragma unroll
            for (int v = 0; v < 4; v++) {
                float wv = ws[cq * 4 + v][f];
                #pragma unroll
                for (int u = 0; u < 4; u++) acc[v][u] += wv * xv[u];
            }
        }

        #pragma unroll
        for (int v = 0; v < 4; v++) {
            int c = cq * 4 + v;
            #pragma unroll
            for (int u = 0; u < 4; u++) {
                float a = acc[v][u];
                sum += a; sumsq += a * a;
                ob[(size_t)c * PDIM + pt * 128 + pl + 32 * u] = a;
            }
        }
    }

    red[t] = sum; __syncthreads();
    for (int s = 128; s > 0; s >>= 1) { if (t < s) red[t] += red[t + s]; __syncthreads(); }
    if (t == 0) stats[0] = red[0] * (1.0f / 65536.0f);
    __syncthreads();
    red[t] = sumsq; __syncthreads();
    for (int s = 128; s > 0; s >>= 1) { if (t < s) red[t] += red[t + s]; __syncthreads(); }
    if (t == 0) {
        float mu = stats[0];
        float var = red[0] * (1.0f / 65536.0f) - mu * mu;
        stats[1] = rsqrtf(var + 1e-5f);
    }
    __syncthreads();
    const float mu = stats[0], inv = stats[1];

    for (int i = t; i < 32 * PDIM; i += 256) {
        int c = i >> 11, p = i & (PDIM - 1);
        float y = ob[(size_t)c * PDIM + p];
        float z = (y - mu) * inv * gws[c] + gbs[c];
        ob[(size_t)c * PDIM + p] = (z >= 0.f) ? z : 0.1f * z;
    }
}

// ---------------------------------------------------------------------------
// Kernel 2: scores S[bh][i][j] = scale * sum_c K[c,i] V[c,j]
// tf32 tensor-core GEMM with 3xTF32 precision split.
// Block 128x128, 8 warps (2x4), warp tile 64x32, BK=16.
// ---------------------------------------------------------------------------
__global__ __launch_bounds__(256, 1) void scores_mma_kernel()
{
    const int bh = blockIdx.z;
    const int b = bh >> 3, h = bh & 7;
    const int j0 = blockIdx.x * 128;
    const int i0 = blockIdx.y * 128;

    const float* Kb = g_K + ((size_t)b * COUT + h * Dd) * PDIM;
    const float* Vb = g_V + ((size_t)b * COUT + h * Dd) * PDIM;
    float* Sb = g_S + (size_t)bh * PDIM * PDIM;

    __shared__ unsigned Ahi[16][132], Alo[16][132];
    __shared__ unsigned Bhi[16][132], Blo[16][132];

    const int t = threadIdx.x;
    const int lane = t & 31, w = t >> 5;
    const int wm = w & 1, wn = w >> 1;
    const int gid = lane >> 2, tig = lane & 3;
    const int mbase = wm * 64, nbase = wn * 32;

    const int sk = t >> 4;          // staging row 0..15
    const int sc = (t & 15) * 8;    // staging col base

    float acc[4][4][4];
    #pragma unroll
    for (int mt = 0; mt < 4; mt++)
        #pragma unroll
        for (int nt = 0; nt < 4; nt++)
            #pragma unroll
            for (int r = 0; r < 4; r++) acc[mt][nt][r] = 0.f;

    for (int kc0 = 0; kc0 < Dd; kc0 += 16) {
        __syncthreads();
        {
            const float4* asrc = (const float4*)(Kb + (size_t)(kc0 + sk) * PDIM + i0 + sc);
            const float4* bsrc = (const float4*)(Vb + (size_t)(kc0 + sk) * PDIM + j0 + sc);
            float4 a0 = asrc[0], a1 = asrc[1];
            float4 b0 = bsrc[0], b1 = bsrc[1];
            float av[8] = {a0.x, a0.y, a0.z, a0.w, a1.x, a1.y, a1.z, a1.w};
            float bv[8] = {b0.x, b0.y, b0.z, b0.w, b1.x, b1.y, b1.z, b1.w};
            #pragma unroll
            for (int r = 0; r < 8; r++) {
                unsigned hi, lo;
                tf32_split(av[r], hi, lo);
                Ahi[sk][sc + r] = hi; Alo[sk][sc + r] = lo;
                tf32_split(bv[r], hi, lo);
                Bhi[sk][sc + r] = hi; Blo[sk][sc + r] = lo;
            }
        }
        __syncthreads();

        #pragma unroll
        for (int kk = 0; kk < 16; kk += 8) {
            unsigned ah[4][4], al[4][4];
            #pragma unroll
            for (int mt = 0; mt < 4; mt++) {
                int r0 = mbase + mt * 16 + gid, r1 = r0 + 8;
                ah[mt][0] = Ahi[kk + tig][r0];
                ah[mt][1] = Ahi[kk + tig][r1];
                ah[mt][2] = Ahi[kk + tig + 4][r0];
                ah[mt][3] = Ahi[kk + tig + 4][r1];
                al[mt][0] = Alo[kk + tig][r0];
                al[mt][1] = Alo[kk + tig][r1];
                al[mt][2] = Alo[kk + tig + 4][r0];
                al[mt][3] = Alo[kk + tig + 4][r1];
            }
            unsigned bh2[4][2], bl2[4][2];
            #pragma unroll
            for (int nt = 0; nt < 4; nt++) {
                int c = nbase + nt * 8 + gid;
                bh2[nt][0] = Bhi[kk + tig][c];
                bh2[nt][1] = Bhi[kk + tig + 4][c];
                bl2[nt][0] = Blo[kk + tig][c];
                bl2[nt][1] = Blo[kk + tig + 4][c];
            }
            #pragma unroll
            for (int mt = 0; mt < 4; mt++)
                #pragma unroll
                for (int nt = 0; nt < 4; nt++) {
                    mma_tf32(acc[mt][nt], ah[mt], bh2[nt]);
                    mma_tf32(acc[mt][nt], ah[mt], bl2[nt]);
                    mma_tf32(acc[mt][nt], al[mt], bh2[nt]);
                }
        }
    }

    const float scale = 0.088388347648318447f;  // 1/sqrt(128)
    #pragma unroll
    for (int mt = 0; mt < 4; mt++) {
        int r0 = i0 + mbase + mt * 16 + gid;
        #pragma unroll
        for (int nt = 0; nt < 4; nt++) {
            int c = j0 + nbase + nt * 8 + 2 * tig;
            Sb[(size_t)r0 * PDIM + c]       = acc[mt][nt][0] * scale;
            Sb[(size_t)r0 * PDIM + c + 1]   = acc[mt][nt][1] * scale;
            Sb[(size_t)(r0 + 8) * PDIM + c]     = acc[mt][nt][2] * scale;
            Sb[(size_t)(r0 + 8) * PDIM + c + 1] = acc[mt][nt][3] * scale;
        }
    }
}

// ---------------------------------------------------------------------------
// Kernel 3: softmax over rows of S (unchanged)
// ---------------------------------------------------------------------------
__global__ __launch_bounds__(256) void softmax_kernel()
{
    float* row = g_S + (size_t)blockIdx.x * PDIM;
    const int t = threadIdx.x;
    __shared__ float red[256];
    __shared__ float bc;

    float v[8];
    float m = -1e30f;
    #pragma unroll
    for (int k = 0; k < 8; k++) { v[k] = row[t + 256 * k]; m = fmaxf(m, v[k]); }
    red[t] = m; __syncthreads();
    for (int s = 128; s > 0; s >>= 1) { if (t < s) red[t] = fmaxf(red[t], red[t + s]); __syncthreads(); }
    if (t == 0) bc = red[0];
    __syncthreads();
    const float M = bc;

    float sum = 0.f;
    #pragma unroll
    for (int k = 0; k < 8; k++) { v[k] = __expf(v[k] - M); sum += v[k]; }
    __syncthreads();
    red[t] = sum; __syncthreads();
    for (int s = 128; s > 0; s >>= 1) { if (t < s) red[t] += red[t + s]; __syncthreads(); }
    if (t == 0) bc = 1.0f / red[0];
    __syncthreads();
    const float inv = bc;
    #pragma unroll
    for (int k = 0; k < 8; k++) row[t + 256 * k] = v[k] * inv;
}

// ---------------------------------------------------------------------------
// Kernel 4: out[c,i] = sum_j A[i,j] Q[c,j].  tf32 tensor-core GEMM.
// M=128 (c), N=128 (i tile), K=j (2048), BK=16. Single-pass tf32.
// ---------------------------------------------------------------------------
__global__ __launch_bounds__(256, 1) void out_mma_kernel(float* __restrict__ out)
{
    const int bh = blockIdx.y;
    const int b = bh >> 3, h = bh & 7;
    const int i0 = blockIdx.x * 128;

    const float* Qb = g_Q + ((size_t)b * COUT + h * Dd) * PDIM;
    const float* Ab = g_S + (size_t)bh * PDIM * PDIM;
    float* Ob = out + ((size_t)b * COUT + h * Dd) * PDIM;

    __shared__ unsigned Qs[16][132];   // [k=j][m=c]
    __shared__ unsigned Ps[16][132];   // [k=j][n=i]

    const int t = threadIdx.x;
    const int lane = t & 31, w = t >> 5;
    const int wm = w & 1, wn = w >> 1;
    const int gid = lane >> 2, tig = lane & 3;
    const int mbase = wm * 64, nbase = wn * 32;

    const int lr = t >> 1;              // row (c or i) 0..127
    const int lj = (t & 1) * 8;         // k base 0 or 8

    float acc[4][4][4];
    #pragma unroll
    for (int mt = 0; mt < 4; mt++)
        #pragma unroll
        for (int nt = 0; nt < 4; nt++)
            #pragma unroll
            for (int r = 0; r < 4; r++) acc[mt][nt][r] = 0.f;

    for (int j0 = 0; j0 < PDIM; j0 += 16) {
        __syncthreads();
        {
            const float4* qsrc = (const float4*)(Qb + (size_t)lr * PDIM + j0 + lj);
            const float4* psrc = (const float4*)(Ab + (size_t)(i0 + lr) * PDIM + j0 + lj);
            float4 q0 = qsrc[0], q1 = qsrc[1];
            float4 p0 = psrc[0], p1 = psrc[1];
            float qv[8] = {q0.x, q0.y, q0.z, q0.w, q1.x, q1.y, q1.z, q1.w};
            float pv[8] = {p0.x, p0.y, p0.z, p0.w, p1.x, p1.y, p1.z, p1.w};
            #pragma unroll
            for (int r = 0; r < 8; r++) {
                Qs[lj + r][lr] = f2tf32(qv[r]);
                Ps[lj + r][lr] = f2tf32(pv[r]);
            }
        }
        __syncthreads();

        #pragma unroll
        for (int kk = 0; kk < 16; kk += 8) {
            unsigned af[4][4];
            #pragma unroll
            for (int mt = 0; mt < 4; mt++) {
                int r0 = mbase + mt * 16 + gid, r1 = r0 + 8;
                af[mt][0] = Qs[kk + tig][r0];
                af[mt][1] = Qs[kk + tig][r1];
                af[mt][2] = Qs[kk + tig + 4][r0];
                af[mt][3] = Qs[kk + tig + 4][r1];
            }
            unsigned bf[4][2];
            #pragma unroll
            for (int nt = 0; nt < 4; nt++) {
                int c = nbase + nt * 8 + gid;
                bf[nt][0] = Ps[kk + tig][c];
                bf[nt][1] = Ps[kk + tig + 4][c];
            }
            #pragma unroll
            for (int mt = 0; mt < 4; mt++)
                #pragma unroll
                for (int nt = 0; nt < 4; nt++)
                    mma_tf32(acc[mt][nt], af[mt], bf[nt]);
        }
    }

    #pragma unroll
    for (int mt = 0; mt < 4; mt++) {
        int r0 = mbase + mt * 16 + gid;
        #pragma unroll
        for (int nt = 0; nt < 4; nt++) {
            int c = i0 + nbase + nt * 8 + 2 * tig;
            Ob[(size_t)r0 * PDIM + c]       = acc[mt][nt][0];
            Ob[(size_t)r0 * PDIM + c + 1]   = acc[mt][nt][1];
            Ob[(size_t)(r0 + 8) * PDIM + c]     = acc[mt][nt][2];
            Ob[(size_t)(r0 + 8) * PDIM + c + 1] = acc[mt][nt][3];
        }
    }
}

// ---------------------------------------------------------------------------
extern "C" void kernel_launch(void* const* d_in, const int* in_sizes, int n_in,
                              void* d_out, int out_size)
{
    const float* x   = (const float*)d_in[0];
    const float* wq  = (const float*)d_in[1];
    const float* bq  = (const float*)d_in[2];
    const float* gw1 = (const float*)d_in[3];
    const float* gb1 = (const float*)d_in[4];
    const float* wk  = (const float*)d_in[5];
    const float* bk  = (const float*)d_in[6];
    const float* gw2 = (const float*)d_in[7];
    const float* gb2 = (const float*)d_in[8];
    const float* wv  = (const float*)d_in[9];
    const float* bv  = (const float*)d_in[10];
    const float* gw3 = (const float*)d_in[11];
    const float* gb3 = (const float*)d_in[12];
    float* out = (float*)d_out;

    dim3 g1(NG, B_);
    qkv_gn_kernel<<<g1, 256>>>(x, wq, bq, gw1, gb1, 0);
    qkv_gn_kernel<<<g1, 256>>>(x, wk, bk, gw2, gb2, 1);
    qkv_gn_kernel<<<g1, 256>>>(x, wv, bv, gw3, gb3, 2);

    dim3 g2(PDIM / 128, PDIM / 128, B_ * Hh);
    scores_mma_kernel<<<g2, 256>>>();

    softmax_kernel<<<B_ * Hh * PDIM, 256>>>();

    dim3 g4(PDIM / 128, B_ * Hh);
    out_mma_kernel<<<g4, 256>>>(out);
}

// round 3
// speedup vs baseline: 1.6586x; 1.3215x over previous
#include <cuda_runtime.h>
#include <cuda_bf16.h>
#include <math.h>
#include <stdint.h>

#define B_    8
#define CIN   512
#define COUT  1024
#define PDIM  2048
#define Hh    8
#define Dd    128
#define NG    32

// ------------------------- device scratch (static) -------------------------
__device__ float    g_raw[(size_t)B_ * COUT * PDIM];            // pre-norm y
__device__ unsigned g_KH[(size_t)B_ * (COUT/2) * PDIM];         // bf16x2 pairs along c
__device__ unsigned g_KL[(size_t)B_ * (COUT/2) * PDIM];
__device__ unsigned g_VH[(size_t)B_ * (COUT/2) * PDIM];
__device__ unsigned g_VL[(size_t)B_ * (COUT/2) * PDIM];
__device__ unsigned g_QH[(size_t)B_ * COUT * (PDIM/2)];         // bf16x2 pairs along p
__device__ unsigned g_QL[(size_t)B_ * COUT * (PDIM/2)];
__device__ float    g_S [(size_t)B_ * Hh * PDIM * PDIM];        // scores fp32
__device__ unsigned g_PH[(size_t)B_ * Hh * PDIM * (PDIM/2)];    // probs pairs along j
__device__ unsigned g_PL[(size_t)B_ * Hh * PDIM * (PDIM/2)];

// ------------------------------- helpers -----------------------------------
__device__ __forceinline__ unsigned pack_split(float a, float b, unsigned& lo) {
    __nv_bfloat16 ha = __float2bfloat16(a);
    __nv_bfloat16 hb = __float2bfloat16(b);
    float ra = a - __bfloat162float(ha);
    float rb = b - __bfloat162float(hb);
    __nv_bfloat162 l2 = __floats2bfloat162_rn(ra, rb);
    lo = *reinterpret_cast<unsigned*>(&l2);
    __nv_bfloat162 h2; h2.x = ha; h2.y = hb;
    return *reinterpret_cast<unsigned*>(&h2);
}

__device__ __forceinline__ void mma_bf16(float (&c)[4], const unsigned (&a)[4],
                                          const unsigned (&b)[2]) {
    asm volatile(
        "mma.sync.aligned.m16n8k16.row.col.f32.bf16.bf16.f32 "
        "{%0,%1,%2,%3}, {%4,%5,%6,%7}, {%8,%9}, {%0,%1,%2,%3};\n"
        : "+f"(c[0]), "+f"(c[1]), "+f"(c[2]), "+f"(c[3])
        : "r"(a[0]), "r"(a[1]), "r"(a[2]), "r"(a[3]), "r"(b[0]), "r"(b[1]));
}

// ---------------------------------------------------------------------------
// Kernel 1: grouped 1x1 conv + bias -> GroupNorm -> LeakyReLU -> packed bf16
// which: 0=Q (pack along p), 1=K, 2=V (pack along c)
// ---------------------------------------------------------------------------
__global__ __launch_bounds__(256) void qkv_gn_kernel(
    const float* __restrict__ x, const float* __restrict__ w,
    const float* __restrict__ bias, const float* __restrict__ gw,
    const float* __restrict__ gb, int which)
{
    const int ng = blockIdx.x;
    const int b  = blockIdx.y;
    const int c0 = ng * 32;
    const int g  = c0 >> 7;
    const int f0 = g * 64;

    __shared__ float xs[64][128];
    __shared__ float ws[32][64];
    __shared__ float bs[32], gws[32], gbs[32];
    __shared__ float red[256];
    __shared__ float stats[2];

    const int t = threadIdx.x;

    for (int i = t; i < 32 * 64; i += 256) {
        int c = i >> 6, f = i & 63;
        ws[c][f] = w[(size_t)(c0 + c) * 64 + f];
    }
    if (t < 32) { bs[t] = bias[c0 + t]; gws[t] = gw[c0 + t]; gbs[t] = gb[c0 + t]; }

    const int pl = t & 31;
    const int cq = t >> 5;

    const float* xb = x + (size_t)b * CIN * PDIM + (size_t)f0 * PDIM;
    float* rawb = g_raw + (size_t)b * COUT * PDIM + (size_t)c0 * PDIM;

    float sum = 0.f, sumsq = 0.f;

    for (int pt = 0; pt < 16; pt++) {
        __syncthreads();
        for (int i = t; i < 64 * 128; i += 256) {
            int r = i >> 7, cc = i & 127;
            xs[r][cc] = xb[(size_t)r * PDIM + pt * 128 + cc];
        }
        __syncthreads();

        float acc[4][4];
        #pragma unroll
        for (int v = 0; v < 4; v++)
            #pragma unroll
            for (int u = 0; u < 4; u++) acc[v][u] = bs[cq * 4 + v];

        #pragma unroll
        for (int f = 0; f < 64; f++) {
            float xv[4];
            #pragma unroll
            for (int u = 0; u < 4; u++) xv[u] = xs[f][pl + 32 * u];
            #pragma unroll
            for (int v = 0; v < 4; v++) {
                float wv = ws[cq * 4 + v][f];
                #pragma unroll
                for (int u = 0; u < 4; u++) acc[v][u] += wv * xv[u];
            }
        }

        #pragma unroll
        for (int v = 0; v < 4; v++) {
            int c = cq * 4 + v;
            #pragma unroll
            for (int u = 0; u < 4; u++) {
                float a = acc[v][u];
                sum += a; sumsq += a * a;
                rawb[(size_t)c * PDIM + pt * 128 + pl + 32 * u] = a;
            }
        }
    }

    red[t] = sum; __syncthreads();
    for (int s = 128; s > 0; s >>= 1) { if (t < s) red[t] += red[t + s]; __syncthreads(); }
    if (t == 0) stats[0] = red[0] * (1.0f / 65536.0f);
    __syncthreads();
    red[t] = sumsq; __syncthreads();
    for (int s = 128; s > 0; s >>= 1) { if (t < s) red[t] += red[t + s]; __syncthreads(); }
    if (t == 0) {
        float mu = stats[0];
        float var = red[0] * (1.0f / 65536.0f) - mu * mu;
        stats[1] = rsqrtf(var + 1e-5f);
    }
    __syncthreads();
    const float mu = stats[0], inv = stats[1];

    if (which == 0) {
        // Q: pack pairs along p
        unsigned* dh = g_QH + ((size_t)b * COUT + c0) * (PDIM / 2);
        unsigned* dl = g_QL + ((size_t)b * COUT + c0) * (PDIM / 2);
        for (int i = t; i < 32 * (PDIM / 2); i += 256) {
            int c = i >> 10, p2 = i & (PDIM / 2 - 1);
            float2 y = *(const float2*)(rawb + (size_t)c * PDIM + 2 * p2);
            float z0 = (y.x - mu) * inv * gws[c] + gbs[c];
            float z1 = (y.y - mu) * inv * gws[c] + gbs[c];
            z0 = (z0 >= 0.f) ? z0 : 0.1f * z0;
            z1 = (z1 >= 0.f) ? z1 : 0.1f * z1;
            unsigned lo;
            unsigned hi = pack_split(z0, z1, lo);
            dh[(size_t)c * (PDIM / 2) + p2] = hi;
            dl[(size_t)c * (PDIM / 2) + p2] = lo;
        }
    } else {
        // K/V: pack pairs along c
        unsigned* dh = (which == 1 ? g_KH : g_VH) + ((size_t)b * (COUT / 2) + ng * 16) * PDIM;
        unsigned* dl = (which == 1 ? g_KL : g_VL) + ((size_t)b * (COUT / 2) + ng * 16) * PDIM;
        for (int i = t; i < 16 * PDIM; i += 256) {
            int c2l = i >> 11, p = i & (PDIM - 1);
            int ca = 2 * c2l, cb = ca + 1;
            float y0 = rawb[(size_t)ca * PDIM + p];
            float y1 = rawb[(size_t)cb * PDIM + p];
            float z0 = (y0 - mu) * inv * gws[ca] + gbs[ca];
            float z1 = (y1 - mu) * inv * gws[cb] + gbs[cb];
            z0 = (z0 >= 0.f) ? z0 : 0.1f * z0;
            z1 = (z1 >= 0.f) ? z1 : 0.1f * z1;
            unsigned lo;
            unsigned hi = pack_split(z0, z1, lo);
            dh[(size_t)c2l * PDIM + p] = hi;
            dl[(size_t)c2l * PDIM + p] = lo;
        }
    }
}

// ---------------------------------------------------------------------------
// Kernel 2: scores S[i,j] = scale * sum_c K[c,i] V[c,j], bf16 split MMA.
// Block 128x128, 8 warps (2x4), warp tile 64x32, BK=16 channels (8 c2 rows).
// ---------------------------------------------------------------------------
__global__ __launch_bounds__(256, 1) void scores_mma_kernel()
{
    const int bh = blockIdx.z;
    const int b = bh >> 3, h = bh & 7;
    const int j0 = blockIdx.x * 128;
    const int i0 = blockIdx.y * 128;

    const unsigned* KHb = g_KH + ((size_t)b * (COUT / 2) + h * (Dd / 2)) * PDIM;
    const unsigned* KLb = g_KL + ((size_t)b * (COUT / 2) + h * (Dd / 2)) * PDIM;
    const unsigned* VHb = g_VH + ((size_t)b * (COUT / 2) + h * (Dd / 2)) * PDIM;
    const unsigned* VLb = g_VL + ((size_t)b * (COUT / 2) + h * (Dd / 2)) * PDIM;
    float* Sb = g_S + (size_t)bh * PDIM * PDIM;

    __shared__ unsigned sKH[8][136], sKL[8][136];
    __shared__ unsigned sVH[8][136], sVL[8][136];

    const int t = threadIdx.x;
    const int lane = t & 31, w = t >> 5;
    const int wm = w & 1, wn = w >> 1;
    const int gid = lane >> 2, tig = lane & 3;
    const int mbase = wm * 64, nbase = wn * 32;

    const int sr = t >> 5;          // staging row 0..7
    const int scl = (t & 31) * 4;   // staging col base

    float acc[4][4][4];
    #pragma unroll
    for (int mt = 0; mt < 4; mt++)
        #pragma unroll
        for (int nt = 0; nt < 4; nt++)
            #pragma unroll
            for (int r = 0; r < 4; r++) acc[mt][nt][r] = 0.f;

    for (int it = 0; it < 8; it++) {
        const size_t krow = (size_t)(it * 8 + sr) * PDIM;
        uint4 kh = *(const uint4*)(KHb + krow + i0 + scl);
        uint4 kl = *(const uint4*)(KLb + krow + i0 + scl);
        uint4 vh = *(const uint4*)(VHb + krow + j0 + scl);
        uint4 vl = *(const uint4*)(VLb + krow + j0 + scl);
        __syncthreads();
        *(uint4*)&sKH[sr][scl] = kh;
        *(uint4*)&sKL[sr][scl] = kl;
        *(uint4*)&sVH[sr][scl] = vh;
        *(uint4*)&sVL[sr][scl] = vl;
        __syncthreads();

        unsigned ah[4][4], al[4][4];
        #pragma unroll
        for (int mt = 0; mt < 4; mt++) {
            int m0 = mbase + mt * 16 + gid;
            ah[mt][0] = sKH[tig][m0];     ah[mt][1] = sKH[tig][m0 + 8];
            ah[mt][2] = sKH[tig + 4][m0]; ah[mt][3] = sKH[tig + 4][m0 + 8];
            al[mt][0] = sKL[tig][m0];     al[mt][1] = sKL[tig][m0 + 8];
            al[mt][2] = sKL[tig + 4][m0]; al[mt][3] = sKL[tig + 4][m0 + 8];
        }
        unsigned bh2[4][2], bl2[4][2];
        #pragma unroll
        for (int nt = 0; nt < 4; nt++) {
            int n0 = nbase + nt * 8 + gid;
            bh2[nt][0] = sVH[tig][n0]; bh2[nt][1] = sVH[tig + 4][n0];
            bl2[nt][0] = sVL[tig][n0]; bl2[nt][1] = sVL[tig + 4][n0];
        }
        #pragma unroll
        for (int mt = 0; mt < 4; mt++)
            #pragma unroll
            for (int nt = 0; nt < 4; nt++) {
                mma_bf16(acc[mt][nt], ah[mt], bh2[nt]);
                mma_bf16(acc[mt][nt], ah[mt], bl2[nt]);
                mma_bf16(acc[mt][nt], al[mt], bh2[nt]);
            }
    }

    const float scale = 0.088388347648318447f;  // 1/sqrt(128)
    #pragma unroll
    for (int mt = 0; mt < 4; mt++) {
        int r0 = i0 + mbase + mt * 16 + gid;
        #pragma unroll
        for (int nt = 0; nt < 4; nt++) {
            int c = j0 + nbase + nt * 8 + 2 * tig;
            float2 v0 = make_float2(acc[mt][nt][0] * scale, acc[mt][nt][1] * scale);
            float2 v1 = make_float2(acc[mt][nt][2] * scale, acc[mt][nt][3] * scale);
            *(float2*)(Sb + (size_t)r0 * PDIM + c) = v0;
            *(float2*)(Sb + (size_t)(r0 + 8) * PDIM + c) = v1;
        }
    }
}

// ---------------------------------------------------------------------------
// Kernel 3: softmax rows of S -> packed bf16 split probs
// ---------------------------------------------------------------------------
__global__ __launch_bounds__(256) void softmax_kernel()
{
    const size_t rowid = blockIdx.x;
    const float2* srow = (const float2*)(g_S + rowid * PDIM);
    unsigned* ph = g_PH + rowid * (PDIM / 2);
    unsigned* pl = g_PL + rowid * (PDIM / 2);
    const int t = threadIdx.x;
    __shared__ float red[256];
    __shared__ float bc;

    float2 v[4];
    float m = -1e30f;
    #pragma unroll
    for (int k = 0; k < 4; k++) {
        v[k] = srow[t + 256 * k];
        m = fmaxf(m, fmaxf(v[k].x, v[k].y));
    }
    red[t] = m; __syncthreads();
    for (int s = 128; s > 0; s >>= 1) { if (t < s) red[t] = fmaxf(red[t], red[t + s]); __syncthreads(); }
    if (t == 0) bc = red[0];
    __syncthreads();
    const float M = bc;

    float sum = 0.f;
    #pragma unroll
    for (int k = 0; k < 4; k++) {
        v[k].x = __expf(v[k].x - M);
        v[k].y = __expf(v[k].y - M);
        sum += v[k].x + v[k].y;
    }
    __syncthreads();
    red[t] = sum; __syncthreads();
    for (int s = 128; s > 0; s >>= 1) { if (t < s) red[t] += red[t + s]; __syncthreads(); }
    if (t == 0) bc = 1.0f / red[0];
    __syncthreads();
    const float inv = bc;

    #pragma unroll
    for (int k = 0; k < 4; k++) {
        unsigned lo;
        unsigned hi = pack_split(v[k].x * inv, v[k].y * inv, lo);
        ph[t + 256 * k] = hi;
        pl[t + 256 * k] = lo;
    }
}

// ---------------------------------------------------------------------------
// Kernel 4: out[c,i] = sum_j P[i,j] Q[c,j], bf16 split MMA, k=j, BK=16.
// ---------------------------------------------------------------------------
__global__ __launch_bounds__(256, 1) void out_mma_kernel(float* __restrict__ out)
{
    const int bh = blockIdx.y;
    const int b = bh >> 3, h = bh & 7;
    const int i0 = blockIdx.x * 128;

    const unsigned* QHb = g_QH + ((size_t)b * COUT + h * Dd) * (PDIM / 2);
    const unsigned* QLb = g_QL + ((size_t)b * COUT + h * Dd) * (PDIM / 2);
    const unsigned* PHb = g_PH + ((size_t)bh * PDIM + i0) * (PDIM / 2);
    const unsigned* PLb = g_PL + ((size_t)bh * PDIM + i0) * (PDIM / 2);
    float* Ob = out + ((size_t)b * COUT + h * Dd) * PDIM;

    __shared__ unsigned sQH[8][136], sQL[8][136];
    __shared__ unsigned sPH[8][136], sPL[8][136];

    const int t = threadIdx.x;
    const int lane = t & 31, w = t >> 5;
    const int wm = w & 1, wn = w >> 1;
    const int gid = lane >> 2, tig = lane & 3;
    const int mbase = wm * 64, nbase = wn * 32;

    const int lr = t >> 1;          // row 0..127 (c for Q, i for P)
    const int ljb = (t & 1) * 4;    // j2 base 0 or 4

    float acc[4][4][4];
    #pragma unroll
    for (int mt = 0; mt < 4; mt++)
        #pragma unroll
        for (int nt = 0; nt < 4; nt++)
            #pragma unroll
            for (int r = 0; r < 4; r++) acc[mt][nt][r] = 0.f;

    for (int j20 = 0; j20 < PDIM / 2; j20 += 8) {
        uint4 qh = *(const uint4*)(QHb + (size_t)lr * (PDIM / 2) + j20 + ljb);
        uint4 ql = *(const uint4*)(QLb + (size_t)lr * (PDIM / 2) + j20 + ljb);
        uint4 phv = *(const uint4*)(PHb + (size_t)lr * (PDIM / 2) + j20 + ljb);
        uint4 plv = *(const uint4*)(PLb + (size_t)lr * (PDIM / 2) + j20 + ljb);
        __syncthreads();
        sQH[ljb + 0][lr] = qh.x; sQH[ljb + 1][lr] = qh.y;
        sQH[ljb + 2][lr] = qh.z; sQH[ljb + 3][lr] = qh.w;
        sQL[ljb + 0][lr] = ql.x; sQL[ljb + 1][lr] = ql.y;
        sQL[ljb + 2][lr] = ql.z; sQL[ljb + 3][lr] = ql.w;
        sPH[ljb + 0][lr] = phv.x; sPH[ljb + 1][lr] = phv.y;
        sPH[ljb + 2][lr] = phv.z; sPH[ljb + 3][lr] = phv.w;
        sPL[ljb + 0][lr] = plv.x; sPL[ljb + 1][lr] = plv.y;
        sPL[ljb + 2][lr] = plv.z; sPL[ljb + 3][lr] = plv.w;
        __syncthreads();

        unsigned ah[4][4], al[4][4];
        #pragma unroll
        for (int mt = 0; mt < 4; mt++) {
            int m0 = mbase + mt * 16 + gid;
            ah[mt][0] = sQH[tig][m0];     ah[mt][1] = sQH[tig][m0 + 8];
            ah[mt][2] = sQH[tig + 4][m0]; ah[mt][3] = sQH[tig + 4][m0 + 8];
            al[mt][0] = sQL[tig][m0];     al[mt][1] = sQL[tig][m0 + 8];
            al[mt][2] = sQL[tig + 4][m0]; al[mt][3] = sQL[tig + 4][m0 + 8];
        }
        unsigned bh2[4][2], bl2[4][2];
        #pragma unroll
        for (int nt = 0; nt < 4; nt++) {
            int n0 = nbase + nt * 8 + gid;
            bh2[nt][0] = sPH[tig][n0]; bh2[nt][1] = sPH[tig + 4][n0];
            bl2[nt][0] = sPL[tig][n0]; bl2[nt][1] = sPL[tig + 4][n0];
        }
        #pragma unroll
        for (int mt = 0; mt < 4; mt++)
            #pragma unroll
            for (int nt = 0; nt < 4; nt++) {
                mma_bf16(acc[mt][nt], ah[mt], bh2[nt]);
                mma_bf16(acc[mt][nt], ah[mt], bl2[nt]);
                mma_bf16(acc[mt][nt], al[mt], bh2[nt]);
            }
    }

    #pragma unroll
    for (int mt = 0; mt < 4; mt++) {
        int r0 = mbase + mt * 16 + gid;
        #pragma unroll
        for (int nt = 0; nt < 4; nt++) {
            int c = i0 + nbase + nt * 8 + 2 * tig;
            float2 v0 = make_float2(acc[mt][nt][0], acc[mt][nt][1]);
            float2 v1 = make_float2(acc[mt][nt][2], acc[mt][nt][3]);
            *(float2*)(Ob + (size_t)r0 * PDIM + c) = v0;
            *(float2*)(Ob + (size_t)(r0 + 8) * PDIM + c) = v1;
        }
    }
}

// ---------------------------------------------------------------------------
extern "C" void kernel_launch(void* const* d_in, const int* in_sizes, int n_in,
                              void* d_out, int out_size)
{
    const float* x   = (const float*)d_in[0];
    const float* wq  = (const float*)d_in[1];
    const float* bq  = (const float*)d_in[2];
    const float* gw1 = (const float*)d_in[3];
    const float* gb1 = (const float*)d_in[4];
    const float* wk  = (const float*)d_in[5];
    const float* bk  = (const float*)d_in[6];
    const float* gw2 = (const float*)d_in[7];
    const float* gb2 = (const float*)d_in[8];
    const float* wv  = (const float*)d_in[9];
    const float* bv  = (const float*)d_in[10];
    const float* gw3 = (const float*)d_in[11];
    const float* gb3 = (const float*)d_in[12];
    float* out = (float*)d_out;

    dim3 g1(NG, B_);
    qkv_gn_kernel<<<g1, 256>>>(x, wq, bq, gw1, gb1, 0);
    qkv_gn_kernel<<<g1, 256>>>(x, wk, bk, gw2, gb2, 1);
    qkv_gn_kernel<<<g1, 256>>>(x, wv, bv, gw3, gb3, 2);

    dim3 g2(PDIM / 128, PDIM / 128, B_ * Hh);
    scores_mma_kernel<<<g2, 256>>>();

    softmax_kernel<<<B_ * Hh * PDIM, 256>>>();

    dim3 g4(PDIM / 128, B_ * Hh);
    out_mma_kernel<<<g4, 256>>>(out);
}

// round 4
// speedup vs baseline: 2.5697x; 1.5493x over previous
#include <cuda_runtime.h>
#include <cuda_bf16.h>
#include <math.h>
#include <stdint.h>

#define B_    8
#define CIN   512
#define COUT  1024
#define PDIM  2048
#define Hh    8
#define Dd    128
#define NG    32

// ------------------------- device scratch (static) -------------------------
__device__ float    g_raw[(size_t)B_ * COUT * PDIM];            // pre-norm y
__device__ unsigned g_KH[(size_t)B_ * (COUT/2) * PDIM];         // bf16x2 pairs along c
__device__ unsigned g_KL[(size_t)B_ * (COUT/2) * PDIM];
__device__ unsigned g_VH[(size_t)B_ * (COUT/2) * PDIM];
__device__ unsigned g_VL[(size_t)B_ * (COUT/2) * PDIM];
__device__ unsigned g_QH[(size_t)B_ * COUT * (PDIM/2)];         // bf16x2 pairs along p
__device__ float    g_S [(size_t)B_ * Hh * PDIM * PDIM];        // scores fp32
__device__ unsigned g_PH[(size_t)B_ * Hh * PDIM * (PDIM/2)];    // probs bf16x2 along j

// ------------------------------- helpers -----------------------------------
__device__ __forceinline__ unsigned pack_split(float a, float b, unsigned& lo) {
    __nv_bfloat16 ha = __float2bfloat16(a);
    __nv_bfloat16 hb = __float2bfloat16(b);
    float ra = a - __bfloat162float(ha);
    float rb = b - __bfloat162float(hb);
    __nv_bfloat162 l2 = __floats2bfloat162_rn(ra, rb);
    lo = *reinterpret_cast<unsigned*>(&l2);
    __nv_bfloat162 h2; h2.x = ha; h2.y = hb;
    return *reinterpret_cast<unsigned*>(&h2);
}
__device__ __forceinline__ unsigned pack2(float a, float b) {
    __nv_bfloat162 h2 = __floats2bfloat162_rn(a, b);
    return *reinterpret_cast<unsigned*>(&h2);
}

__device__ __forceinline__ void mma_bf16(float (&c)[4], const unsigned (&a)[4],
                                          const unsigned (&b)[2]) {
    asm volatile(
        "mma.sync.aligned.m16n8k16.row.col.f32.bf16.bf16.f32 "
        "{%0,%1,%2,%3}, {%4,%5,%6,%7}, {%8,%9}, {%0,%1,%2,%3};\n"
        : "+f"(c[0]), "+f"(c[1]), "+f"(c[2]), "+f"(c[3])
        : "r"(a[0]), "r"(a[1]), "r"(a[2]), "r"(a[3]), "r"(b[0]), "r"(b[1]));
}

// ---------------------------------------------------------------------------
// Kernel 1: grouped 1x1 conv + bias -> GroupNorm -> LeakyReLU -> packed bf16
// which: 0=Q (pack hi along p), 1=K, 2=V (pack hi+lo along c)
// ---------------------------------------------------------------------------
__global__ __launch_bounds__(256) void qkv_gn_kernel(
    const float* __restrict__ x, const float* __restrict__ w,
    const float* __restrict__ bias, const float* __restrict__ gw,
    const float* __restrict__ gb, int which)
{
    const int ng = blockIdx.x;
    const int b  = blockIdx.y;
    const int c0 = ng * 32;
    const int g  = c0 >> 7;
    const int f0 = g * 64;

    __shared__ float xs[64][128];
    __shared__ float ws[32][64];
    __shared__ float bs[32], gws[32], gbs[32];
    __shared__ float red[256];
    __shared__ float stats[2];

    const int t = threadIdx.x;

    for (int i = t; i < 32 * 64; i += 256) {
        int c = i >> 6, f = i & 63;
        ws[c][f] = w[(size_t)(c0 + c) * 64 + f];
    }
    if (t < 32) { bs[t] = bias[c0 + t]; gws[t] = gw[c0 + t]; gbs[t] = gb[c0 + t]; }

    const int pl = t & 31;
    const int cq = t >> 5;

    const float* xb = x + (size_t)b * CIN * PDIM + (size_t)f0 * PDIM;
    float* rawb = g_raw + (size_t)b * COUT * PDIM + (size_t)c0 * PDIM;

    float sum = 0.f, sumsq = 0.f;

    for (int pt = 0; pt < 16; pt++) {
        __syncthreads();
        for (int i = t; i < 64 * 128; i += 256) {
            int r = i >> 7, cc = i & 127;
            xs[r][cc] = xb[(size_t)r * PDIM + pt * 128 + cc];
        }
        __syncthreads();

        float acc[4][4];
        #pragma unroll
        for (int v = 0; v < 4; v++)
            #pragma unroll
            for (int u = 0; u < 4; u++) acc[v][u] = bs[cq * 4 + v];

        #pragma unroll
        for (int f = 0; f < 64; f++) {
            float xv[4];
            #pragma unroll
            for (int u = 0; u < 4; u++) xv[u] = xs[f][pl + 32 * u];
            #pragma unroll
            for (int v = 0; v < 4; v++) {
                float wv = ws[cq * 4 + v][f];
                #pragma unroll
                for (int u = 0; u < 4; u++) acc[v][u] += wv * xv[u];
            }
        }

        #pragma unroll
        for (int v = 0; v < 4; v++) {
            int c = cq * 4 + v;
            #pragma unroll
            for (int u = 0; u < 4; u++) {
                float a = acc[v][u];
                sum += a; sumsq += a * a;
                rawb[(size_t)c * PDIM + pt * 128 + pl + 32 * u] = a;
            }
        }
    }

    red[t] = sum; __syncthreads();
    for (int s = 128; s > 0; s >>= 1) { if (t < s) red[t] += red[t + s]; __syncthreads(); }
    if (t == 0) stats[0] = red[0] * (1.0f / 65536.0f);
    __syncthreads();
    red[t] = sumsq; __syncthreads();
    for (int s = 128; s > 0; s >>= 1) { if (t < s) red[t] += red[t + s]; __syncthreads(); }
    if (t == 0) {
        float mu = stats[0];
        float var = red[0] * (1.0f / 65536.0f) - mu * mu;
        stats[1] = rsqrtf(var + 1e-5f);
    }
    __syncthreads();
    const float mu = stats[0], inv = stats[1];

    if (which == 0) {
        // Q: pack hi pairs along p
        unsigned* dh = g_QH + ((size_t)b * COUT + c0) * (PDIM / 2);
        for (int i = t; i < 32 * (PDIM / 2); i += 256) {
            int c = i >> 10, p2 = i & (PDIM / 2 - 1);
            float2 y = *(const float2*)(rawb + (size_t)c * PDIM + 2 * p2);
            float z0 = (y.x - mu) * inv * gws[c] + gbs[c];
            float z1 = (y.y - mu) * inv * gws[c] + gbs[c];
            z0 = (z0 >= 0.f) ? z0 : 0.1f * z0;
            z1 = (z1 >= 0.f) ? z1 : 0.1f * z1;
            dh[(size_t)c * (PDIM / 2) + p2] = pack2(z0, z1);
        }
    } else {
        // K/V: pack hi+lo pairs along c
        unsigned* dh = (which == 1 ? g_KH : g_VH) + ((size_t)b * (COUT / 2) + ng * 16) * PDIM;
        unsigned* dl = (which == 1 ? g_KL : g_VL) + ((size_t)b * (COUT / 2) + ng * 16) * PDIM;
        for (int i = t; i < 16 * PDIM; i += 256) {
            int c2l = i >> 11, p = i & (PDIM - 1);
            int ca = 2 * c2l, cb = ca + 1;
            float y0 = rawb[(size_t)ca * PDIM + p];
            float y1 = rawb[(size_t)cb * PDIM + p];
            float z0 = (y0 - mu) * inv * gws[ca] + gbs[ca];
            float z1 = (y1 - mu) * inv * gws[cb] + gbs[cb];
            z0 = (z0 >= 0.f) ? z0 : 0.1f * z0;
            z1 = (z1 >= 0.f) ? z1 : 0.1f * z1;
            unsigned lo;
            unsigned hi = pack_split(z0, z1, lo);
            dh[(size_t)c2l * PDIM + p] = hi;
            dl[(size_t)c2l * PDIM + p] = lo;
        }
    }
}

// ---------------------------------------------------------------------------
// Kernel 2: scores S[i,j] = scale * sum_c K[c,i] V[c,j], bf16 split MMA.
// Block 128x128, 8 warps (2x4), warp tile 64x32, BK=16 ch, double-buffered.
// ---------------------------------------------------------------------------
__global__ __launch_bounds__(256, 2) void scores_mma_kernel()
{
    const int bh = blockIdx.z;
    const int b = bh >> 3, h = bh & 7;
    const int j0 = blockIdx.x * 128;
    const int i0 = blockIdx.y * 128;

    const unsigned* KHb = g_KH + ((size_t)b * (COUT / 2) + h * (Dd / 2)) * PDIM;
    const unsigned* KLb = g_KL + ((size_t)b * (COUT / 2) + h * (Dd / 2)) * PDIM;
    const unsigned* VHb = g_VH + ((size_t)b * (COUT / 2) + h * (Dd / 2)) * PDIM;
    const unsigned* VLb = g_VL + ((size_t)b * (COUT / 2) + h * (Dd / 2)) * PDIM;
    float* Sb = g_S + (size_t)bh * PDIM * PDIM;

    __shared__ unsigned sKH[2][8][136], sKL[2][8][136];
    __shared__ unsigned sVH[2][8][136], sVL[2][8][136];

    const int t = threadIdx.x;
    const int lane = t & 31, w = t >> 5;
    const int wm = w & 1, wn = w >> 1;
    const int gid = lane >> 2, tig = lane & 3;
    const int mbase = wm * 64, nbase = wn * 32;

    const int sr = t >> 5;          // staging row 0..7
    const int scl = (t & 31) * 4;   // staging col base

    float acc[4][4][4];
    #pragma unroll
    for (int mt = 0; mt < 4; mt++)
        #pragma unroll
        for (int nt = 0; nt < 4; nt++)
            #pragma unroll
            for (int r = 0; r < 4; r++) acc[mt][nt][r] = 0.f;

    uint4 kh, kl, vh, vl;
    {
        const size_t krow = (size_t)sr * PDIM;
        kh = *(const uint4*)(KHb + krow + i0 + scl);
        kl = *(const uint4*)(KLb + krow + i0 + scl);
        vh = *(const uint4*)(VHb + krow + j0 + scl);
        vl = *(const uint4*)(VLb + krow + j0 + scl);
    }
    *(uint4*)&sKH[0][sr][scl] = kh;
    *(uint4*)&sKL[0][sr][scl] = kl;
    *(uint4*)&sVH[0][sr][scl] = vh;
    *(uint4*)&sVL[0][sr][scl] = vl;
    __syncthreads();

    for (int it = 0; it < 8; it++) {
        const int cur = it & 1;
        if (it < 7) {
            const size_t krow = (size_t)((it + 1) * 8 + sr) * PDIM;
            kh = *(const uint4*)(KHb + krow + i0 + scl);
            kl = *(const uint4*)(KLb + krow + i0 + scl);
            vh = *(const uint4*)(VHb + krow + j0 + scl);
            vl = *(const uint4*)(VLb + krow + j0 + scl);
        }

        unsigned ah[4][4], al[4][4];
        #pragma unroll
        for (int mt = 0; mt < 4; mt++) {
            int m0 = mbase + mt * 16 + gid;
            ah[mt][0] = sKH[cur][tig][m0];     ah[mt][1] = sKH[cur][tig][m0 + 8];
            ah[mt][2] = sKH[cur][tig + 4][m0]; ah[mt][3] = sKH[cur][tig + 4][m0 + 8];
            al[mt][0] = sKL[cur][tig][m0];     al[mt][1] = sKL[cur][tig][m0 + 8];
            al[mt][2] = sKL[cur][tig + 4][m0]; al[mt][3] = sKL[cur][tig + 4][m0 + 8];
        }
        unsigned bh2[4][2], bl2[4][2];
        #pragma unroll
        for (int nt = 0; nt < 4; nt++) {
            int n0 = nbase + nt * 8 + gid;
            bh2[nt][0] = sVH[cur][tig][n0]; bh2[nt][1] = sVH[cur][tig + 4][n0];
            bl2[nt][0] = sVL[cur][tig][n0]; bl2[nt][1] = sVL[cur][tig + 4][n0];
        }
        #pragma unroll
        for (int mt = 0; mt < 4; mt++)
            #pragma unroll
            for (int nt = 0; nt < 4; nt++) {
                mma_bf16(acc[mt][nt], ah[mt], bh2[nt]);
                mma_bf16(acc[mt][nt], ah[mt], bl2[nt]);
                mma_bf16(acc[mt][nt], al[mt], bh2[nt]);
            }

        if (it < 7) {
            *(uint4*)&sKH[cur ^ 1][sr][scl] = kh;
            *(uint4*)&sKL[cur ^ 1][sr][scl] = kl;
            *(uint4*)&sVH[cur ^ 1][sr][scl] = vh;
            *(uint4*)&sVL[cur ^ 1][sr][scl] = vl;
        }
        __syncthreads();
    }

    const float scale = 0.088388347648318447f;  // 1/sqrt(128)
    #pragma unroll
    for (int mt = 0; mt < 4; mt++) {
        int r0 = i0 + mbase + mt * 16 + gid;
        #pragma unroll
        for (int nt = 0; nt < 4; nt++) {
            int c = j0 + nbase + nt * 8 + 2 * tig;
            float2 v0 = make_float2(acc[mt][nt][0] * scale, acc[mt][nt][1] * scale);
            float2 v1 = make_float2(acc[mt][nt][2] * scale, acc[mt][nt][3] * scale);
            *(float2*)(Sb + (size_t)r0 * PDIM + c) = v0;
            *(float2*)(Sb + (size_t)(r0 + 8) * PDIM + c) = v1;
        }
    }
}

// ---------------------------------------------------------------------------
// Kernel 3: softmax rows of S -> packed bf16 probs (hi only)
// ---------------------------------------------------------------------------
__global__ __launch_bounds__(256) void softmax_kernel()
{
    const size_t rowid = blockIdx.x;
    const float2* srow = (const float2*)(g_S + rowid * PDIM);
    unsigned* ph = g_PH + rowid * (PDIM / 2);
    const int t = threadIdx.x;
    __shared__ float red[256];
    __shared__ float bc;

    float2 v[4];
    float m = -1e30f;
    #pragma unroll
    for (int k = 0; k < 4; k++) {
        v[k] = srow[t + 256 * k];
        m = fmaxf(m, fmaxf(v[k].x, v[k].y));
    }
    red[t] = m; __syncthreads();
    for (int s = 128; s > 0; s >>= 1) { if (t < s) red[t] = fmaxf(red[t], red[t + s]); __syncthreads(); }
    if (t == 0) bc = red[0];
    __syncthreads();
    const float M = bc;

    float sum = 0.f;
    #pragma unroll
    for (int k = 0; k < 4; k++) {
        v[k].x = __expf(v[k].x - M);
        v[k].y = __expf(v[k].y - M);
        sum += v[k].x + v[k].y;
    }
    __syncthreads();
    red[t] = sum; __syncthreads();
    for (int s = 128; s > 0; s >>= 1) { if (t < s) red[t] += red[t + s]; __syncthreads(); }
    if (t == 0) bc = 1.0f / red[0];
    __syncthreads();
    const float inv = bc;

    #pragma unroll
    for (int k = 0; k < 4; k++)
        ph[t + 256 * k] = pack2(v[k].x * inv, v[k].y * inv);
}

// ---------------------------------------------------------------------------
// Kernel 4: out[c,i] = sum_j P[i,j] Q[c,j]. Plain bf16 MMA, BK=16 j,
// double-buffered. m=c (128), n=i (128), k=j.
// ---------------------------------------------------------------------------
__global__ __launch_bounds__(256, 2) void out_mma_kernel(float* __restrict__ out)
{
    const int bh = blockIdx.y;
    const int b = bh >> 3, h = bh & 7;
    const int i0 = blockIdx.x * 128;

    const unsigned* QHb = g_QH + ((size_t)b * COUT + h * Dd) * (PDIM / 2);
    const unsigned* PHb = g_PH + ((size_t)bh * PDIM + i0) * (PDIM / 2);
    float* Ob = out + ((size_t)b * COUT + h * Dd) * PDIM;

    __shared__ unsigned sQH[2][8][136];   // [buf][j2][c]
    __shared__ unsigned sPH[2][8][136];   // [buf][j2][i]

    const int t = threadIdx.x;
    const int lane = t & 31, w = t >> 5;
    const int wm = w & 1, wn = w >> 1;
    const int gid = lane >> 2, tig = lane & 3;
    const int mbase = wm * 64, nbase = wn * 32;

    const int lr  = t & 127;        // row (c for Q, i for P)
    const int ljb = (t >> 7) * 4;   // j2 word base 0 or 4

    float acc[4][4][4];
    #pragma unroll
    for (int mt = 0; mt < 4; mt++)
        #pragma unroll
        for (int nt = 0; nt < 4; nt++)
            #pragma unroll
            for (int r = 0; r < 4; r++) acc[mt][nt][r] = 0.f;

    uint4 qh, phv;
    qh  = *(const uint4*)(QHb + (size_t)lr * (PDIM / 2) + ljb);
    phv = *(const uint4*)(PHb + (size_t)lr * (PDIM / 2) + ljb);
    sQH[0][ljb + 0][lr] = qh.x;  sQH[0][ljb + 1][lr] = qh.y;
    sQH[0][ljb + 2][lr] = qh.z;  sQH[0][ljb + 3][lr] = qh.w;
    sPH[0][ljb + 0][lr] = phv.x; sPH[0][ljb + 1][lr] = phv.y;
    sPH[0][ljb + 2][lr] = phv.z; sPH[0][ljb + 3][lr] = phv.w;
    __syncthreads();

    const int NIT = PDIM / 16;   // 128 iters of 8 j2-words
    for (int it = 0; it < NIT; it++) {
        const int cur = it & 1;
        if (it < NIT - 1) {
            int j20 = (it + 1) * 8;
            qh  = *(const uint4*)(QHb + (size_t)lr * (PDIM / 2) + j20 + ljb);
            phv = *(const uint4*)(PHb + (size_t)lr * (PDIM / 2) + j20 + ljb);
        }

        unsigned af[4][4];
        #pragma unroll
        for (int mt = 0; mt < 4; mt++) {
            int m0 = mbase + mt * 16 + gid;
            af[mt][0] = sQH[cur][tig][m0];     af[mt][1] = sQH[cur][tig][m0 + 8];
            af[mt][2] = sQH[cur][tig + 4][m0]; af[mt][3] = sQH[cur][tig + 4][m0 + 8];
        }
        unsigned bf[4][2];
        #pragma unroll
        for (int nt = 0; nt < 4; nt++) {
            int n0 = nbase + nt * 8 + gid;
            bf[nt][0] = sPH[cur][tig][n0]; bf[nt][1] = sPH[cur][tig + 4][n0];
        }
        #pragma unroll
        for (int mt = 0; mt < 4; mt++)
            #pragma unroll
            for (int nt = 0; nt < 4; nt++)
                mma_bf16(acc[mt][nt], af[mt], bf[nt]);

        if (it < NIT - 1) {
            const int nb = cur ^ 1;
            sQH[nb][ljb + 0][lr] = qh.x;  sQH[nb][ljb + 1][lr] = qh.y;
            sQH[nb][ljb + 2][lr] = qh.z;  sQH[nb][ljb + 3][lr] = qh.w;
            sPH[nb][ljb + 0][lr] = phv.x; sPH[nb][ljb + 1][lr] = phv.y;
            sPH[nb][ljb + 2][lr] = phv.z; sPH[nb][ljb + 3][lr] = phv.w;
        }
        __syncthreads();
    }

    #pragma unroll
    for (int mt = 0; mt < 4; mt++) {
        int r0 = mbase + mt * 16 + gid;
        #pragma unroll
        for (int nt = 0; nt < 4; nt++) {
            int c = i0 + nbase + nt * 8 + 2 * tig;
            float2 v0 = make_float2(acc[mt][nt][0], acc[mt][nt][1]);
            float2 v1 = make_float2(acc[mt][nt][2], acc[mt][nt][3]);
            *(float2*)(Ob + (size_t)r0 * PDIM + c) = v0;
            *(float2*)(Ob + (size_t)(r0 + 8) * PDIM + c) = v1;
        }
    }
}

// ---------------------------------------------------------------------------
extern "C" void kernel_launch(void* const* d_in, const int* in_sizes, int n_in,
                              void* d_out, int out_size)
{
    const float* x   = (const float*)d_in[0];
    const float* wq  = (const float*)d_in[1];
    const float* bq  = (const float*)d_in[2];
    const float* gw1 = (const float*)d_in[3];
    const float* gb1 = (const float*)d_in[4];
    const float* wk  = (const float*)d_in[5];
    const float* bk  = (const float*)d_in[6];
    const float* gw2 = (const float*)d_in[7];
    const float* gb2 = (const float*)d_in[8];
    const float* wv  = (const float*)d_in[9];
    const float* bv  = (const float*)d_in[10];
    const float* gw3 = (const float*)d_in[11];
    const float* gb3 = (const float*)d_in[12];
    float* out = (float*)d_out;

    dim3 g1(NG, B_);
    qkv_gn_kernel<<<g1, 256>>>(x, wq, bq, gw1, gb1, 0);
    qkv_gn_kernel<<<g1, 256>>>(x, wk, bk, gw2, gb2, 1);
    qkv_gn_kernel<<<g1, 256>>>(x, wv, bv, gw3, gb3, 2);

    dim3 g2(PDIM / 128, PDIM / 128, B_ * Hh);
    scores_mma_kernel<<<g2, 256>>>();

    softmax_kernel<<<B_ * Hh * PDIM, 256>>>();

    dim3 g4(PDIM / 128, B_ * Hh);
    out_mma_kernel<<<g4, 256>>>(out);
}

// round 6
// speedup vs baseline: 3.3560x; 1.3060x over previous
#include <cuda_runtime.h>
#include <cuda_bf16.h>
#include <math.h>
#include <stdint.h>

#define B_    8
#define CIN   512
#define COUT  1024
#define PDIM  2048
#define Hh    8
#define Dd    128
#define NG    32
#define BR    128
#define BC    64

// ------------------------- device scratch (static) -------------------------
__device__ float    g_raw[(size_t)B_ * COUT * PDIM];            // pre-norm y
__device__ unsigned g_KH[(size_t)B_ * (COUT/2) * PDIM];         // bf16x2 pairs along c
__device__ unsigned g_KL[(size_t)B_ * (COUT/2) * PDIM];
__device__ unsigned g_VH[(size_t)B_ * (COUT/2) * PDIM];
__device__ unsigned g_VL[(size_t)B_ * (COUT/2) * PDIM];
__device__ unsigned g_QT[(size_t)B_ * Hh * (PDIM/2) * Dd];      // Q bf16x2 [j2][c]

// ------------------------------- helpers -----------------------------------
__device__ __forceinline__ unsigned pack_split(float a, float b, unsigned& lo) {
    __nv_bfloat16 ha = __float2bfloat16(a);
    __nv_bfloat16 hb = __float2bfloat16(b);
    float ra = a - __bfloat162float(ha);
    float rb = b - __bfloat162float(hb);
    __nv_bfloat162 l2 = __floats2bfloat162_rn(ra, rb);
    lo = *reinterpret_cast<unsigned*>(&l2);
    __nv_bfloat162 h2; h2.x = ha; h2.y = hb;
    return *reinterpret_cast<unsigned*>(&h2);
}
__device__ __forceinline__ unsigned pack2(float a, float b) {
    __nv_bfloat162 h2 = __floats2bfloat162_rn(a, b);
    return *reinterpret_cast<unsigned*>(&h2);
}
__device__ __forceinline__ void mma_bf16(float (&c)[4], const unsigned (&a)[4],
                                          const unsigned (&b)[2]) {
    asm volatile(
        "mma.sync.aligned.m16n8k16.row.col.f32.bf16.bf16.f32 "
        "{%0,%1,%2,%3}, {%4,%5,%6,%7}, {%8,%9}, {%0,%1,%2,%3};\n"
        : "+f"(c[0]), "+f"(c[1]), "+f"(c[2]), "+f"(c[3])
        : "r"(a[0]), "r"(a[1]), "r"(a[2]), "r"(a[3]), "r"(b[0]), "r"(b[1]));
}
__device__ __forceinline__ unsigned smem_u32(const void* p) {
    return (unsigned)__cvta_generic_to_shared(p);
}
__device__ __forceinline__ void cp16(unsigned s, const void* g) {
    asm volatile("cp.async.cg.shared.global [%0], [%1], 16;\n" :: "r"(s), "l"(g));
}

// ---------------------------------------------------------------------------
// Kernel 1: grouped 1x1 conv + bias -> GroupNorm -> LeakyReLU -> packed bf16
// which: 0=Q (transposed [j2][c] hi only), 1=K, 2=V (hi+lo pairs along c)
// ---------------------------------------------------------------------------
__global__ __launch_bounds__(256) void qkv_gn_kernel(
    const float* __restrict__ x, const float* __restrict__ w,
    const float* __restrict__ bias, const float* __restrict__ gw,
    const float* __restrict__ gb, int which)
{
    const int ng = blockIdx.x;
    const int b  = blockIdx.y;
    const int c0 = ng * 32;
    const int g  = c0 >> 7;
    const int f0 = g * 64;

    __shared__ float xs[64][129];
    __shared__ float ws[32][64];
    __shared__ float bs[32], gws[32], gbs[32];
    __shared__ float red[256];
    __shared__ float stats[2];

    const int t = threadIdx.x;

    for (int i = t; i < 32 * 64; i += 256) {
        int c = i >> 6, f = i & 63;
        ws[c][f] = w[(size_t)(c0 + c) * 64 + f];
    }
    if (t < 32) { bs[t] = bias[c0 + t]; gws[t] = gw[c0 + t]; gbs[t] = gb[c0 + t]; }

    const int pl = t & 31;
    const int cq = t >> 5;

    const float* xb = x + (size_t)b * CIN * PDIM + (size_t)f0 * PDIM;
    float* rawb = g_raw + (size_t)b * COUT * PDIM + (size_t)c0 * PDIM;

    float sum = 0.f, sumsq = 0.f;

    for (int pt = 0; pt < 16; pt++) {
        __syncthreads();
        for (int i = t; i < 64 * 128; i += 256) {
            int r = i >> 7, cc = i & 127;
            xs[r][cc] = xb[(size_t)r * PDIM + pt * 128 + cc];
        }
        __syncthreads();

        float acc[4][4];
        #pragma unroll
        for (int v = 0; v < 4; v++)
            #pragma unroll
            for (int u = 0; u < 4; u++) acc[v][u] = bs[cq * 4 + v];

        #pragma unroll
        for (int f = 0; f < 64; f++) {
            float xv[4];
            #pragma unroll
            for (int u = 0; u < 4; u++) xv[u] = xs[f][pl + 32 * u];
            #pragma unroll
            for (int v = 0; v < 4; v++) {
                float wv = ws[cq * 4 + v][f];
                #pragma unroll
                for (int u = 0; u < 4; u++) acc[v][u] += wv * xv[u];
            }
        }

        #pragma unroll
        for (int v = 0; v < 4; v++) {
            int c = cq * 4 + v;
            #pragma unroll
            for (int u = 0; u < 4; u++) {
                float a = acc[v][u];
                sum += a; sumsq += a * a;
                rawb[(size_t)c * PDIM + pt * 128 + pl + 32 * u] = a;
            }
        }
    }

    red[t] = sum; __syncthreads();
    for (int s = 128; s > 0; s >>= 1) { if (t < s) red[t] += red[t + s]; __syncthreads(); }
    if (t == 0) stats[0] = red[0] * (1.0f / 65536.0f);
    __syncthreads();
    red[t] = sumsq; __syncthreads();
    for (int s = 128; s > 0; s >>= 1) { if (t < s) red[t] += red[t + s]; __syncthreads(); }
    if (t == 0) {
        float mu = stats[0];
        float var = red[0] * (1.0f / 65536.0f) - mu * mu;
        stats[1] = rsqrtf(var + 1e-5f);
    }
    __syncthreads();
    const float mu = stats[0], inv = stats[1];

    if (which == 0) {
        // Q: transposed layout g_QT[(b,h)][j2][c], bf16x2 pairs along p(=j)
        unsigned* qt = g_QT + (size_t)(b * Hh + (c0 >> 7)) * (PDIM / 2) * Dd;
        const int c0loc = c0 & 127;
        for (int pt = 0; pt < 16; pt++) {
            __syncthreads();
            for (int i = t; i < 32 * 128; i += 256) {
                int c = i >> 7, pp = i & 127;
                float y = rawb[(size_t)c * PDIM + pt * 128 + pp];
                float z = (y - mu) * inv * gws[c] + gbs[c];
                xs[c][pp] = (z >= 0.f) ? z : 0.1f * z;
            }
            __syncthreads();
            for (int i = t; i < 32 * 64; i += 256) {
                int c = i & 31, j2l = i >> 5;
                unsigned v = pack2(xs[c][2 * j2l], xs[c][2 * j2l + 1]);
                qt[(size_t)(pt * 64 + j2l) * Dd + c0loc + c] = v;
            }
        }
    } else {
        // K/V: hi+lo pairs along c
        unsigned* dh = (which == 1 ? g_KH : g_VH) + ((size_t)b * (COUT / 2) + ng * 16) * PDIM;
        unsigned* dl = (which == 1 ? g_KL : g_VL) + ((size_t)b * (COUT / 2) + ng * 16) * PDIM;
        for (int i = t; i < 16 * PDIM; i += 256) {
            int c2l = i >> 11, p = i & (PDIM - 1);
            int ca = 2 * c2l, cb = ca + 1;
            float y0 = rawb[(size_t)ca * PDIM + p];
            float y1 = rawb[(size_t)cb * PDIM + p];
            float z0 = (y0 - mu) * inv * gws[ca] + gbs[ca];
            float z1 = (y1 - mu) * inv * gws[cb] + gbs[cb];
            z0 = (z0 >= 0.f) ? z0 : 0.1f * z0;
            z1 = (z1 >= 0.f) ? z1 : 0.1f * z1;
            unsigned lo;
            unsigned hi = pack_split(z0, z1, lo);
            dh[(size_t)c2l * PDIM + p] = hi;
            dl[(size_t)c2l * PDIM + p] = lo;
        }
    }
}

// ---------------------------------------------------------------------------
// Kernel 2: fused flash attention.
// Block = (i-tile of 128, bh). 8 warps, each owns 16 i-rows x full 64-j tile.
// K (hi+lo) resident in smem [c2=64][i=128]; loop 32 j-tiles of 64:
//   S = scale*K^T V (3-pass bf16 split, fp32 acc) -> online softmax ->
//   P bf16 -> O += P * Q (Q staged [j2][c] per tile, double-buffered cp.async)
// ---------------------------------------------------------------------------
// smem word offsets: KH[64][136]@0  KL@8704  VH[2][64][72]@17408  VL@26624
//                    QH[2][32][136]@35840 ; total 44544 words = 178176 B
#define SM_KL 8704
#define SM_VH 17408
#define SM_VL 26624
#define SM_QH 35840
#define SM_TOTAL_BYTES 178176

__global__ void __launch_bounds__(256, 1) flash_kernel(float* __restrict__ out)
{
    extern __shared__ unsigned sm[];
    unsigned* sKH = sm;
    unsigned* sKL = sm + SM_KL;
    unsigned* sVH = sm + SM_VH;
    unsigned* sVL = sm + SM_VL;
    unsigned* sQH = sm + SM_QH;

    const int bh = blockIdx.y;
    const int b = bh >> 3, h = bh & 7;
    const int i0 = blockIdx.x * BR;
    const int t = threadIdx.x, lane = t & 31, w = t >> 5;
    const int gid = lane >> 2, tig = lane & 3;

    const unsigned* KHb = g_KH + ((size_t)b * (COUT / 2) + h * 64) * PDIM;
    const unsigned* KLb = g_KL + ((size_t)b * (COUT / 2) + h * 64) * PDIM;
    const unsigned* VHb = g_VH + ((size_t)b * (COUT / 2) + h * 64) * PDIM;
    const unsigned* VLb = g_VL + ((size_t)b * (COUT / 2) + h * 64) * PDIM;
    const unsigned* QTb = g_QT + (size_t)bh * (PDIM / 2) * Dd;

    // ---- stage resident K tile (64 c2-rows x 128 i) hi+lo via cp.async ----
    {
        int r = t >> 2, cb = (t & 3) * 32;
        const unsigned* srcH = KHb + (size_t)r * PDIM + i0 + cb;
        const unsigned* srcL = KLb + (size_t)r * PDIM + i0 + cb;
        unsigned dH = smem_u32(sKH + r * 136 + cb);
        unsigned dL = smem_u32(sKL + r * 136 + cb);
        #pragma unroll
        for (int q = 0; q < 8; q++) {
            cp16(dH + q * 16, srcH + q * 4);
            cp16(dL + q * 16, srcL + q * 4);
        }
    }

    // ---- staging helper for V(j-tile) + Q(j-tile) ----
    auto stage_vq = [&](int jt, int buf) {
        const int j0 = jt * BC;
        {
            int r = t >> 2, cb = (t & 3) * 16;
            const unsigned* sH = VHb + (size_t)r * PDIM + j0 + cb;
            const unsigned* sL = VLb + (size_t)r * PDIM + j0 + cb;
            unsigned dH = smem_u32(sVH + buf * 4608 + r * 72 + cb);
            unsigned dL = smem_u32(sVL + buf * 4608 + r * 72 + cb);
            #pragma unroll
            for (int q = 0; q < 4; q++) {
                cp16(dH + q * 16, sH + q * 4);
                cp16(dL + q * 16, sL + q * 4);
            }
        }
        {
            int r = t >> 3, cb = (t & 7) * 16;
            const unsigned* sQ = QTb + (size_t)(jt * 32 + r) * Dd + cb;
            unsigned dQ = smem_u32(sQH + buf * 4352 + r * 136 + cb);
            #pragma unroll
            for (int q = 0; q < 4; q++) cp16(dQ + q * 16, sQ + q * 4);
        }
    };

    stage_vq(0, 0);
    asm volatile("cp.async.commit_group;\n");
    asm volatile("cp.async.wait_group 0;\n");
    __syncthreads();

    float accO[16][4];
    #pragma unroll
    for (int nf = 0; nf < 16; nf++)
        #pragma unroll
        for (int r = 0; r < 4; r++) accO[nf][r] = 0.f;
    float m0 = -1e30f, m1 = -1e30f, l0 = 0.f, l1 = 0.f;
    const float scale = 0.088388347648318447f;  // 1/sqrt(128)
    const int mcol = w * 16 + gid;

    for (int jt = 0; jt < PDIM / BC; jt++) {
        const int cur = jt & 1;
        if (jt + 1 < PDIM / BC) {
            stage_vq(jt + 1, cur ^ 1);
            asm volatile("cp.async.commit_group;\n");
        }

        // ---- S = K^T V over c (3-pass bf16 split) ----
        float accS[8][4];
        #pragma unroll
        for (int nf = 0; nf < 8; nf++)
            #pragma unroll
            for (int r = 0; r < 4; r++) accS[nf][r] = 0.f;

        const unsigned* vH = sVH + cur * 4608;
        const unsigned* vL = sVL + cur * 4608;
        #pragma unroll
        for (int kk = 0; kk < 8; kk++) {
            const int ra = (8 * kk + tig) * 136, rb = (8 * kk + tig + 4) * 136;
            unsigned ah[4], al[4];
            ah[0] = sKH[ra + mcol]; ah[1] = sKH[ra + mcol + 8];
            ah[2] = sKH[rb + mcol]; ah[3] = sKH[rb + mcol + 8];
            al[0] = sKL[ra + mcol]; al[1] = sKL[ra + mcol + 8];
            al[2] = sKL[rb + mcol]; al[3] = sKL[rb + mcol + 8];
            const int va = (8 * kk + tig) * 72 + gid, vb = (8 * kk + tig + 4) * 72 + gid;
            unsigned bhf[8][2], blf[8][2];
            #pragma unroll
            for (int nf = 0; nf < 8; nf++) {
                bhf[nf][0] = vH[va + nf * 8]; bhf[nf][1] = vH[vb + nf * 8];
                blf[nf][0] = vL[va + nf * 8]; blf[nf][1] = vL[vb + nf * 8];
            }
            #pragma unroll
            for (int nf = 0; nf < 8; nf++) mma_bf16(accS[nf], ah, bhf[nf]);
            #pragma unroll
            for (int nf = 0; nf < 8; nf++) mma_bf16(accS[nf], ah, blf[nf]);
            #pragma unroll
            for (int nf = 0; nf < 8; nf++) mma_bf16(accS[nf], al, bhf[nf]);
        }

        // ---- online softmax (rows gid and gid+8; 4 tig lanes share a row) ----
        float rm0 = -1e30f, rm1 = -1e30f;
        #pragma unroll
        for (int nf = 0; nf < 8; nf++) {
            accS[nf][0] *= scale; accS[nf][1] *= scale;
            accS[nf][2] *= scale; accS[nf][3] *= scale;
            rm0 = fmaxf(rm0, fmaxf(accS[nf][0], accS[nf][1]));
            rm1 = fmaxf(rm1, fmaxf(accS[nf][2], accS[nf][3]));
        }
        rm0 = fmaxf(rm0, __shfl_xor_sync(0xffffffffu, rm0, 1));
        rm0 = fmaxf(rm0, __shfl_xor_sync(0xffffffffu, rm0, 2));
        rm1 = fmaxf(rm1, __shfl_xor_sync(0xffffffffu, rm1, 1));
        rm1 = fmaxf(rm1, __shfl_xor_sync(0xffffffffu, rm1, 2));
        const float m0n = fmaxf(m0, rm0), m1n = fmaxf(m1, rm1);
        const float cf0 = __expf(m0 - m0n), cf1 = __expf(m1 - m1n);
        float rs0 = 0.f, rs1 = 0.f;
        #pragma unroll
        for (int nf = 0; nf < 8; nf++) {
            accS[nf][0] = __expf(accS[nf][0] - m0n);
            accS[nf][1] = __expf(accS[nf][1] - m0n);
            accS[nf][2] = __expf(accS[nf][2] - m1n);
            accS[nf][3] = __expf(accS[nf][3] - m1n);
            rs0 += accS[nf][0] + accS[nf][1];
            rs1 += accS[nf][2] + accS[nf][3];
        }
        rs0 += __shfl_xor_sync(0xffffffffu, rs0, 1);
        rs0 += __shfl_xor_sync(0xffffffffu, rs0, 2);
        rs1 += __shfl_xor_sync(0xffffffffu, rs1, 1);
        rs1 += __shfl_xor_sync(0xffffffffu, rs1, 2);
        l0 = l0 * cf0 + rs0; l1 = l1 * cf1 + rs1;
        m0 = m0n; m1 = m1n;
        #pragma unroll
        for (int nf = 0; nf < 16; nf++) {
            accO[nf][0] *= cf0; accO[nf][1] *= cf0;
            accO[nf][2] *= cf1; accO[nf][3] *= cf1;
        }

        // ---- P -> bf16 A-frags (acc m16n8 -> A m16k16 remap) ----
        unsigned pa[4][4];
        #pragma unroll
        for (int kj = 0; kj < 4; kj++) {
            pa[kj][0] = pack2(accS[2 * kj][0], accS[2 * kj][1]);
            pa[kj][1] = pack2(accS[2 * kj][2], accS[2 * kj][3]);
            pa[kj][2] = pack2(accS[2 * kj + 1][0], accS[2 * kj + 1][1]);
            pa[kj][3] = pack2(accS[2 * kj + 1][2], accS[2 * kj + 1][3]);
        }

        // ---- O += P * Q (k = j, 4 k16 steps, n = c 128) ----
        const unsigned* qh = sQH + cur * 4352;
        #pragma unroll
        for (int kj = 0; kj < 4; kj++) {
            const int qa = (8 * kj + tig) * 136 + gid, qb = (8 * kj + tig + 4) * 136 + gid;
            #pragma unroll
            for (int nf2 = 0; nf2 < 16; nf2++) {
                unsigned bq[2];
                bq[0] = qh[qa + nf2 * 8];
                bq[1] = qh[qb + nf2 * 8];
                mma_bf16(accO[nf2], pa[kj], bq);
            }
        }

        asm volatile("cp.async.wait_group 0;\n");
        __syncthreads();
    }

    // ---- epilogue: O /= l, write out[c, i] ----
    const float inv0 = 1.0f / l0, inv1 = 1.0f / l1;
    float* Ob = out + ((size_t)b * COUT + h * Dd) * PDIM;
    const int ir0 = i0 + w * 16 + gid;
    #pragma unroll
    for (int nf2 = 0; nf2 < 16; nf2++) {
        const int c = nf2 * 8 + 2 * tig;
        Ob[(size_t)c * PDIM + ir0]           = accO[nf2][0] * inv0;
        Ob[(size_t)(c + 1) * PDIM + ir0]     = accO[nf2][1] * inv0;
        Ob[(size_t)c * PDIM + ir0 + 8]       = accO[nf2][2] * inv1;
        Ob[(size_t)(c + 1) * PDIM + ir0 + 8] = accO[nf2][3] * inv1;
    }
}

// ---------------------------------------------------------------------------
extern "C" void kernel_launch(void* const* d_in, const int* in_sizes, int n_in,
                              void* d_out, int out_size)
{
    const float* x   = (const float*)d_in[0];
    const float* wq  = (const float*)d_in[1];
    const float* bq  = (const float*)d_in[2];
    const float* gw1 = (const float*)d_in[3];
    const float* gb1 = (const float*)d_in[4];
    const float* wk  = (const float*)d_in[5];
    const float* bk  = (const float*)d_in[6];
    const float* gw2 = (const float*)d_in[7];
    const float* gb2 = (const float*)d_in[8];
    const float* wv  = (const float*)d_in[9];
    const float* bv  = (const float*)d_in[10];
    const float* gw3 = (const float*)d_in[11];
    const float* gb3 = (const float*)d_in[12];
    float* out = (float*)d_out;

    static int smem_set = 0;
    if (!smem_set) {
        cudaFuncSetAttribute(flash_kernel,
                             cudaFuncAttributeMaxDynamicSharedMemorySize,
                             SM_TOTAL_BYTES);
        smem_set = 1;
    }

    dim3 g1(NG, B_);
    qkv_gn_kernel<<<g1, 256>>>(x, wq, bq, gw1, gb1, 0);
    qkv_gn_kernel<<<g1, 256>>>(x, wk, bk, gw2, gb2, 1);
    qkv_gn_kernel<<<g1, 256>>>(x, wv, bv, gw3, gb3, 2);

    dim3 gf(PDIM / BR, B_ * Hh);
    flash_kernel<<<gf, 256, SM_TOTAL_BYTES>>>(out);
}

// round 9
// speedup vs baseline: 4.6808x; 1.3948x over previous
#include <cuda_runtime.h>
#include <cuda_bf16.h>
#include <stdint.h>

#define B_    8
#define CIN   512
#define COUT  1024
#define PDIM  2048
#define Hh    8
#define NG    32

// ------------------------- device scratch (static) -------------------------
__device__ float g_raw[(size_t)3 * B_ * COUT * PDIM];     // per-branch pre-norm y
// tile buffers for ldmatrix-friendly layouts
__device__ uint4 g_Kt[(size_t)B_ * Hh * 16 * 4096];   // [bh][it][hi2048|lo2048] rows i, 16 c2-quads
__device__ uint4 g_Vt[(size_t)B_ * Hh * 32 * 2048];   // [bh][jt][hi1024|lo1024] rows j, 16 c2-quads
__device__ uint4 g_Qt[(size_t)B_ * Hh * 32 * 1024];   // [bh][jt] rows c(128), 8 j2-quads

// ------------------------------- helpers -----------------------------------
__device__ __forceinline__ unsigned pack2(float a, float b) {
    __nv_bfloat162 h2 = __floats2bfloat162_rn(a, b);
    return *reinterpret_cast<unsigned*>(&h2);
}
__device__ __forceinline__ void cp16(unsigned s, const void* g) {
    asm volatile("cp.async.cg.shared.global [%0], [%1], 16;" :: "r"(s), "l"(g));
}
__device__ __forceinline__ void ldsm4(unsigned (&d)[4], unsigned addr) {
    asm volatile("ldmatrix.sync.aligned.m8n8.x4.shared.b16 {%0,%1,%2,%3}, [%4];"
                 : "=r"(d[0]), "=r"(d[1]), "=r"(d[2]), "=r"(d[3]) : "r"(addr));
}
__device__ __forceinline__ void mma_bf16(float (&c)[4], const unsigned (&a)[4],
                                          const unsigned (&b)[2]) {
    asm volatile(
        "mma.sync.aligned.m16n8k16.row.col.f32.bf16.bf16.f32 "
        "{%0,%1,%2,%3}, {%4,%5,%6,%7}, {%8,%9}, {%0,%1,%2,%3};\n"
        : "+f"(c[0]), "+f"(c[1]), "+f"(c[2]), "+f"(c[3])
        : "r"(a[0]), "r"(a[1]), "r"(a[2]), "r"(a[3]), "r"(b[0]), "r"(b[1]));
}

// ---------------------------------------------------------------------------
// Kernel 1: grouped 1x1 conv + bias -> GroupNorm -> LeakyReLU -> tile buffers
// One launch, blockIdx.z = which (0=Q, 1=K, 2=V).
// ---------------------------------------------------------------------------
__global__ __launch_bounds__(256) void qkv_gn_kernel(
    const float* __restrict__ x,
    const float* __restrict__ wq, const float* __restrict__ bq_,
    const float* __restrict__ gw1, const float* __restrict__ gb1,
    const float* __restrict__ wk, const float* __restrict__ bk_,
    const float* __restrict__ gw2, const float* __restrict__ gb2,
    const float* __restrict__ wv, const float* __restrict__ bv_,
    const float* __restrict__ gw3, const float* __restrict__ gb3)
{
    const int which = blockIdx.z;
    const float* w    = which == 0 ? wq  : which == 1 ? wk  : wv;
    const float* bias = which == 0 ? bq_ : which == 1 ? bk_ : bv_;
    const float* gw   = which == 0 ? gw1 : which == 1 ? gw2 : gw3;
    const float* gb   = which == 0 ? gb1 : which == 1 ? gb2 : gb3;

    const int ng = blockIdx.x;
    const int b  = blockIdx.y;
    const int c0 = ng * 32;
    const int g  = c0 >> 7;
    const int f0 = g * 64;

    __shared__ float xs[64][129];
    __shared__ float ws[32][64];
    __shared__ float bs[32], gws[32], gbs[32];
    __shared__ float red[256];
    __shared__ float stats[2];

    const int t = threadIdx.x;

    for (int i = t; i < 32 * 64; i += 256) {
        int c = i >> 6, f = i & 63;
        ws[c][f] = w[(size_t)(c0 + c) * 64 + f];
    }
    if (t < 32) { bs[t] = bias[c0 + t]; gws[t] = gw[c0 + t]; gbs[t] = gb[c0 + t]; }

    const int pl = t & 31;
    const int cq = t >> 5;

    const float* xb = x + (size_t)b * CIN * PDIM + (size_t)f0 * PDIM;
    float* rawb = g_raw + ((size_t)which * B_ * COUT + (size_t)b * COUT + c0) * PDIM;

    float sum = 0.f, sumsq = 0.f;

    for (int pt = 0; pt < 16; pt++) {
        __syncthreads();
        for (int i = t; i < 64 * 128; i += 256) {
            int r = i >> 7, cc = i & 127;
            xs[r][cc] = xb[(size_t)r * PDIM + pt * 128 + cc];
        }
        __syncthreads();

        float acc[4][4];
        #pragma unroll
        for (int v = 0; v < 4; v++)
            #pragma unroll
            for (int u = 0; u < 4; u++) acc[v][u] = bs[cq * 4 + v];

        #pragma unroll
        for (int f = 0; f < 64; f++) {
            float xv[4];
            #pragma unroll
            for (int u = 0; u < 4; u++) xv[u] = xs[f][pl + 32 * u];
            #pragma unroll
            for (int v = 0; v < 4; v++) {
                float wv = ws[cq * 4 + v][f];
                #pragma unroll
                for (int u = 0; u < 4; u++) acc[v][u] += wv * xv[u];
            }
        }

        #pragma unroll
        for (int v = 0; v < 4; v++) {
            int c = cq * 4 + v;
            #pragma unroll
            for (int u = 0; u < 4; u++) {
                float a = acc[v][u];
                sum += a; sumsq += a * a;
                rawb[(size_t)c * PDIM + pt * 128 + pl + 32 * u] = a;
            }
        }
    }

    red[t] = sum; __syncthreads();
    for (int s = 128; s > 0; s >>= 1) { if (t < s) red[t] += red[t + s]; __syncthreads(); }
    if (t == 0) stats[0] = red[0] * (1.0f / 65536.0f);
    __syncthreads();
    red[t] = sumsq; __syncthreads();
    for (int s = 128; s > 0; s >>= 1) { if (t < s) red[t] += red[t + s]; __syncthreads(); }
    if (t == 0) {
        float mu = stats[0];
        float var = red[0] * (1.0f / 65536.0f) - mu * mu;
        stats[1] = rsqrtf(var + 1e-5f);
    }
    __syncthreads();
    const float mu = stats[0], inv = stats[1];

    const int h = ng >> 2;              // head
    const int bh = b * Hh + h;
    const int c0loc = c0 & 127;         // channel base within head
    const int ngl = ng & 3;             // c2-quad base = ngl*4

    for (int pt = 0; pt < 16; pt++) {
        __syncthreads();
        for (int i = t; i < 32 * 128; i += 256) {
            int c = i >> 7, pp = i & 127;
            float y = rawb[(size_t)c * PDIM + pt * 128 + pp];
            float z = (y - mu) * inv * gws[c] + gbs[c];
            xs[c][pp] = (z >= 0.f) ? z : 0.1f * z;
        }
        __syncthreads();

        if (which == 0) {
            // Q tiles: [bh][jt][c=128 rows][8 j2-quads], plain bf16
            for (int idx = t; idx < 512; idx += 256) {
                int cl = idx >> 4, u = idx & 15;
                int jt = 2 * pt + (u >> 3), qd = u & 7;
                int jbase = (u >> 3) * 64 + qd * 8;
                uint4 hv;
                hv.x = pack2(xs[cl][jbase + 0], xs[cl][jbase + 1]);
                hv.y = pack2(xs[cl][jbase + 2], xs[cl][jbase + 3]);
                hv.z = pack2(xs[cl][jbase + 4], xs[cl][jbase + 5]);
                hv.w = pack2(xs[cl][jbase + 6], xs[cl][jbase + 7]);
                g_Qt[(size_t)(bh * 32 + jt) * 1024 + (c0loc + cl) * 8 + qd] = hv;
            }
        } else {
            // K/V tiles: rows = p(i or j), cols = c2; hi + lo split
            for (int idx = t; idx < 512; idx += 256) {
                int il = idx >> 2, qd = idx & 3;
                unsigned hw[4], lw[4];
                #pragma unroll
                for (int k2 = 0; k2 < 4; k2++) {
                    float a  = xs[qd * 8 + 2 * k2][il];
                    float b2 = xs[qd * 8 + 2 * k2 + 1][il];
                    __nv_bfloat16 ha = __float2bfloat16(a), hb = __float2bfloat16(b2);
                    __nv_bfloat162 hh; hh.x = ha; hh.y = hb;
                    hw[k2] = *(unsigned*)&hh;
                    __nv_bfloat162 ll = __floats2bfloat162_rn(
                        a - __bfloat162float(ha), b2 - __bfloat162float(hb));
                    lw[k2] = *(unsigned*)&ll;
                }
                uint4 hv = make_uint4(hw[0], hw[1], hw[2], hw[3]);
                uint4 lv = make_uint4(lw[0], lw[1], lw[2], lw[3]);
                int q16 = ngl * 4 + qd;  // c2-quad within head (0..15)
                if (which == 1) {
                    size_t tb = (size_t)(bh * 16 + pt) * 4096;
                    unsigned u = il * 16 + q16;
                    g_Kt[tb + u]        = hv;
                    g_Kt[tb + 2048 + u] = lv;
                } else {
                    int jt = 2 * pt + (il >> 6), j = il & 63;
                    size_t tb = (size_t)(bh * 32 + jt) * 2048;
                    unsigned u = j * 16 + q16;
                    g_Vt[tb + u]        = hv;
                    g_Vt[tb + 1024 + u] = lv;
                }
            }
        }
    }
}

// ---------------------------------------------------------------------------
// Kernel 2: fused flash attention, ldmatrix-fed mma.sync.
// CTA = (i-tile 128, bh), 256 threads / 8 warps; warp w owns i-rows w*16..+15.
// K resident in smem [i=128][c2 stride 68 words] hi+lo.
// Per j-tile(64): S = K^T V (3-pass bf16 split) -> online softmax (regs) ->
// P bf16 A-frags -> O += P*Q (Q [c][j2 stride 36]); V/Q double-buffered.
// ---------------------------------------------------------------------------
#define SK_L   34816
#define SV     69632
#define SV_BUF 34816
#define SV_LO  17408
#define SQ     139264
#define SQ_BUF 18432
#define SMEM_BYTES 176128

__global__ void __launch_bounds__(256, 1) flash_kernel(float* __restrict__ out)
{
    extern __shared__ unsigned char sm[];
    const unsigned sb = (unsigned)__cvta_generic_to_shared(sm);
    const int t = threadIdx.x, lane = t & 31, wrp = t >> 5;
    const int gid = lane >> 2, tig = lane & 3;
    const int it = blockIdx.x, bh = blockIdx.y;
    const int b = bh >> 3, h = bh & 7;
    const int i0 = it * 128;

    // ---- resident K staging (hi+lo, 64KB) ----
    {
        const uint4* src = g_Kt + (size_t)(bh * 16 + it) * 4096;
        #pragma unroll
        for (int qq = 0; qq < 16; qq++) {
            int ch = t + 256 * qq;
            int part = ch >> 11, i = (ch >> 4) & 127, qd = ch & 15;
            cp16(sb + part * SK_L + i * 272 + qd * 16, src + ch);
        }
    }
    auto stage_vq = [&](int jt, int buf) {
        const uint4* vs = g_Vt + (size_t)(bh * 32 + jt) * 2048;
        #pragma unroll
        for (int qq = 0; qq < 8; qq++) {
            int ch = t + 256 * qq;
            int part = ch >> 10, j = (ch >> 4) & 63, qd = ch & 15;
            cp16(sb + SV + buf * SV_BUF + part * SV_LO + j * 272 + qd * 16, vs + ch);
        }
        const uint4* qs = g_Qt + (size_t)(bh * 32 + jt) * 1024;
        #pragma unroll
        for (int qq = 0; qq < 4; qq++) {
            int ch = t + 256 * qq;
            int cr = ch >> 3, qd = ch & 7;
            cp16(sb + SQ + buf * SQ_BUF + cr * 144 + qd * 16, qs + ch);
        }
    };
    stage_vq(0, 0);
    asm volatile("cp.async.commit_group;" ::: "memory");
    asm volatile("cp.async.wait_group 0;" ::: "memory");
    __syncthreads();

    // ---- per-lane ldmatrix base offsets ----
    const int lq = lane >> 3, lr = lane & 7;
    // A (K): matrices: q0:(m0-7,h0) q1:(m8-15,h0) q2:(m0-7,h1) q3:(m8-15,h1)
    const unsigned aOff = (wrp * 16 + ((lq & 1) << 3) + lr) * 272 + (lq >> 1) * 16;
    // B (V/Q): q0:(n0-7,h0) q1:(n0-7,h1) q2:(n8-15,h0) q3:(n8-15,h1)
    const unsigned bRow = ((lq >> 1) << 3) + lr;
    const unsigned bHlf = (lq & 1) * 16;

    float accO[16][4];
    #pragma unroll
    for (int nf = 0; nf < 16; nf++)
        #pragma unroll
        for (int r = 0; r < 4; r++) accO[nf][r] = 0.f;
    float m0 = -1e30f, m1 = -1e30f, l0 = 0.f, l1 = 0.f;
    const float scale = 0.088388347648318447f;  // 1/sqrt(128)

    for (int jt = 0; jt < 32; jt++) {
        const int cur = jt & 1;
        if (jt < 31) {
            stage_vq(jt + 1, cur ^ 1);
            asm volatile("cp.async.commit_group;" ::: "memory");
        }

        // ---- S = K^T V (3-pass split) ----
        float accS[8][4];
        #pragma unroll
        for (int nf = 0; nf < 8; nf++)
            #pragma unroll
            for (int r = 0; r < 4; r++) accS[nf][r] = 0.f;

        const unsigned aH = sb + aOff;
        const unsigned aL = aH + SK_L;
        const unsigned vH = sb + SV + cur * SV_BUF + bRow * 272 + bHlf;
        const unsigned vL = vH + SV_LO;
        #pragma unroll
        for (int kk = 0; kk < 8; kk++) {
            unsigned ah[4], al[4];
            ldsm4(ah, aH + kk * 32);
            ldsm4(al, aL + kk * 32);
            unsigned bhf[4][4], blf[4][4];
            #pragma unroll
            for (int g2 = 0; g2 < 4; g2++) {
                ldsm4(bhf[g2], vH + g2 * (16 * 272) + kk * 32);
                ldsm4(blf[g2], vL + g2 * (16 * 272) + kk * 32);
            }
            #pragma unroll
            for (int nf = 0; nf < 8; nf++) {
                unsigned bb[2] = {bhf[nf >> 1][2 * (nf & 1)], bhf[nf >> 1][2 * (nf & 1) + 1]};
                mma_bf16(accS[nf], ah, bb);
            }
            #pragma unroll
            for (int nf = 0; nf < 8; nf++) {
                unsigned bb[2] = {blf[nf >> 1][2 * (nf & 1)], blf[nf >> 1][2 * (nf & 1) + 1]};
                mma_bf16(accS[nf], ah, bb);
            }
            #pragma unroll
            for (int nf = 0; nf < 8; nf++) {
                unsigned bb[2] = {bhf[nf >> 1][2 * (nf & 1)], bhf[nf >> 1][2 * (nf & 1) + 1]};
                mma_bf16(accS[nf], al, bb);
            }
        }

        // ---- online softmax (rows gid, gid+8; 4 tig lanes share a row) ----
        float rm0 = -1e30f, rm1 = -1e30f;
        #pragma unroll
        for (int nf = 0; nf < 8; nf++) {
            accS[nf][0] *= scale; accS[nf][1] *= scale;
            accS[nf][2] *= scale; accS[nf][3] *= scale;
            rm0 = fmaxf(rm0, fmaxf(accS[nf][0], accS[nf][1]));
            rm1 = fmaxf(rm1, fmaxf(accS[nf][2], accS[nf][3]));
        }
        rm0 = fmaxf(rm0, __shfl_xor_sync(0xffffffffu, rm0, 1));
        rm0 = fmaxf(rm0, __shfl_xor_sync(0xffffffffu, rm0, 2));
        rm1 = fmaxf(rm1, __shfl_xor_sync(0xffffffffu, rm1, 1));
        rm1 = fmaxf(rm1, __shfl_xor_sync(0xffffffffu, rm1, 2));
        const float m0n = fmaxf(m0, rm0), m1n = fmaxf(m1, rm1);
        const float cf0 = __expf(m0 - m0n), cf1 = __expf(m1 - m1n);
        float rs0 = 0.f, rs1 = 0.f;
        #pragma unroll
        for (int nf = 0; nf < 8; nf++) {
            accS[nf][0] = __expf(accS[nf][0] - m0n);
            accS[nf][1] = __expf(accS[nf][1] - m0n);
            accS[nf][2] = __expf(accS[nf][2] - m1n);
            accS[nf][3] = __expf(accS[nf][3] - m1n);
            rs0 += accS[nf][0] + accS[nf][1];
            rs1 += accS[nf][2] + accS[nf][3];
        }
        rs0 += __shfl_xor_sync(0xffffffffu, rs0, 1);
        rs0 += __shfl_xor_sync(0xffffffffu, rs0, 2);
        rs1 += __shfl_xor_sync(0xffffffffu, rs1, 1);
        rs1 += __shfl_xor_sync(0xffffffffu, rs1, 2);
        l0 = l0 * cf0 + rs0; l1 = l1 * cf1 + rs1;
        m0 = m0n; m1 = m1n;
        #pragma unroll
        for (int nf = 0; nf < 16; nf++) {
            accO[nf][0] *= cf0; accO[nf][1] *= cf0;
            accO[nf][2] *= cf1; accO[nf][3] *= cf1;
        }

        // ---- P -> bf16 A-frags ----
        unsigned pa[4][4];
        #pragma unroll
        for (int kj = 0; kj < 4; kj++) {
            pa[kj][0] = pack2(accS[2 * kj][0], accS[2 * kj][1]);
            pa[kj][1] = pack2(accS[2 * kj][2], accS[2 * kj][3]);
            pa[kj][2] = pack2(accS[2 * kj + 1][0], accS[2 * kj + 1][1]);
            pa[kj][3] = pack2(accS[2 * kj + 1][2], accS[2 * kj + 1][3]);
        }

        // ---- O += P * Q ----
        const unsigned qB = sb + SQ + cur * SQ_BUF + bRow * 144 + bHlf;
        #pragma unroll
        for (int kj = 0; kj < 4; kj++) {
            unsigned qf[8][4];
            #pragma unroll
            for (int g2 = 0; g2 < 8; g2++)
                ldsm4(qf[g2], qB + g2 * (16 * 144) + kj * 32);
            #pragma unroll
            for (int nf = 0; nf < 16; nf++) {
                unsigned bb[2] = {qf[nf >> 1][2 * (nf & 1)], qf[nf >> 1][2 * (nf & 1) + 1]};
                mma_bf16(accO[nf], pa[kj], bb);
            }
        }

        asm volatile("cp.async.wait_group 0;" ::: "memory");
        __syncthreads();
    }

    // ---- epilogue: O /= l, write out[c, i] ----
    const float inv0 = 1.0f / l0, inv1 = 1.0f / l1;
    float* Ob = out + ((size_t)b * COUT + h * 128) * PDIM;
    const int ir0 = i0 + wrp * 16 + gid;
    #pragma unroll
    for (int nf = 0; nf < 16; nf++) {
        const int c = nf * 8 + 2 * tig;
        Ob[(size_t)c * PDIM + ir0]           = accO[nf][0] * inv0;
        Ob[(size_t)(c + 1) * PDIM + ir0]     = accO[nf][1] * inv0;
        Ob[(size_t)c * PDIM + ir0 + 8]       = accO[nf][2] * inv1;
        Ob[(size_t)(c + 1) * PDIM + ir0 + 8] = accO[nf][3] * inv1;
    }
}

// ---------------------------------------------------------------------------
extern "C" void kernel_launch(void* const* d_in, const int* in_sizes, int n_in,
                              void* d_out, int out_size)
{
    const float* x   = (const float*)d_in[0];
    const float* wq  = (const float*)d_in[1];
    const float* bq  = (const float*)d_in[2];
    const float* gw1 = (const float*)d_in[3];
    const float* gb1 = (const float*)d_in[4];
    const float* wk  = (const float*)d_in[5];
    const float* bk  = (const float*)d_in[6];
    const float* gw2 = (const float*)d_in[7];
    const float* gb2 = (const float*)d_in[8];
    const float* wv  = (const float*)d_in[9];
    const float* bv  = (const float*)d_in[10];
    const float* gw3 = (const float*)d_in[11];
    const float* gb3 = (const float*)d_in[12];
    float* out = (float*)d_out;

    static int smem_set = 0;
    if (!smem_set) {
        cudaFuncSetAttribute(flash_kernel,
                             cudaFuncAttributeMaxDynamicSharedMemorySize,
                             SMEM_BYTES);
        smem_set = 1;
    }

    dim3 g1(NG, B_, 3);
    qkv_gn_kernel<<<g1, 256>>>(x, wq, bq, gw1, gb1, wk, bk, gw2, gb2,
                               wv, bv, gw3, gb3);

    dim3 gf(PDIM / 128, B_ * Hh);
    flash_kernel<<<gf, 256, SMEM_BYTES>>>(out);
}

// round 10
// speedup vs baseline: 5.5134x; 1.1779x over previous
#include <cuda_runtime.h>
#include <cuda_fp16.h>
#include <stdint.h>

#define B_    8
#define CIN   512
#define COUT  1024
#define PDIM  2048
#define Hh    8
#define NG    32

// ------------------------- device scratch (static) -------------------------
__device__ float g_raw[(size_t)3 * B_ * COUT * PDIM];     // per-branch pre-norm y
// fp16 tile buffers (ldmatrix-friendly row layouts)
__device__ uint4 g_Kt[(size_t)B_ * Hh * 16 * 4096];   // [bh][it][hi2048|lo2048] rows i, 16 c2-quads
__device__ uint4 g_Vt[(size_t)B_ * Hh * 32 * 1024];   // [bh][jt] rows j(64), 16 c2-quads (hi only)
__device__ uint4 g_Qt[(size_t)B_ * Hh * 32 * 1024];   // [bh][jt] rows c(128), 8 j2-quads

// ------------------------------- helpers -----------------------------------
__device__ __forceinline__ unsigned packh2(float a, float b) {
    __half2 h = __floats2half2_rn(a, b);
    return *reinterpret_cast<unsigned*>(&h);
}
__device__ __forceinline__ float ex2(float x) {
    float r;
    asm("ex2.approx.f32 %0, %1;" : "=f"(r) : "f"(x));
    return r;
}
__device__ __forceinline__ void cp16(unsigned s, const void* g) {
    asm volatile("cp.async.cg.shared.global [%0], [%1], 16;" :: "r"(s), "l"(g));
}
__device__ __forceinline__ void ldsm4(unsigned (&d)[4], unsigned addr) {
    asm volatile("ldmatrix.sync.aligned.m8n8.x4.shared.b16 {%0,%1,%2,%3}, [%4];"
                 : "=r"(d[0]), "=r"(d[1]), "=r"(d[2]), "=r"(d[3]) : "r"(addr));
}
__device__ __forceinline__ void mma_fp16(float (&c)[4], const unsigned (&a)[4],
                                          const unsigned (&b)[2]) {
    asm volatile(
        "mma.sync.aligned.m16n8k16.row.col.f32.f16.f16.f32 "
        "{%0,%1,%2,%3}, {%4,%5,%6,%7}, {%8,%9}, {%0,%1,%2,%3};\n"
        : "+f"(c[0]), "+f"(c[1]), "+f"(c[2]), "+f"(c[3])
        : "r"(a[0]), "r"(a[1]), "r"(a[2]), "r"(a[3]), "r"(b[0]), "r"(b[1]));
}

// ---------------------------------------------------------------------------
// Kernel 1: grouped 1x1 conv + bias -> GroupNorm -> LeakyReLU -> fp16 tiles
// One launch, blockIdx.z = which (0=Q, 1=K, 2=V).
// ---------------------------------------------------------------------------
__global__ __launch_bounds__(256) void qkv_gn_kernel(
    const float* __restrict__ x,
    const float* __restrict__ wq, const float* __restrict__ bq_,
    const float* __restrict__ gw1, const float* __restrict__ gb1,
    const float* __restrict__ wk, const float* __restrict__ bk_,
    const float* __restrict__ gw2, const float* __restrict__ gb2,
    const float* __restrict__ wv, const float* __restrict__ bv_,
    const float* __restrict__ gw3, const float* __restrict__ gb3)
{
    const int which = blockIdx.z;
    const float* w    = which == 0 ? wq  : which == 1 ? wk  : wv;
    const float* bias = which == 0 ? bq_ : which == 1 ? bk_ : bv_;
    const float* gw   = which == 0 ? gw1 : which == 1 ? gw2 : gw3;
    const float* gb   = which == 0 ? gb1 : which == 1 ? gb2 : gb3;

    const int ng = blockIdx.x;
    const int b  = blockIdx.y;
    const int c0 = ng * 32;
    const int g  = c0 >> 7;
    const int f0 = g * 64;

    __shared__ float xs[64][129];
    __shared__ float ws[32][64];
    __shared__ float bs[32], gws[32], gbs[32];
    __shared__ float red[256];
    __shared__ float stats[2];

    const int t = threadIdx.x;

    for (int i = t; i < 32 * 64; i += 256) {
        int c = i >> 6, f = i & 63;
        ws[c][f] = w[(size_t)(c0 + c) * 64 + f];
    }
    if (t < 32) { bs[t] = bias[c0 + t]; gws[t] = gw[c0 + t]; gbs[t] = gb[c0 + t]; }

    const int pl = t & 31;
    const int cq = t >> 5;

    const float* xb = x + (size_t)b * CIN * PDIM + (size_t)f0 * PDIM;
    float* rawb = g_raw + ((size_t)which * B_ * COUT + (size_t)b * COUT + c0) * PDIM;

    float sum = 0.f, sumsq = 0.f;

    for (int pt = 0; pt < 16; pt++) {
        __syncthreads();
        for (int i = t; i < 64 * 128; i += 256) {
            int r = i >> 7, cc = i & 127;
            xs[r][cc] = xb[(size_t)r * PDIM + pt * 128 + cc];
        }
        __syncthreads();

        float acc[4][4];
        #pragma unroll
        for (int v = 0; v < 4; v++)
            #pragma unroll
            for (int u = 0; u < 4; u++) acc[v][u] = bs[cq * 4 + v];

        #pragma unroll
        for (int f = 0; f < 64; f++) {
            float xv[4];
            #pragma unroll
            for (int u = 0; u < 4; u++) xv[u] = xs[f][pl + 32 * u];
            #pragma unroll
            for (int v = 0; v < 4; v++) {
                float wv = ws[cq * 4 + v][f];
                #pragma unroll
                for (int u = 0; u < 4; u++) acc[v][u] += wv * xv[u];
            }
        }

        #pragma unroll
        for (int v = 0; v < 4; v++) {
            int c = cq * 4 + v;
            #pragma unroll
            for (int u = 0; u < 4; u++) {
                float a = acc[v][u];
                sum += a; sumsq += a * a;
                rawb[(size_t)c * PDIM + pt * 128 + pl + 32 * u] = a;
            }
        }
    }

    red[t] = sum; __syncthreads();
    for (int s = 128; s > 0; s >>= 1) { if (t < s) red[t] += red[t + s]; __syncthreads(); }
    if (t == 0) stats[0] = red[0] * (1.0f / 65536.0f);
    __syncthreads();
    red[t] = sumsq; __syncthreads();
    for (int s = 128; s > 0; s >>= 1) { if (t < s) red[t] += red[t + s]; __syncthreads(); }
    if (t == 0) {
        float mu = stats[0];
        float var = red[0] * (1.0f / 65536.0f) - mu * mu;
        stats[1] = rsqrtf(var + 1e-5f);
    }
    __syncthreads();
    const float mu = stats[0], inv = stats[1];

    const int h = ng >> 2;              // head
    const int bh = b * Hh + h;
    const int c0loc = c0 & 127;         // channel base within head
    const int ngl = ng & 3;             // c2-quad base = ngl*4

    for (int pt = 0; pt < 16; pt++) {
        __syncthreads();
        for (int i = t; i < 32 * 128; i += 256) {
            int c = i >> 7, pp = i & 127;
            float y = rawb[(size_t)c * PDIM + pt * 128 + pp];
            float z = (y - mu) * inv * gws[c] + gbs[c];
            xs[c][pp] = (z >= 0.f) ? z : 0.1f * z;
        }
        __syncthreads();

        if (which == 0) {
            // Q tiles: [bh][jt][c=128 rows][8 j2-quads], fp16
            for (int idx = t; idx < 512; idx += 256) {
                int cl = idx >> 4, u = idx & 15;
                int jt = 2 * pt + (u >> 3), qd = u & 7;
                int jbase = (u >> 3) * 64 + qd * 8;
                uint4 hv;
                hv.x = packh2(xs[cl][jbase + 0], xs[cl][jbase + 1]);
                hv.y = packh2(xs[cl][jbase + 2], xs[cl][jbase + 3]);
                hv.z = packh2(xs[cl][jbase + 4], xs[cl][jbase + 5]);
                hv.w = packh2(xs[cl][jbase + 6], xs[cl][jbase + 7]);
                g_Qt[(size_t)(bh * 32 + jt) * 1024 + (c0loc + cl) * 8 + qd] = hv;
            }
        } else if (which == 1) {
            // K tiles: rows = i, cols = c2; fp16 hi + lo split
            for (int idx = t; idx < 512; idx += 256) {
                int il = idx >> 2, qd = idx & 3;
                unsigned hw[4], lw[4];
                #pragma unroll
                for (int k2 = 0; k2 < 4; k2++) {
                    float a  = xs[qd * 8 + 2 * k2][il];
                    float b2 = xs[qd * 8 + 2 * k2 + 1][il];
                    __half ha = __float2half_rn(a), hb2 = __float2half_rn(b2);
                    __half2 hh; hh.x = ha; hh.y = hb2;
                    hw[k2] = *(unsigned*)&hh;
                    __half2 ll = __floats2half2_rn(
                        a - __half2float(ha), b2 - __half2float(hb2));
                    lw[k2] = *(unsigned*)&ll;
                }
                int q16 = ngl * 4 + qd;
                size_t tb = (size_t)(bh * 16 + pt) * 4096;
                unsigned u = il * 16 + q16;
                g_Kt[tb + u]        = make_uint4(hw[0], hw[1], hw[2], hw[3]);
                g_Kt[tb + 2048 + u] = make_uint4(lw[0], lw[1], lw[2], lw[3]);
            }
        } else {
            // V tiles: rows = j, cols = c2; fp16 single
            for (int idx = t; idx < 512; idx += 256) {
                int il = idx >> 2, qd = idx & 3;
                unsigned hw[4];
                #pragma unroll
                for (int k2 = 0; k2 < 4; k2++)
                    hw[k2] = packh2(xs[qd * 8 + 2 * k2][il],
                                    xs[qd * 8 + 2 * k2 + 1][il]);
                int q16 = ngl * 4 + qd;
                int jt = 2 * pt + (il >> 6), j = il & 63;
                size_t tb = (size_t)(bh * 32 + jt) * 1024;
                g_Vt[tb + j * 16 + q16] = make_uint4(hw[0], hw[1], hw[2], hw[3]);
            }
        }
    }
}

// ---------------------------------------------------------------------------
// Kernel 2: fused flash attention, fp16 ldmatrix-fed mma.sync.
// CTA = (i-tile 128, bh), 256 threads / 8 warps; warp w owns i-rows w*16..+15.
// K resident in smem [i=128][c2 stride 272B] hi+lo (fp16 split).
// Per j-tile(64): S = (Khi + Klo)^T V (2-pass) -> online softmax (exp2) ->
// P fp16 A-frags -> O += P*Q; V/Q double-buffered cp.async.
// ---------------------------------------------------------------------------
#define SK_L   34816
#define SV     69632
#define SV_BUF 17408
#define SQ     104448
#define SQ_BUF 18432
#define SMEM_BYTES 141312

__global__ void __launch_bounds__(256, 1) flash_kernel(float* __restrict__ out)
{
    extern __shared__ unsigned char sm[];
    const unsigned sb = (unsigned)__cvta_generic_to_shared(sm);
    const int t = threadIdx.x, lane = t & 31, wrp = t >> 5;
    const int gid = lane >> 2, tig = lane & 3;
    const int it = blockIdx.x, bh = blockIdx.y;
    const int b = bh >> 3, h = bh & 7;
    const int i0 = it * 128;

    // ---- resident K staging (hi+lo, 64KB) ----
    {
        const uint4* src = g_Kt + (size_t)(bh * 16 + it) * 4096;
        #pragma unroll
        for (int qq = 0; qq < 16; qq++) {
            int ch = t + 256 * qq;
            int part = ch >> 11, i = (ch >> 4) & 127, qd = ch & 15;
            cp16(sb + part * SK_L + i * 272 + qd * 16, src + ch);
        }
    }
    auto stage_vq = [&](int jt, int buf) {
        const uint4* vs = g_Vt + (size_t)(bh * 32 + jt) * 1024;
        #pragma unroll
        for (int qq = 0; qq < 4; qq++) {
            int ch = t + 256 * qq;
            int j = ch >> 4, qd = ch & 15;
            cp16(sb + SV + buf * SV_BUF + j * 272 + qd * 16, vs + ch);
        }
        const uint4* qs = g_Qt + (size_t)(bh * 32 + jt) * 1024;
        #pragma unroll
        for (int qq = 0; qq < 4; qq++) {
            int ch = t + 256 * qq;
            int cr = ch >> 3, qd = ch & 7;
            cp16(sb + SQ + buf * SQ_BUF + cr * 144 + qd * 16, qs + ch);
        }
    };
    stage_vq(0, 0);
    asm volatile("cp.async.commit_group;" ::: "memory");
    asm volatile("cp.async.wait_group 0;" ::: "memory");
    __syncthreads();

    // ---- per-lane ldmatrix base offsets ----
    const int lq = lane >> 3, lr = lane & 7;
    const unsigned aOff = (wrp * 16 + ((lq & 1) << 3) + lr) * 272 + (lq >> 1) * 16;
    const unsigned bRow = ((lq >> 1) << 3) + lr;
    const unsigned bHlf = (lq & 1) * 16;

    float accO[16][4];
    #pragma unroll
    for (int nf = 0; nf < 16; nf++)
        #pragma unroll
        for (int r = 0; r < 4; r++) accO[nf][r] = 0.f;
    float m0 = -1e30f, m1 = -1e30f, l0 = 0.f, l1 = 0.f;
    // scale/sqrt(128) * log2(e) folded into one constant; exp(x*s) = 2^(x*K2)
    const float K2 = 0.12753102198074527f;

    for (int jt = 0; jt < 32; jt++) {
        const int cur = jt & 1;
        if (jt < 31) {
            stage_vq(jt + 1, cur ^ 1);
            asm volatile("cp.async.commit_group;" ::: "memory");
        }

        // ---- S = K^T V (2-pass fp16 split) ----
        float accS[8][4];
        #pragma unroll
        for (int nf = 0; nf < 8; nf++)
            #pragma unroll
            for (int r = 0; r < 4; r++) accS[nf][r] = 0.f;

        const unsigned aH = sb + aOff;
        const unsigned aL = aH + SK_L;
        const unsigned vB = sb + SV + cur * SV_BUF + bRow * 272 + bHlf;
        #pragma unroll
        for (int kk = 0; kk < 8; kk++) {
            unsigned ah[4], al[4];
            ldsm4(ah, aH + kk * 32);
            ldsm4(al, aL + kk * 32);
            unsigned bhf[4][4];
            #pragma unroll
            for (int g2 = 0; g2 < 4; g2++)
                ldsm4(bhf[g2], vB + g2 * (16 * 272) + kk * 32);
            #pragma unroll
            for (int nf = 0; nf < 8; nf++) {
                unsigned bb[2] = {bhf[nf >> 1][2 * (nf & 1)], bhf[nf >> 1][2 * (nf & 1) + 1]};
                mma_fp16(accS[nf], ah, bb);
            }
            #pragma unroll
            for (int nf = 0; nf < 8; nf++) {
                unsigned bb[2] = {bhf[nf >> 1][2 * (nf & 1)], bhf[nf >> 1][2 * (nf & 1) + 1]};
                mma_fp16(accS[nf], al, bb);
            }
        }

        // ---- online softmax in log2 domain (rows gid, gid+8) ----
        float rm0 = -1e30f, rm1 = -1e30f;
        #pragma unroll
        for (int nf = 0; nf < 8; nf++) {
            accS[nf][0] *= K2; accS[nf][1] *= K2;
            accS[nf][2] *= K2; accS[nf][3] *= K2;
            rm0 = fmaxf(rm0, fmaxf(accS[nf][0], accS[nf][1]));
            rm1 = fmaxf(rm1, fmaxf(accS[nf][2], accS[nf][3]));
        }
        rm0 = fmaxf(rm0, __shfl_xor_sync(0xffffffffu, rm0, 1));
        rm0 = fmaxf(rm0, __shfl_xor_sync(0xffffffffu, rm0, 2));
        rm1 = fmaxf(rm1, __shfl_xor_sync(0xffffffffu, rm1, 1));
        rm1 = fmaxf(rm1, __shfl_xor_sync(0xffffffffu, rm1, 2));
        const float m0n = fmaxf(m0, rm0), m1n = fmaxf(m1, rm1);
        const float cf0 = ex2(m0 - m0n), cf1 = ex2(m1 - m1n);
        float rs0 = 0.f, rs1 = 0.f;
        #pragma unroll
        for (int nf = 0; nf < 8; nf++) {
            accS[nf][0] = ex2(accS[nf][0] - m0n);
            accS[nf][1] = ex2(accS[nf][1] - m0n);
            accS[nf][2] = ex2(accS[nf][2] - m1n);
            accS[nf][3] = ex2(accS[nf][3] - m1n);
            rs0 += accS[nf][0] + accS[nf][1];
            rs1 += accS[nf][2] + accS[nf][3];
        }
        rs0 += __shfl_xor_sync(0xffffffffu, rs0, 1);
        rs0 += __shfl_xor_sync(0xffffffffu, rs0, 2);
        rs1 += __shfl_xor_sync(0xffffffffu, rs1, 1);
        rs1 += __shfl_xor_sync(0xffffffffu, rs1, 2);
        l0 = l0 * cf0 + rs0; l1 = l1 * cf1 + rs1;
        m0 = m0n; m1 = m1n;
        #pragma unroll
        for (int nf = 0; nf < 16; nf++) {
            accO[nf][0] *= cf0; accO[nf][1] *= cf0;
            accO[nf][2] *= cf1; accO[nf][3] *= cf1;
        }

        // ---- P -> fp16 A-frags ----
        unsigned pa[4][4];
        #pragma unroll
        for (int kj = 0; kj < 4; kj++) {
            pa[kj][0] = packh2(accS[2 * kj][0], accS[2 * kj][1]);
            pa[kj][1] = packh2(accS[2 * kj][2], accS[2 * kj][3]);
            pa[kj][2] = packh2(accS[2 * kj + 1][0], accS[2 * kj + 1][1]);
            pa[kj][3] = packh2(accS[2 * kj + 1][2], accS[2 * kj + 1][3]);
        }

        // ---- O += P * Q ----
        const unsigned qB = sb + SQ + cur * SQ_BUF + bRow * 144 + bHlf;
        #pragma unroll
        for (int kj = 0; kj < 4; kj++) {
            unsigned qf[8][4];
            #pragma unroll
            for (int g2 = 0; g2 < 8; g2++)
                ldsm4(qf[g2], qB + g2 * (16 * 144) + kj * 32);
            #pragma unroll
            for (int nf = 0; nf < 16; nf++) {
                unsigned bb[2] = {qf[nf >> 1][2 * (nf & 1)], qf[nf >> 1][2 * (nf & 1) + 1]};
                mma_fp16(accO[nf], pa[kj], bb);
            }
        }

        asm volatile("cp.async.wait_group 0;" ::: "memory");
        __syncthreads();
    }

    // ---- epilogue: O /= l, write out[c, i] ----
    const float inv0 = 1.0f / l0, inv1 = 1.0f / l1;
    float* Ob = out + ((size_t)b * COUT + h * 128) * PDIM;
    const int ir0 = i0 + wrp * 16 + gid;
    #pragma unroll
    for (int nf = 0; nf < 16; nf++) {
        const int c = nf * 8 + 2 * tig;
        Ob[(size_t)c * PDIM + ir0]           = accO[nf][0] * inv0;
        Ob[(size_t)(c + 1) * PDIM + ir0]     = accO[nf][1] * inv0;
        Ob[(size_t)c * PDIM + ir0 + 8]       = accO[nf][2] * inv1;
        Ob[(size_t)(c + 1) * PDIM + ir0 + 8] = accO[nf][3] * inv1;
    }
}

// ---------------------------------------------------------------------------
extern "C" void kernel_launch(void* const* d_in, const int* in_sizes, int n_in,
                              void* d_out, int out_size)
{
    const float* x   = (const float*)d_in[0];
    const float* wq  = (const float*)d_in[1];
    const float* bq  = (const float*)d_in[2];
    const float* gw1 = (const float*)d_in[3];
    const float* gb1 = (const float*)d_in[4];
    const float* wk  = (const float*)d_in[5];
    const float* bk  = (const float*)d_in[6];
    const float* gw2 = (const float*)d_in[7];
    const float* gb2 = (const float*)d_in[8];
    const float* wv  = (const float*)d_in[9];
    const float* bv  = (const float*)d_in[10];
    const float* gw3 = (const float*)d_in[11];
    const float* gb3 = (const float*)d_in[12];
    float* out = (float*)d_out;

    static int smem_set = 0;
    if (!smem_set) {
        cudaFuncSetAttribute(flash_kernel,
                             cudaFuncAttributeMaxDynamicSharedMemorySize,
                             SMEM_BYTES);
        smem_set = 1;
    }

    dim3 g1(NG, B_, 3);
    qkv_gn_kernel<<<g1, 256>>>(x, wq, bq, gw1, gb1, wk, bk, gw2, gb2,
                               wv, bv, gw3, gb3);

    dim3 gf(PDIM / 128, B_ * Hh);
    flash_kernel<<<gf, 256, SMEM_BYTES>>>(out);
}

// round 11
// speedup vs baseline: 6.5134x; 1.1814x over previous
#include <cuda_runtime.h>
#include <cuda_fp16.h>
#include <stdint.h>

#define B_    8
#define CIN   512
#define COUT  1024
#define PDIM  2048
#define Hh    8
#define NG    32

// ------------------------- device scratch (static) -------------------------
__device__ float g_raw[(size_t)3 * B_ * COUT * PDIM];     // per-branch pre-norm y
// fp16 tile buffers (ldmatrix-friendly row layouts)
__device__ uint4 g_Kt[(size_t)B_ * Hh * 16 * 2048];   // [bh][it] rows i(128), 16 c2-quads
__device__ uint4 g_Vt[(size_t)B_ * Hh * 32 * 1024];   // [bh][jt] rows j(64), 16 c2-quads
__device__ uint4 g_Qt[(size_t)B_ * Hh * 32 * 1024];   // [bh][jt] rows c(128), 8 j2-quads

// ------------------------------- helpers -----------------------------------
__device__ __forceinline__ unsigned packh2(float a, float b) {
    __half2 h = __floats2half2_rn(a, b);
    return *reinterpret_cast<unsigned*>(&h);
}
__device__ __forceinline__ float ex2(float x) {
    float r;
    asm("ex2.approx.f32 %0, %1;" : "=f"(r) : "f"(x));
    return r;
}
__device__ __forceinline__ void cp16(unsigned s, const void* g) {
    asm volatile("cp.async.cg.shared.global [%0], [%1], 16;" :: "r"(s), "l"(g));
}
__device__ __forceinline__ void ldsm4(unsigned (&d)[4], unsigned addr) {
    asm volatile("ldmatrix.sync.aligned.m8n8.x4.shared.b16 {%0,%1,%2,%3}, [%4];"
                 : "=r"(d[0]), "=r"(d[1]), "=r"(d[2]), "=r"(d[3]) : "r"(addr));
}
__device__ __forceinline__ void mma_fp16(float (&c)[4], const unsigned (&a)[4],
                                          const unsigned (&b)[2]) {
    asm volatile(
        "mma.sync.aligned.m16n8k16.row.col.f32.f16.f16.f32 "
        "{%0,%1,%2,%3}, {%4,%5,%6,%7}, {%8,%9}, {%0,%1,%2,%3};\n"
        : "+f"(c[0]), "+f"(c[1]), "+f"(c[2]), "+f"(c[3])
        : "r"(a[0]), "r"(a[1]), "r"(a[2]), "r"(a[3]), "r"(b[0]), "r"(b[1]));
}

// ---------------------------------------------------------------------------
// Kernel 1: grouped 1x1 conv + bias -> GroupNorm -> LeakyReLU -> fp16 tiles
// One launch, blockIdx.z = which (0=Q, 1=K, 2=V).
// ---------------------------------------------------------------------------
__global__ __launch_bounds__(256) void qkv_gn_kernel(
    const float* __restrict__ x,
    const float* __restrict__ wq, const float* __restrict__ bq_,
    const float* __restrict__ gw1, const float* __restrict__ gb1,
    const float* __restrict__ wk, const float* __restrict__ bk_,
    const float* __restrict__ gw2, const float* __restrict__ gb2,
    const float* __restrict__ wv, const float* __restrict__ bv_,
    const float* __restrict__ gw3, const float* __restrict__ gb3)
{
    const int which = blockIdx.z;
    const float* w    = which == 0 ? wq  : which == 1 ? wk  : wv;
    const float* bias = which == 0 ? bq_ : which == 1 ? bk_ : bv_;
    const float* gw   = which == 0 ? gw1 : which == 1 ? gw2 : gw3;
    const float* gb   = which == 0 ? gb1 : which == 1 ? gb2 : gb3;

    const int ng = blockIdx.x;
    const int b  = blockIdx.y;
    const int c0 = ng * 32;
    const int g  = c0 >> 7;
    const int f0 = g * 64;

    __shared__ float xs[64][129];
    __shared__ float ws[32][64];
    __shared__ float bs[32], gws[32], gbs[32];
    __shared__ float red[256];
    __shared__ float stats[2];

    const int t = threadIdx.x;

    for (int i = t; i < 32 * 64; i += 256) {
        int c = i >> 6, f = i & 63;
        ws[c][f] = w[(size_t)(c0 + c) * 64 + f];
    }
    if (t < 32) { bs[t] = bias[c0 + t]; gws[t] = gw[c0 + t]; gbs[t] = gb[c0 + t]; }

    const int pl = t & 31;
    const int cq = t >> 5;

    const float* xb = x + (size_t)b * CIN * PDIM + (size_t)f0 * PDIM;
    float* rawb = g_raw + ((size_t)which * B_ * COUT + (size_t)b * COUT + c0) * PDIM;

    float sum = 0.f, sumsq = 0.f;

    for (int pt = 0; pt < 16; pt++) {
        __syncthreads();
        for (int i = t; i < 64 * 128; i += 256) {
            int r = i >> 7, cc = i & 127;
            xs[r][cc] = xb[(size_t)r * PDIM + pt * 128 + cc];
        }
        __syncthreads();

        float acc[4][4];
        #pragma unroll
        for (int v = 0; v < 4; v++)
            #pragma unroll
            for (int u = 0; u < 4; u++) acc[v][u] = bs[cq * 4 + v];

        #pragma unroll
        for (int f = 0; f < 64; f++) {
            float xv[4];
            #pragma unroll
            for (int u = 0; u < 4; u++) xv[u] = xs[f][pl + 32 * u];
            #pragma unroll
            for (int v = 0; v < 4; v++) {
                float wv = ws[cq * 4 + v][f];
                #pragma unroll
                for (int u = 0; u < 4; u++) acc[v][u] += wv * xv[u];
            }
        }

        #pragma unroll
        for (int v = 0; v < 4; v++) {
            int c = cq * 4 + v;
            #pragma unroll
            for (int u = 0; u < 4; u++) {
                float a = acc[v][u];
                sum += a; sumsq += a * a;
                rawb[(size_t)c * PDIM + pt * 128 + pl + 32 * u] = a;
            }
        }
    }

    red[t] = sum; __syncthreads();
    for (int s = 128; s > 0; s >>= 1) { if (t < s) red[t] += red[t + s]; __syncthreads(); }
    if (t == 0) stats[0] = red[0] * (1.0f / 65536.0f);
    __syncthreads();
    red[t] = sumsq; __syncthreads();
    for (int s = 128; s > 0; s >>= 1) { if (t < s) red[t] += red[t + s]; __syncthreads(); }
    if (t == 0) {
        float mu = stats[0];
        float var = red[0] * (1.0f / 65536.0f) - mu * mu;
        stats[1] = rsqrtf(var + 1e-5f);
    }
    __syncthreads();
    const float mu = stats[0], inv = stats[1];

    const int h = ng >> 2;              // head
    const int bh = b * Hh + h;
    const int c0loc = c0 & 127;         // channel base within head
    const int ngl = ng & 3;             // c2-quad base = ngl*4

    for (int pt = 0; pt < 16; pt++) {
        __syncthreads();
        for (int i = t; i < 32 * 128; i += 256) {
            int c = i >> 7, pp = i & 127;
            float y = rawb[(size_t)c * PDIM + pt * 128 + pp];
            float z = (y - mu) * inv * gws[c] + gbs[c];
            xs[c][pp] = (z >= 0.f) ? z : 0.1f * z;
        }
        __syncthreads();

        if (which == 0) {
            // Q tiles: [bh][jt][c=128 rows][8 j2-quads], fp16
            for (int idx = t; idx < 512; idx += 256) {
                int cl = idx >> 4, u = idx & 15;
                int jt = 2 * pt + (u >> 3), qd = u & 7;
                int jbase = (u >> 3) * 64 + qd * 8;
                uint4 hv;
                hv.x = packh2(xs[cl][jbase + 0], xs[cl][jbase + 1]);
                hv.y = packh2(xs[cl][jbase + 2], xs[cl][jbase + 3]);
                hv.z = packh2(xs[cl][jbase + 4], xs[cl][jbase + 5]);
                hv.w = packh2(xs[cl][jbase + 6], xs[cl][jbase + 7]);
                g_Qt[(size_t)(bh * 32 + jt) * 1024 + (c0loc + cl) * 8 + qd] = hv;
            }
        } else if (which == 1) {
            // K tiles: rows = i(128), cols = c2; fp16 single
            for (int idx = t; idx < 512; idx += 256) {
                int il = idx >> 2, qd = idx & 3;
                unsigned hw[4];
                #pragma unroll
                for (int k2 = 0; k2 < 4; k2++)
                    hw[k2] = packh2(xs[qd * 8 + 2 * k2][il],
                                    xs[qd * 8 + 2 * k2 + 1][il]);
                int q16 = ngl * 4 + qd;
                size_t tb = (size_t)(bh * 16 + pt) * 2048;
                g_Kt[tb + il * 16 + q16] = make_uint4(hw[0], hw[1], hw[2], hw[3]);
            }
        } else {
            // V tiles: rows = j(64), cols = c2; fp16 single
            for (int idx = t; idx < 512; idx += 256) {
                int il = idx >> 2, qd = idx & 3;
                unsigned hw[4];
                #pragma unroll
                for (int k2 = 0; k2 < 4; k2++)
                    hw[k2] = packh2(xs[qd * 8 + 2 * k2][il],
                                    xs[qd * 8 + 2 * k2 + 1][il]);
                int q16 = ngl * 4 + qd;
                int jt = 2 * pt + (il >> 6), j = il & 63;
                size_t tb = (size_t)(bh * 32 + jt) * 1024;
                g_Vt[tb + j * 16 + q16] = make_uint4(hw[0], hw[1], hw[2], hw[3]);
            }
        }
    }
}

// ---------------------------------------------------------------------------
// Kernel 2: fused flash attention, single-pass fp16 mma.sync, no-max softmax.
// CTA = (i-tile 128, bh), 256 threads / 8 warps; warp w owns i-rows w*16..+15.
// K resident in smem [i=128][c2 stride 272B] fp16.
// Per j-tile(64): S = K^T V (64 MMAs) -> e = exp2(K2*S) (no max: GroupNorm
// bounds logits; softmax shift-invariant) -> P fp16 -> O += P*Q (64 MMAs).
// l accumulated per-lane, reduced once in epilogue. V/Q double-buffered.
// ---------------------------------------------------------------------------
#define SK_BYTES 34816
#define SV     34816
#define SV_BUF 17408
#define SQ     69632
#define SQ_BUF 18432
#define SMEM_BYTES 106496

__global__ void __launch_bounds__(256, 1) flash_kernel(float* __restrict__ out)
{
    extern __shared__ unsigned char sm[];
    const unsigned sb = (unsigned)__cvta_generic_to_shared(sm);
    const int t = threadIdx.x, lane = t & 31, wrp = t >> 5;
    const int gid = lane >> 2, tig = lane & 3;
    const int it = blockIdx.x, bh = blockIdx.y;
    const int b = bh >> 3, h = bh & 7;
    const int i0 = it * 128;

    // ---- resident K staging (32KB) ----
    {
        const uint4* src = g_Kt + (size_t)(bh * 16 + it) * 2048;
        #pragma unroll
        for (int qq = 0; qq < 8; qq++) {
            int ch = t + 256 * qq;
            int i = ch >> 4, qd = ch & 15;
            cp16(sb + i * 272 + qd * 16, src + ch);
        }
    }
    auto stage_vq = [&](int jt, int buf) {
        const uint4* vs = g_Vt + (size_t)(bh * 32 + jt) * 1024;
        #pragma unroll
        for (int qq = 0; qq < 4; qq++) {
            int ch = t + 256 * qq;
            int j = ch >> 4, qd = ch & 15;
            cp16(sb + SV + buf * SV_BUF + j * 272 + qd * 16, vs + ch);
        }
        const uint4* qs = g_Qt + (size_t)(bh * 32 + jt) * 1024;
        #pragma unroll
        for (int qq = 0; qq < 4; qq++) {
            int ch = t + 256 * qq;
            int cr = ch >> 3, qd = ch & 7;
            cp16(sb + SQ + buf * SQ_BUF + cr * 144 + qd * 16, qs + ch);
        }
    };
    stage_vq(0, 0);
    asm volatile("cp.async.commit_group;" ::: "memory");
    asm volatile("cp.async.wait_group 0;" ::: "memory");
    __syncthreads();

    // ---- per-lane ldmatrix base offsets ----
    const int lq = lane >> 3, lr = lane & 7;
    const unsigned aOff = (wrp * 16 + ((lq & 1) << 3) + lr) * 272 + (lq >> 1) * 16;
    const unsigned bRow = ((lq >> 1) << 3) + lr;
    const unsigned bHlf = (lq & 1) * 16;

    float accO[16][4];
    #pragma unroll
    for (int nf = 0; nf < 16; nf++)
        #pragma unroll
        for (int r = 0; r < 4; r++) accO[nf][r] = 0.f;
    float l0 = 0.f, l1 = 0.f;
    // scale/sqrt(128) * log2(e): exp(x*s) = 2^(x*K2)
    const float K2 = 0.12753102198074527f;

    for (int jt = 0; jt < 32; jt++) {
        const int cur = jt & 1;
        if (jt < 31) {
            stage_vq(jt + 1, cur ^ 1);
            asm volatile("cp.async.commit_group;" ::: "memory");
        }

        // ---- S = K^T V (single-pass fp16) ----
        float accS[8][4];
        #pragma unroll
        for (int nf = 0; nf < 8; nf++)
            #pragma unroll
            for (int r = 0; r < 4; r++) accS[nf][r] = 0.f;

        const unsigned aH = sb + aOff;
        const unsigned vB = sb + SV + cur * SV_BUF + bRow * 272 + bHlf;
        #pragma unroll
        for (int kk = 0; kk < 8; kk++) {
            unsigned ah[4];
            ldsm4(ah, aH + kk * 32);
            unsigned bhf[4][4];
            #pragma unroll
            for (int g2 = 0; g2 < 4; g2++)
                ldsm4(bhf[g2], vB + g2 * (16 * 272) + kk * 32);
            #pragma unroll
            for (int nf = 0; nf < 8; nf++) {
                unsigned bb[2] = {bhf[nf >> 1][2 * (nf & 1)], bhf[nf >> 1][2 * (nf & 1) + 1]};
                mma_fp16(accS[nf], ah, bb);
            }
        }

        // ---- e = 2^(K2*S); per-lane partial row sums (no max needed) ----
        float rs0 = 0.f, rs1 = 0.f;
        #pragma unroll
        for (int nf = 0; nf < 8; nf++) {
            accS[nf][0] = ex2(accS[nf][0] * K2);
            accS[nf][1] = ex2(accS[nf][1] * K2);
            accS[nf][2] = ex2(accS[nf][2] * K2);
            accS[nf][3] = ex2(accS[nf][3] * K2);
            rs0 += accS[nf][0] + accS[nf][1];
            rs1 += accS[nf][2] + accS[nf][3];
        }
        l0 += rs0; l1 += rs1;

        // ---- P -> fp16 A-frags ----
        unsigned pa[4][4];
        #pragma unroll
        for (int kj = 0; kj < 4; kj++) {
            pa[kj][0] = packh2(accS[2 * kj][0], accS[2 * kj][1]);
            pa[kj][1] = packh2(accS[2 * kj][2], accS[2 * kj][3]);
            pa[kj][2] = packh2(accS[2 * kj + 1][0], accS[2 * kj + 1][1]);
            pa[kj][3] = packh2(accS[2 * kj + 1][2], accS[2 * kj + 1][3]);
        }

        // ---- O += P * Q ----
        const unsigned qB = sb + SQ + cur * SQ_BUF + bRow * 144 + bHlf;
        #pragma unroll
        for (int kj = 0; kj < 4; kj++) {
            unsigned qf[8][4];
            #pragma unroll
            for (int g2 = 0; g2 < 8; g2++)
                ldsm4(qf[g2], qB + g2 * (16 * 144) + kj * 32);
            #pragma unroll
            for (int nf = 0; nf < 16; nf++) {
                unsigned bb[2] = {qf[nf >> 1][2 * (nf & 1)], qf[nf >> 1][2 * (nf & 1) + 1]};
                mma_fp16(accO[nf], pa[kj], bb);
            }
        }

        asm volatile("cp.async.wait_group 0;" ::: "memory");
        __syncthreads();
    }

    // ---- epilogue: reduce l across the 4 lanes of each row, O /= l ----
    l0 += __shfl_xor_sync(0xffffffffu, l0, 1);
    l0 += __shfl_xor_sync(0xffffffffu, l0, 2);
    l1 += __shfl_xor_sync(0xffffffffu, l1, 1);
    l1 += __shfl_xor_sync(0xffffffffu, l1, 2);
    const float inv0 = 1.0f / l0, inv1 = 1.0f / l1;
    float* Ob = out + ((size_t)b * COUT + h * 128) * PDIM;
    const int ir0 = i0 + wrp * 16 + gid;
    #pragma unroll
    for (int nf = 0; nf < 16; nf++) {
        const int c = nf * 8 + 2 * tig;
        Ob[(size_t)c * PDIM + ir0]           = accO[nf][0] * inv0;
        Ob[(size_t)(c + 1) * PDIM + ir0]     = accO[nf][1] * inv0;
        Ob[(size_t)c * PDIM + ir0 + 8]       = accO[nf][2] * inv1;
        Ob[(size_t)(c + 1) * PDIM + ir0 + 8] = accO[nf][3] * inv1;
    }
}

// ---------------------------------------------------------------------------
extern "C" void kernel_launch(void* const* d_in, const int* in_sizes, int n_in,
                              void* d_out, int out_size)
{
    const float* x   = (const float*)d_in[0];
    const float* wq  = (const float*)d_in[1];
    const float* bq  = (const float*)d_in[2];
    const float* gw1 = (const float*)d_in[3];
    const float* gb1 = (const float*)d_in[4];
    const float* wk  = (const float*)d_in[5];
    const float* bk  = (const float*)d_in[6];
    const float* gw2 = (const float*)d_in[7];
    const float* gb2 = (const float*)d_in[8];
    const float* wv  = (const float*)d_in[9];
    const float* bv  = (const float*)d_in[10];
    const float* gw3 = (const float*)d_in[11];
    const float* gb3 = (const float*)d_in[12];
    float* out = (float*)d_out;

    static int smem_set = 0;
    if (!smem_set) {
        cudaFuncSetAttribute(flash_kernel,
                             cudaFuncAttributeMaxDynamicSharedMemorySize,
                             SMEM_BYTES);
        smem_set = 1;
    }

    dim3 g1(NG, B_, 3);
    qkv_gn_kernel<<<g1, 256>>>(x, wq, bq, gw1, gb1, wk, bk, gw2, gb2,
                               wv, bv, gw3, gb3);

    dim3 gf(PDIM / 128, B_ * Hh);
    flash_kernel<<<gf, 256, SMEM_BYTES>>>(out);
}

// round 12
// speedup vs baseline: 6.7209x; 1.0319x over previous
#include <cuda_runtime.h>
#include <cuda_fp16.h>
#include <stdint.h>

#define B_    8
#define CIN   512
#define COUT  1024
#define PDIM  2048
#define Hh    8
#define NG    32

// ------------------------- device scratch (static) -------------------------
__device__ float g_raw[(size_t)3 * B_ * COUT * PDIM];     // per-branch pre-norm y
// fp16 tile buffers (ldmatrix-friendly row layouts), 64-row p-tiles
__device__ uint4 g_Kt[(size_t)B_ * Hh * 32 * 1024];   // [bh][it64] rows i(64), 16 c2-quads
__device__ uint4 g_Vt[(size_t)B_ * Hh * 32 * 1024];   // [bh][jt]   rows j(64), 16 c2-quads
__device__ uint4 g_Qt[(size_t)B_ * Hh * 32 * 1024];   // [bh][jt]   rows c(128), 8 j2-quads

// ------------------------------- helpers -----------------------------------
__device__ __forceinline__ unsigned packh2(float a, float b) {
    __half2 h = __floats2half2_rn(a, b);
    return *reinterpret_cast<unsigned*>(&h);
}
__device__ __forceinline__ float ex2(float x) {
    float r;
    asm("ex2.approx.f32 %0, %1;" : "=f"(r) : "f"(x));
    return r;
}
__device__ __forceinline__ void cp16(unsigned s, const void* g) {
    asm volatile("cp.async.cg.shared.global [%0], [%1], 16;" :: "r"(s), "l"(g));
}
__device__ __forceinline__ void ldsm4(unsigned (&d)[4], unsigned addr) {
    asm volatile("ldmatrix.sync.aligned.m8n8.x4.shared.b16 {%0,%1,%2,%3}, [%4];"
                 : "=r"(d[0]), "=r"(d[1]), "=r"(d[2]), "=r"(d[3]) : "r"(addr));
}
__device__ __forceinline__ void mma_fp16(float (&c)[4], const unsigned (&a)[4],
                                          const unsigned (&b)[2]) {
    asm volatile(
        "mma.sync.aligned.m16n8k16.row.col.f32.f16.f16.f32 "
        "{%0,%1,%2,%3}, {%4,%5,%6,%7}, {%8,%9}, {%0,%1,%2,%3};\n"
        : "+f"(c[0]), "+f"(c[1]), "+f"(c[2]), "+f"(c[3])
        : "r"(a[0]), "r"(a[1]), "r"(a[2]), "r"(a[3]), "r"(b[0]), "r"(b[1]));
}

// ---------------------------------------------------------------------------
// Kernel 1: grouped 1x1 conv + bias -> GroupNorm -> LeakyReLU -> fp16 tiles
// One launch, blockIdx.z = which (0=Q, 1=K, 2=V).
// ---------------------------------------------------------------------------
__global__ __launch_bounds__(256) void qkv_gn_kernel(
    const float* __restrict__ x,
    const float* __restrict__ wq, const float* __restrict__ bq_,
    const float* __restrict__ gw1, const float* __restrict__ gb1,
    const float* __restrict__ wk, const float* __restrict__ bk_,
    const float* __restrict__ gw2, const float* __restrict__ gb2,
    const float* __restrict__ wv, const float* __restrict__ bv_,
    const float* __restrict__ gw3, const float* __restrict__ gb3)
{
    const int which = blockIdx.z;
    const float* w    = which == 0 ? wq  : which == 1 ? wk  : wv;
    const float* bias = which == 0 ? bq_ : which == 1 ? bk_ : bv_;
    const float* gw   = which == 0 ? gw1 : which == 1 ? gw2 : gw3;
    const float* gb   = which == 0 ? gb1 : which == 1 ? gb2 : gb3;

    const int ng = blockIdx.x;
    const int b  = blockIdx.y;
    const int c0 = ng * 32;
    const int g  = c0 >> 7;
    const int f0 = g * 64;

    __shared__ float xs[64][129];
    __shared__ float ws[32][64];
    __shared__ float bs[32], gws[32], gbs[32];
    __shared__ float red[256];
    __shared__ float stats[2];

    const int t = threadIdx.x;

    for (int i = t; i < 32 * 64; i += 256) {
        int c = i >> 6, f = i & 63;
        ws[c][f] = w[(size_t)(c0 + c) * 64 + f];
    }
    if (t < 32) { bs[t] = bias[c0 + t]; gws[t] = gw[c0 + t]; gbs[t] = gb[c0 + t]; }

    const int pl = t & 31;
    const int cq = t >> 5;

    const float* xb = x + (size_t)b * CIN * PDIM + (size_t)f0 * PDIM;
    float* rawb = g_raw + ((size_t)which * B_ * COUT + (size_t)b * COUT + c0) * PDIM;

    float sum = 0.f, sumsq = 0.f;

    for (int pt = 0; pt < 16; pt++) {
        __syncthreads();
        for (int i = t; i < 64 * 128; i += 256) {
            int r = i >> 7, cc = i & 127;
            xs[r][cc] = xb[(size_t)r * PDIM + pt * 128 + cc];
        }
        __syncthreads();

        float acc[4][4];
        #pragma unroll
        for (int v = 0; v < 4; v++)
            #pragma unroll
            for (int u = 0; u < 4; u++) acc[v][u] = bs[cq * 4 + v];

        #pragma unroll
        for (int f = 0; f < 64; f++) {
            float xv[4];
            #pragma unroll
            for (int u = 0; u < 4; u++) xv[u] = xs[f][pl + 32 * u];
            #pragma unroll
            for (int v = 0; v < 4; v++) {
                float wv = ws[cq * 4 + v][f];
                #pragma unroll
                for (int u = 0; u < 4; u++) acc[v][u] += wv * xv[u];
            }
        }

        #pragma unroll
        for (int v = 0; v < 4; v++) {
            int c = cq * 4 + v;
            #pragma unroll
            for (int u = 0; u < 4; u++) {
                float a = acc[v][u];
                sum += a; sumsq += a * a;
                rawb[(size_t)c * PDIM + pt * 128 + pl + 32 * u] = a;
            }
        }
    }

    red[t] = sum; __syncthreads();
    for (int s = 128; s > 0; s >>= 1) { if (t < s) red[t] += red[t + s]; __syncthreads(); }
    if (t == 0) stats[0] = red[0] * (1.0f / 65536.0f);
    __syncthreads();
    red[t] = sumsq; __syncthreads();
    for (int s = 128; s > 0; s >>= 1) { if (t < s) red[t] += red[t + s]; __syncthreads(); }
    if (t == 0) {
        float mu = stats[0];
        float var = red[0] * (1.0f / 65536.0f) - mu * mu;
        stats[1] = rsqrtf(var + 1e-5f);
    }
    __syncthreads();
    const float mu = stats[0], inv = stats[1];

    const int h = ng >> 2;              // head
    const int bh = b * Hh + h;
    const int c0loc = c0 & 127;         // channel base within head
    const int ngl = ng & 3;             // c2-quad base = ngl*4

    for (int pt = 0; pt < 16; pt++) {
        __syncthreads();
        for (int i = t; i < 32 * 128; i += 256) {
            int c = i >> 7, pp = i & 127;
            float y = rawb[(size_t)c * PDIM + pt * 128 + pp];
            float z = (y - mu) * inv * gws[c] + gbs[c];
            xs[c][pp] = (z >= 0.f) ? z : 0.1f * z;
        }
        __syncthreads();

        if (which == 0) {
            // Q tiles: [bh][jt][c=128 rows][8 j2-quads], fp16
            for (int idx = t; idx < 512; idx += 256) {
                int cl = idx >> 4, u = idx & 15;
                int jt = 2 * pt + (u >> 3), qd = u & 7;
                int jbase = (u >> 3) * 64 + qd * 8;
                uint4 hv;
                hv.x = packh2(xs[cl][jbase + 0], xs[cl][jbase + 1]);
                hv.y = packh2(xs[cl][jbase + 2], xs[cl][jbase + 3]);
                hv.z = packh2(xs[cl][jbase + 4], xs[cl][jbase + 5]);
                hv.w = packh2(xs[cl][jbase + 6], xs[cl][jbase + 7]);
                g_Qt[(size_t)(bh * 32 + jt) * 1024 + (c0loc + cl) * 8 + qd] = hv;
            }
        } else {
            // K/V tiles: 64-row p-tiles, rows = p, cols = c2; fp16 single
            uint4* dst = (which == 1) ? g_Kt : g_Vt;
            for (int idx = t; idx < 512; idx += 256) {
                int il = idx >> 2, qd = idx & 3;
                unsigned hw[4];
                #pragma unroll
                for (int k2 = 0; k2 < 4; k2++)
                    hw[k2] = packh2(xs[qd * 8 + 2 * k2][il],
                                    xs[qd * 8 + 2 * k2 + 1][il]);
                int q16 = ngl * 4 + qd;
                int ptile = 2 * pt + (il >> 6), r = il & 63;
                size_t tb = (size_t)(bh * 32 + ptile) * 1024;
                dst[tb + r * 16 + q16] = make_uint4(hw[0], hw[1], hw[2], hw[3]);
            }
        }
    }
}

// ---------------------------------------------------------------------------
// Kernel 2: fused flash attention, single-pass fp16 mma.sync, no-max softmax.
// CTA = (i-tile 64, bh), 128 threads / 4 warps, 2 CTAs/SM (bubble overlap).
// K resident in smem [i=64][c2 stride 272B] fp16.
// Per j-tile(64): S = K^T V (64 MMAs/warp) -> e = exp2(K2*S) -> P fp16 ->
// O += P*Q (64 MMAs/warp). l per-lane, reduced once in epilogue.
// V/Q double-buffered cp.async.
// ---------------------------------------------------------------------------
#define SV     17408
#define SV_BUF 17408
#define SQ     52224
#define SQ_BUF 18432
#define SMEM_BYTES 89088

__global__ void __launch_bounds__(128, 2) flash_kernel(float* __restrict__ out)
{
    extern __shared__ unsigned char sm[];
    const unsigned sb = (unsigned)__cvta_generic_to_shared(sm);
    const int t = threadIdx.x, lane = t & 31, wrp = t >> 5;
    const int gid = lane >> 2, tig = lane & 3;
    const int it = blockIdx.x, bh = blockIdx.y;
    const int b = bh >> 3, h = bh & 7;
    const int i0 = it * 64;

    // ---- resident K staging (64 rows, 17KB) ----
    {
        const uint4* src = g_Kt + (size_t)(bh * 32 + it) * 1024;
        #pragma unroll
        for (int qq = 0; qq < 8; qq++) {
            int ch = t + 128 * qq;
            int i = ch >> 4, qd = ch & 15;
            cp16(sb + i * 272 + qd * 16, src + ch);
        }
    }
    auto stage_vq = [&](int jt, int buf) {
        const uint4* vs = g_Vt + (size_t)(bh * 32 + jt) * 1024;
        #pragma unroll
        for (int qq = 0; qq < 8; qq++) {
            int ch = t + 128 * qq;
            int j = ch >> 4, qd = ch & 15;
            cp16(sb + SV + buf * SV_BUF + j * 272 + qd * 16, vs + ch);
        }
        const uint4* qs = g_Qt + (size_t)(bh * 32 + jt) * 1024;
        #pragma unroll
        for (int qq = 0; qq < 8; qq++) {
            int ch = t + 128 * qq;
            int cr = ch >> 3, qd = ch & 7;
            cp16(sb + SQ + buf * SQ_BUF + cr * 144 + qd * 16, qs + ch);
        }
    };
    stage_vq(0, 0);
    asm volatile("cp.async.commit_group;" ::: "memory");
    asm volatile("cp.async.wait_group 0;" ::: "memory");
    __syncthreads();

    // ---- per-lane ldmatrix base offsets ----
    const int lq = lane >> 3, lr = lane & 7;
    const unsigned aOff = (wrp * 16 + ((lq & 1) << 3) + lr) * 272 + (lq >> 1) * 16;
    const unsigned bRow = ((lq >> 1) << 3) + lr;
    const unsigned bHlf = (lq & 1) * 16;

    float accO[16][4];
    #pragma unroll
    for (int nf = 0; nf < 16; nf++)
        #pragma unroll
        for (int r = 0; r < 4; r++) accO[nf][r] = 0.f;
    float l0 = 0.f, l1 = 0.f;
    // scale/sqrt(128) * log2(e): exp(x*s) = 2^(x*K2)
    const float K2 = 0.12753102198074527f;

    for (int jt = 0; jt < 32; jt++) {
        const int cur = jt & 1;
        if (jt < 31) {
            stage_vq(jt + 1, cur ^ 1);
            asm volatile("cp.async.commit_group;" ::: "memory");
        }

        // ---- S = K^T V (single-pass fp16) ----
        float accS[8][4];
        #pragma unroll
        for (int nf = 0; nf < 8; nf++)
            #pragma unroll
            for (int r = 0; r < 4; r++) accS[nf][r] = 0.f;

        const unsigned aH = sb + aOff;
        const unsigned vB = sb + SV + cur * SV_BUF + bRow * 272 + bHlf;
        #pragma unroll
        for (int kk = 0; kk < 8; kk++) {
            unsigned ah[4];
            ldsm4(ah, aH + kk * 32);
            unsigned bhf[4][4];
            #pragma unroll
            for (int g2 = 0; g2 < 4; g2++)
                ldsm4(bhf[g2], vB + g2 * (16 * 272) + kk * 32);
            #pragma unroll
            for (int nf = 0; nf < 8; nf++) {
                unsigned bb[2] = {bhf[nf >> 1][2 * (nf & 1)], bhf[nf >> 1][2 * (nf & 1) + 1]};
                mma_fp16(accS[nf], ah, bb);
            }
        }

        // ---- e = 2^(K2*S); per-lane partial row sums (no max needed) ----
        float rs0 = 0.f, rs1 = 0.f;
        #pragma unroll
        for (int nf = 0; nf < 8; nf++) {
            accS[nf][0] = ex2(accS[nf][0] * K2);
            accS[nf][1] = ex2(accS[nf][1] * K2);
            accS[nf][2] = ex2(accS[nf][2] * K2);
            accS[nf][3] = ex2(accS[nf][3] * K2);
            rs0 += accS[nf][0] + accS[nf][1];
            rs1 += accS[nf][2] + accS[nf][3];
        }
        l0 += rs0; l1 += rs1;

        // ---- P -> fp16 A-frags ----
        unsigned pa[4][4];
        #pragma unroll
        for (int kj = 0; kj < 4; kj++) {
            pa[kj][0] = packh2(accS[2 * kj][0], accS[2 * kj][1]);
            pa[kj][1] = packh2(accS[2 * kj][2], accS[2 * kj][3]);
            pa[kj][2] = packh2(accS[2 * kj + 1][0], accS[2 * kj + 1][1]);
            pa[kj][3] = packh2(accS[2 * kj + 1][2], accS[2 * kj + 1][3]);
        }

        // ---- O += P * Q ----
        const unsigned qB = sb + SQ + cur * SQ_BUF + bRow * 144 + bHlf;
        #pragma unroll
        for (int kj = 0; kj < 4; kj++) {
            unsigned qf[8][4];
            #pragma unroll
            for (int g2 = 0; g2 < 8; g2++)
                ldsm4(qf[g2], qB + g2 * (16 * 144) + kj * 32);
            #pragma unroll
            for (int nf = 0; nf < 16; nf++) {
                unsigned bb[2] = {qf[nf >> 1][2 * (nf & 1)], qf[nf >> 1][2 * (nf & 1) + 1]};
                mma_fp16(accO[nf], pa[kj], bb);
            }
        }

        asm volatile("cp.async.wait_group 0;" ::: "memory");
        __syncthreads();
    }

    // ---- epilogue: reduce l across the 4 lanes of each row, O /= l ----
    l0 += __shfl_xor_sync(0xffffffffu, l0, 1);
    l0 += __shfl_xor_sync(0xffffffffu, l0, 2);
    l1 += __shfl_xor_sync(0xffffffffu, l1, 1);
    l1 += __shfl_xor_sync(0xffffffffu, l1, 2);
    const float inv0 = 1.0f / l0, inv1 = 1.0f / l1;
    float* Ob = out + ((size_t)b * COUT + h * 128) * PDIM;
    const int ir0 = i0 + wrp * 16 + gid;
    #pragma unroll
    for (int nf = 0; nf < 16; nf++) {
        const int c = nf * 8 + 2 * tig;
        Ob[(size_t)c * PDIM + ir0]           = accO[nf][0] * inv0;
        Ob[(size_t)(c + 1) * PDIM + ir0]     = accO[nf][1] * inv0;
        Ob[(size_t)c * PDIM + ir0 + 8]       = accO[nf][2] * inv1;
        Ob[(size_t)(c + 1) * PDIM + ir0 + 8] = accO[nf][3] * inv1;
    }
}

// ---------------------------------------------------------------------------
extern "C" void kernel_launch(void* const* d_in, const int* in_sizes, int n_in,
                              void* d_out, int out_size)
{
    const float* x   = (const float*)d_in[0];
    const float* wq  = (const float*)d_in[1];
    const float* bq  = (const float*)d_in[2];
    const float* gw1 = (const float*)d_in[3];
    const float* gb1 = (const float*)d_in[4];
    const float* wk  = (const float*)d_in[5];
    const float* bk  = (const float*)d_in[6];
    const float* gw2 = (const float*)d_in[7];
    const float* gb2 = (const float*)d_in[8];
    const float* wv  = (const float*)d_in[9];
    const float* bv  = (const float*)d_in[10];
    const float* gw3 = (const float*)d_in[11];
    const float* gb3 = (const float*)d_in[12];
    float* out = (float*)d_out;

    static int smem_set = 0;
    if (!smem_set) {
        cudaFuncSetAttribute(flash_kernel,
                             cudaFuncAttributeMaxDynamicSharedMemorySize,
                             SMEM_BYTES);
        smem_set = 1;
    }

    dim3 g1(NG, B_, 3);
    qkv_gn_kernel<<<g1, 256>>>(x, wq, bq, gw1, gb1, wk, bk, gw2, gb2,
                               wv, bv, gw3, gb3);

    dim3 gf(PDIM / 64, B_ * Hh);
    flash_kernel<<<gf, 128, SMEM_BYTES>>>(out);
}

// round 13
// speedup vs baseline: 10.0463x; 1.4948x over previous
#include <cuda_runtime.h>
#include <cuda_fp16.h>
#include <stdint.h>

#define B_    8
#define CIN   512
#define COUT  1024
#define PDIM  2048
#define Hh    8
#define NG    32

// ------------------------- device scratch (static) -------------------------
// fp16 tile buffers (ldmatrix-friendly row layouts), 64-row p-tiles
__device__ uint4 g_Kt[(size_t)B_ * Hh * 32 * 1024];   // [bh][it64] rows i(64), 16 c2-quads
__device__ uint4 g_Vt[(size_t)B_ * Hh * 32 * 1024];   // [bh][jt]   rows j(64), 16 c2-quads
__device__ uint4 g_Qt[(size_t)B_ * Hh * 32 * 1024];   // [bh][jt]   rows c(128), 8 j2-quads

// ------------------------------- helpers -----------------------------------
__device__ __forceinline__ unsigned packh2(float a, float b) {
    __half2 h = __floats2half2_rn(a, b);
    return *reinterpret_cast<unsigned*>(&h);
}
__device__ __forceinline__ float ex2(float x) {
    float r;
    asm("ex2.approx.f32 %0, %1;" : "=f"(r) : "f"(x));
    return r;
}
__device__ __forceinline__ void cp16(unsigned s, const void* g) {
    asm volatile("cp.async.cg.shared.global [%0], [%1], 16;" :: "r"(s), "l"(g));
}
__device__ __forceinline__ void ldsm4(unsigned (&d)[4], unsigned addr) {
    asm volatile("ldmatrix.sync.aligned.m8n8.x4.shared.b16 {%0,%1,%2,%3}, [%4];"
                 : "=r"(d[0]), "=r"(d[1]), "=r"(d[2]), "=r"(d[3]) : "r"(addr));
}
__device__ __forceinline__ void ldsm4t(unsigned (&d)[4], unsigned addr) {
    asm volatile("ldmatrix.sync.aligned.m8n8.x4.trans.shared.b16 {%0,%1,%2,%3}, [%4];"
                 : "=r"(d[0]), "=r"(d[1]), "=r"(d[2]), "=r"(d[3]) : "r"(addr));
}
__device__ __forceinline__ void mma_fp16(float (&c)[4], const unsigned (&a)[4],
                                          const unsigned (&b)[2]) {
    asm volatile(
        "mma.sync.aligned.m16n8k16.row.col.f32.f16.f16.f32 "
        "{%0,%1,%2,%3}, {%4,%5,%6,%7}, {%8,%9}, {%0,%1,%2,%3};\n"
        : "+f"(c[0]), "+f"(c[1]), "+f"(c[2]), "+f"(c[3])
        : "r"(a[0]), "r"(a[1]), "r"(a[2]), "r"(a[3]), "r"(b[0]), "r"(b[1]));
}

// ---------------------------------------------------------------------------
// Kernel 1: grouped 1x1 conv (fp16 tensor-core GEMM) + GroupNorm + LeakyReLU
// -> fp16 tiles. One block per (ng, b, which). y kept resident in smem fp16.
//   A = W[32c][64f] (regular ldmatrix), B = x-tile[64f][256p] (ldmatrix.trans)
// ---------------------------------------------------------------------------
#define YSS     2050                 // ys row stride in halves (1025 words)
#define XTS     264                  // xt row stride in halves
#define XT_OFF  131200
#define WS_OFF  164992
#define BS_OFF  169600
#define RED_OFF 169984
#define SMEM1_BYTES 171040

__global__ __launch_bounds__(256, 1) void qkv_gn_kernel(
    const float* __restrict__ x,
    const float* __restrict__ wq, const float* __restrict__ bq_,
    const float* __restrict__ gw1, const float* __restrict__ gb1,
    const float* __restrict__ wk, const float* __restrict__ bk_,
    const float* __restrict__ gw2, const float* __restrict__ gb2,
    const float* __restrict__ wv, const float* __restrict__ bv_,
    const float* __restrict__ gw3, const float* __restrict__ gb3)
{
    const int which = blockIdx.z;
    const float* w    = which == 0 ? wq  : which == 1 ? wk  : wv;
    const float* bias = which == 0 ? bq_ : which == 1 ? bk_ : bv_;
    const float* gw   = which == 0 ? gw1 : which == 1 ? gw2 : gw3;
    const float* gb   = which == 0 ? gb1 : which == 1 ? gb2 : gb3;

    const int ng = blockIdx.x;
    const int b  = blockIdx.y;
    const int c0 = ng * 32;
    const int g  = ng >> 2;
    const int f0 = g * 64;

    extern __shared__ unsigned char smq[];
    __half* ys  = (__half*)smq;                    // [32][YSS]
    __half* xt  = (__half*)(smq + XT_OFF);         // [64][XTS]
    __half* wsh = (__half*)(smq + WS_OFF);         // [32][72]
    float*  bsf = (float*)(smq + BS_OFF);          // 32 bias, 32 gw, 32 gb
    float*  gwf = bsf + 32;
    float*  gbf = bsf + 64;
    float*  red = (float*)(smq + RED_OFF);         // 256
    float*  stats = red + 256;                     // 2
    const unsigned sq = (unsigned)__cvta_generic_to_shared(smq);

    const int t = threadIdx.x, lane = t & 31, wrp = t >> 5;
    const int gid = lane >> 2, tig = lane & 3;
    const int lq = lane >> 3, lr = lane & 7;

    // weights fp32 -> fp16 smem
    for (int i = t; i < 2048; i += 256) {
        int c = i >> 6, f = i & 63;
        wsh[c * 72 + f] = __float2half_rn(w[(size_t)(c0 + c) * 64 + f]);
    }
    if (t < 32) { bsf[t] = bias[c0 + t]; gwf[t] = gw[c0 + t]; gbf[t] = gb[c0 + t]; }

    const float* xb = x + (size_t)b * CIN * PDIM + (size_t)f0 * PDIM;
    float sum = 0.f, sumsq = 0.f;

    const unsigned aB = sq + WS_OFF + (((lq & 1) << 3) + lr) * 144 + (lq >> 1) * 16;
    const unsigned bB = sq + XT_OFF + (((lq & 1) << 3) + lr) * 528 +
                        ((lq >> 1) << 3) * 2 + wrp * 64;   // warp p-base = wrp*32

    for (int pt = 0; pt < 8; pt++) {
        __syncthreads();
        // stage x tile [64f][256p] fp32->fp16
        #pragma unroll
        for (int q = 0; q < 32; q++) {
            int idx = t + 256 * q;
            int r = idx >> 7, p2 = idx & 127;
            float2 v = *(const float2*)(xb + (size_t)r * PDIM + pt * 256 + 2 * p2);
            *(__half2*)(xt + r * XTS + 2 * p2) = __floats2half2_rn(v.x, v.y);
        }
        __syncthreads();

        float acc[2][4][4];
        #pragma unroll
        for (int mt = 0; mt < 2; mt++)
            #pragma unroll
            for (int pg = 0; pg < 4; pg++)
                #pragma unroll
                for (int r = 0; r < 4; r++) acc[mt][pg][r] = 0.f;

        #pragma unroll
        for (int kk = 0; kk < 4; kk++) {
            unsigned a0[4], a1[4], b0[4], b1[4];
            ldsm4(a0, aB + kk * 32);
            ldsm4(a1, aB + 16 * 144 + kk * 32);
            ldsm4t(b0, bB + kk * 8448);           // p 0-15 of warp range
            ldsm4t(b1, bB + kk * 8448 + 32);      // p 16-31
            #pragma unroll
            for (int pg = 0; pg < 4; pg++) {
                const unsigned* bf = (pg < 2) ? b0 : b1;
                unsigned bb[2] = {bf[2 * (pg & 1)], bf[2 * (pg & 1) + 1]};
                mma_fp16(acc[0][pg], a0, bb);
                mma_fp16(acc[1][pg], a1, bb);
            }
        }

        // bias + stats + store y to smem
        #pragma unroll
        for (int mt = 0; mt < 2; mt++) {
            const float bc0 = bsf[mt * 16 + gid], bc1 = bsf[mt * 16 + gid + 8];
            #pragma unroll
            for (int pg = 0; pg < 4; pg++) {
                float v0 = acc[mt][pg][0] + bc0, v1 = acc[mt][pg][1] + bc0;
                float v2 = acc[mt][pg][2] + bc1, v3 = acc[mt][pg][3] + bc1;
                sum += v0 + v1 + v2 + v3;
                sumsq += v0 * v0 + v1 * v1 + v2 * v2 + v3 * v3;
                int p = pt * 256 + wrp * 32 + pg * 8 + 2 * tig;
                *(__half2*)&ys[(mt * 16 + gid) * YSS + p]     = __floats2half2_rn(v0, v1);
                *(__half2*)&ys[(mt * 16 + gid + 8) * YSS + p] = __floats2half2_rn(v2, v3);
            }
        }
    }

    // GroupNorm stats
    __syncthreads();
    red[t] = sum; __syncthreads();
    for (int s = 128; s > 0; s >>= 1) { if (t < s) red[t] += red[t + s]; __syncthreads(); }
    if (t == 0) stats[0] = red[0] * (1.0f / 65536.0f);
    __syncthreads();
    red[t] = sumsq; __syncthreads();
    for (int s = 128; s > 0; s >>= 1) { if (t < s) red[t] += red[t + s]; __syncthreads(); }
    if (t == 0) {
        float mu = stats[0];
        float var = red[0] * (1.0f / 65536.0f) - mu * mu;
        stats[1] = rsqrtf(var + 1e-5f);
    }
    __syncthreads();
    const float mu = stats[0], inv = stats[1];

    const int h = ng >> 2;
    const int bh = b * Hh + h;
    const int c0loc = c0 & 127;
    const int ngl = ng & 3;

    if (which == 0) {
        // Q tiles: [bh][jt][c=128 rows][8 j2-quads]
        uint4* qdst = g_Qt + (size_t)(bh * 32) * 1024;
        #pragma unroll
        for (int q = 0; q < 32; q++) {
            int idx = t + 256 * q;
            int qd = idx & 7, cl = (idx >> 3) & 31, jt = idx >> 8;
            int p0 = jt * 64 + qd * 8;
            const float gwc = gwf[cl] * inv;
            const float gbc = gbf[cl] - mu * gwc;
            unsigned hv[4];
            #pragma unroll
            for (int k = 0; k < 4; k++) {
                __half2 y2 = *(__half2*)&ys[cl * YSS + p0 + 2 * k];
                float z0 = __half2float(y2.x) * gwc + gbc;
                float z1 = __half2float(y2.y) * gwc + gbc;
                z0 = (z0 >= 0.f) ? z0 : 0.1f * z0;
                z1 = (z1 >= 0.f) ? z1 : 0.1f * z1;
                hv[k] = packh2(z0, z1);
            }
            qdst[(size_t)jt * 1024 + (c0loc + cl) * 8 + qd] =
                make_uint4(hv[0], hv[1], hv[2], hv[3]);
        }
    } else {
        // K/V tiles: 64-row p-tiles, uint4 = 8 channels (pairs along c) at one p
        uint4* dst = ((which == 1) ? g_Kt : g_Vt) + (size_t)(bh * 32) * 1024;
        #pragma unroll
        for (int q = 0; q < 16; q++) {
            int idx = t + 256 * q;
            int qd = idx & 3;
            int p = (idx >> 2) * 2;
            int ptile = p >> 6, r = p & 63;
            unsigned ha[4], hb[4];
            #pragma unroll
            for (int k2 = 0; k2 < 4; k2++) {
                int ca = qd * 8 + 2 * k2;
                const float gwa = gwf[ca] * inv,     gba = gbf[ca] - mu * gwa;
                const float gwb = gwf[ca + 1] * inv, gbb = gbf[ca + 1] - mu * gwb;
                __half2 ya = *(__half2*)&ys[ca * YSS + p];        // (p, p+1) ch ca
                __half2 yb = *(__half2*)&ys[(ca + 1) * YSS + p];  // (p, p+1) ch ca+1
                float za0 = __half2float(ya.x) * gwa + gba;
                float za1 = __half2float(yb.x) * gwb + gbb;
                float zb0 = __half2float(ya.y) * gwa + gba;
                float zb1 = __half2float(yb.y) * gwb + gbb;
                za0 = (za0 >= 0.f) ? za0 : 0.1f * za0;
                za1 = (za1 >= 0.f) ? za1 : 0.1f * za1;
                zb0 = (zb0 >= 0.f) ? zb0 : 0.1f * zb0;
                zb1 = (zb1 >= 0.f) ? zb1 : 0.1f * zb1;
                ha[k2] = packh2(za0, za1);
                hb[k2] = packh2(zb0, zb1);
            }
            size_t tb = (size_t)ptile * 1024;
            dst[tb + r * 16 + ngl * 4 + qd]       = make_uint4(ha[0], ha[1], ha[2], ha[3]);
            dst[tb + (r + 1) * 16 + ngl * 4 + qd] = make_uint4(hb[0], hb[1], hb[2], hb[3]);
        }
    }
}

// ---------------------------------------------------------------------------
// Kernel 2: fused flash attention, single-pass fp16 mma.sync, no-max softmax.
// (unchanged from round 12: 392.6 us measured)
// ---------------------------------------------------------------------------
#define SV     17408
#define SV_BUF 17408
#define SQ     52224
#define SQ_BUF 18432
#define SMEM_BYTES 89088

__global__ void __launch_bounds__(128, 2) flash_kernel(float* __restrict__ out)
{
    extern __shared__ unsigned char sm[];
    const unsigned sb = (unsigned)__cvta_generic_to_shared(sm);
    const int t = threadIdx.x, lane = t & 31, wrp = t >> 5;
    const int gid = lane >> 2, tig = lane & 3;
    const int it = blockIdx.x, bh = blockIdx.y;
    const int b = bh >> 3, h = bh & 7;
    const int i0 = it * 64;

    {
        const uint4* src = g_Kt + (size_t)(bh * 32 + it) * 1024;
        #pragma unroll
        for (int qq = 0; qq < 8; qq++) {
            int ch = t + 128 * qq;
            int i = ch >> 4, qd = ch & 15;
            cp16(sb + i * 272 + qd * 16, src + ch);
        }
    }
    auto stage_vq = [&](int jt, int buf) {
        const uint4* vs = g_Vt + (size_t)(bh * 32 + jt) * 1024;
        #pragma unroll
        for (int qq = 0; qq < 8; qq++) {
            int ch = t + 128 * qq;
            int j = ch >> 4, qd = ch & 15;
            cp16(sb + SV + buf * SV_BUF + j * 272 + qd * 16, vs + ch);
        }
        const uint4* qs = g_Qt + (size_t)(bh * 32 + jt) * 1024;
        #pragma unroll
        for (int qq = 0; qq < 8; qq++) {
            int ch = t + 128 * qq;
            int cr = ch >> 3, qd = ch & 7;
            cp16(sb + SQ + buf * SQ_BUF + cr * 144 + qd * 16, qs + ch);
        }
    };
    stage_vq(0, 0);
    asm volatile("cp.async.commit_group;" ::: "memory");
    asm volatile("cp.async.wait_group 0;" ::: "memory");
    __syncthreads();

    const int lq = lane >> 3, lr = lane & 7;
    const unsigned aOff = (wrp * 16 + ((lq & 1) << 3) + lr) * 272 + (lq >> 1) * 16;
    const unsigned bRow = ((lq >> 1) << 3) + lr;
    const unsigned bHlf = (lq & 1) * 16;

    float accO[16][4];
    #pragma unroll
    for (int nf = 0; nf < 16; nf++)
        #pragma unroll
        for (int r = 0; r < 4; r++) accO[nf][r] = 0.f;
    float l0 = 0.f, l1 = 0.f;
    const float K2 = 0.12753102198074527f;

    for (int jt = 0; jt < 32; jt++) {
        const int cur = jt & 1;
        if (jt < 31) {
            stage_vq(jt + 1, cur ^ 1);
            asm volatile("cp.async.commit_group;" ::: "memory");
        }

        float accS[8][4];
        #pragma unroll
        for (int nf = 0; nf < 8; nf++)
            #pragma unroll
            for (int r = 0; r < 4; r++) accS[nf][r] = 0.f;

        const unsigned aH = sb + aOff;
        const unsigned vB = sb + SV + cur * SV_BUF + bRow * 272 + bHlf;
        #pragma unroll
        for (int kk = 0; kk < 8; kk++) {
            unsigned ah[4];
            ldsm4(ah, aH + kk * 32);
            unsigned bhf[4][4];
            #pragma unroll
            for (int g2 = 0; g2 < 4; g2++)
                ldsm4(bhf[g2], vB + g2 * (16 * 272) + kk * 32);
            #pragma unroll
            for (int nf = 0; nf < 8; nf++) {
                unsigned bb[2] = {bhf[nf >> 1][2 * (nf & 1)], bhf[nf >> 1][2 * (nf & 1) + 1]};
                mma_fp16(accS[nf], ah, bb);
            }
        }

        float rs0 = 0.f, rs1 = 0.f;
        #pragma unroll
        for (int nf = 0; nf < 8; nf++) {
            accS[nf][0] = ex2(accS[nf][0] * K2);
            accS[nf][1] = ex2(accS[nf][1] * K2);
            accS[nf][2] = ex2(accS[nf][2] * K2);
            accS[nf][3] = ex2(accS[nf][3] * K2);
            rs0 += accS[nf][0] + accS[nf][1];
            rs1 += accS[nf][2] + accS[nf][3];
        }
        l0 += rs0; l1 += rs1;

        unsigned pa[4][4];
        #pragma unroll
        for (int kj = 0; kj < 4; kj++) {
            pa[kj][0] = packh2(accS[2 * kj][0], accS[2 * kj][1]);
            pa[kj][1] = packh2(accS[2 * kj][2], accS[2 * kj][3]);
            pa[kj][2] = packh2(accS[2 * kj + 1][0], accS[2 * kj + 1][1]);
            pa[kj][3] = packh2(accS[2 * kj + 1][2], accS[2 * kj + 1][3]);
        }

        const unsigned qB = sb + SQ + cur * SQ_BUF + bRow * 144 + bHlf;
        #pragma unroll
        for (int kj = 0; kj < 4; kj++) {
            unsigned qf[8][4];
            #pragma unroll
            for (int g2 = 0; g2 < 8; g2++)
                ldsm4(qf[g2], qB + g2 * (16 * 144) + kj * 32);
            #pragma unroll
            for (int nf = 0; nf < 16; nf++) {
                unsigned bb[2] = {qf[nf >> 1][2 * (nf & 1)], qf[nf >> 1][2 * (nf & 1) + 1]};
                mma_fp16(accO[nf], pa[kj], bb);
            }
        }

        asm volatile("cp.async.wait_group 0;" ::: "memory");
        __syncthreads();
    }

    l0 += __shfl_xor_sync(0xffffffffu, l0, 1);
    l0 += __shfl_xor_sync(0xffffffffu, l0, 2);
    l1 += __shfl_xor_sync(0xffffffffu, l1, 1);
    l1 += __shfl_xor_sync(0xffffffffu, l1, 2);
    const float inv0 = 1.0f / l0, inv1 = 1.0f / l1;
    float* Ob = out + ((size_t)b * COUT + h * 128) * PDIM;
    const int ir0 = i0 + wrp * 16 + gid;
    #pragma unroll
    for (int nf = 0; nf < 16; nf++) {
        const int c = nf * 8 + 2 * tig;
        Ob[(size_t)c * PDIM + ir0]           = accO[nf][0] * inv0;
        Ob[(size_t)(c + 1) * PDIM + ir0]     = accO[nf][1] * inv0;
        Ob[(size_t)c * PDIM + ir0 + 8]       = accO[nf][2] * inv1;
        Ob[(size_t)(c + 1) * PDIM + ir0 + 8] = accO[nf][3] * inv1;
    }
}

// ---------------------------------------------------------------------------
extern "C" void kernel_launch(void* const* d_in, const int* in_sizes, int n_in,
                              void* d_out, int out_size)
{
    const float* x   = (const float*)d_in[0];
    const float* wq  = (const float*)d_in[1];
    const float* bq  = (const float*)d_in[2];
    const float* gw1 = (const float*)d_in[3];
    const float* gb1 = (const float*)d_in[4];
    const float* wk  = (const float*)d_in[5];
    const float* bk  = (const float*)d_in[6];
    const float* gw2 = (const float*)d_in[7];
    const float* gb2 = (const float*)d_in[8];
    const float* wv  = (const float*)d_in[9];
    const float* bv  = (const float*)d_in[10];
    const float* gw3 = (const float*)d_in[11];
    const float* gb3 = (const float*)d_in[12];
    float* out = (float*)d_out;

    static int smem_set = 0;
    if (!smem_set) {
        cudaFuncSetAttribute(flash_kernel,
                             cudaFuncAttributeMaxDynamicSharedMemorySize,
                             SMEM_BYTES);
        cudaFuncSetAttribute(qkv_gn_kernel,
                             cudaFuncAttributeMaxDynamicSharedMemorySize,
                             SMEM1_BYTES);
        smem_set = 1;
    }

    dim3 g1(NG, B_, 3);
    qkv_gn_kernel<<<g1, 256, SMEM1_BYTES>>>(x, wq, bq, gw1, gb1, wk, bk, gw2, gb2,
                                            wv, bv, gw3, gb3);

    dim3 gf(PDIM / 64, B_ * Hh);
    flash_kernel<<<gf, 128, SMEM_BYTES>>>(out);
}

// round 14
// speedup vs baseline: 10.2815x; 1.0234x over previous
#include <cuda_runtime.h>
#include <cuda_fp16.h>
#include <stdint.h>

#define B_    8
#define CIN   512
#define COUT  1024
#define PDIM  2048
#define Hh    8
#define NG    32

// ------------------------- device scratch (static) -------------------------
// fp16 tile buffers (ldmatrix-friendly row layouts), 64-row p-tiles
__device__ uint4 g_Kt[(size_t)B_ * Hh * 32 * 1024];   // [bh][it64] rows i(64), 16 c2-quads (pre-scaled)
__device__ uint4 g_Vt[(size_t)B_ * Hh * 32 * 1024];   // [bh][jt]   rows j(64), 16 c2-quads
__device__ uint4 g_Qt[(size_t)B_ * Hh * 32 * 1024];   // [bh][jt]   rows c(128), 8 j2-quads

// ------------------------------- helpers -----------------------------------
__device__ __forceinline__ unsigned packh2(float a, float b) {
    __half2 h = __floats2half2_rn(a, b);
    return *reinterpret_cast<unsigned*>(&h);
}
__device__ __forceinline__ float ex2(float x) {
    float r;
    asm("ex2.approx.f32 %0, %1;" : "=f"(r) : "f"(x));
    return r;
}
__device__ __forceinline__ void cp16(unsigned s, const void* g) {
    asm volatile("cp.async.cg.shared.global [%0], [%1], 16;" :: "r"(s), "l"(g));
}
__device__ __forceinline__ void ldsm4(unsigned (&d)[4], unsigned addr) {
    asm volatile("ldmatrix.sync.aligned.m8n8.x4.shared.b16 {%0,%1,%2,%3}, [%4];"
                 : "=r"(d[0]), "=r"(d[1]), "=r"(d[2]), "=r"(d[3]) : "r"(addr));
}
__device__ __forceinline__ void ldsm4t(unsigned (&d)[4], unsigned addr) {
    asm volatile("ldmatrix.sync.aligned.m8n8.x4.trans.shared.b16 {%0,%1,%2,%3}, [%4];"
                 : "=r"(d[0]), "=r"(d[1]), "=r"(d[2]), "=r"(d[3]) : "r"(addr));
}
__device__ __forceinline__ void mma_fp16(float (&c)[4], const unsigned (&a)[4],
                                          const unsigned (&b)[2]) {
    asm volatile(
        "mma.sync.aligned.m16n8k16.row.col.f32.f16.f16.f32 "
        "{%0,%1,%2,%3}, {%4,%5,%6,%7}, {%8,%9}, {%0,%1,%2,%3};\n"
        : "+f"(c[0]), "+f"(c[1]), "+f"(c[2]), "+f"(c[3])
        : "r"(a[0]), "r"(a[1]), "r"(a[2]), "r"(a[3]), "r"(b[0]), "r"(b[1]));
}

// ---------------------------------------------------------------------------
// Kernel 1: grouped 1x1 conv (fp16 tensor-core GEMM) + GroupNorm + LeakyReLU
// -> fp16 tiles. K branch pre-scaled by scale*log2(e) (folded into affine;
// LeakyReLU commutes with positive scaling).
// ---------------------------------------------------------------------------
#define YSS     2050                 // ys row stride in halves (1025 words)
#define XTS     264                  // xt row stride in halves
#define XT_OFF  131200
#define WS_OFF  164992
#define BS_OFF  169600
#define RED_OFF 169984
#define SMEM1_BYTES 171040

__global__ __launch_bounds__(256, 1) void qkv_gn_kernel(
    const float* __restrict__ x,
    const float* __restrict__ wq, const float* __restrict__ bq_,
    const float* __restrict__ gw1, const float* __restrict__ gb1,
    const float* __restrict__ wk, const float* __restrict__ bk_,
    const float* __restrict__ gw2, const float* __restrict__ gb2,
    const float* __restrict__ wv, const float* __restrict__ bv_,
    const float* __restrict__ gw3, const float* __restrict__ gb3)
{
    const int which = blockIdx.z;
    const float* w    = which == 0 ? wq  : which == 1 ? wk  : wv;
    const float* bias = which == 0 ? bq_ : which == 1 ? bk_ : bv_;
    const float* gw   = which == 0 ? gw1 : which == 1 ? gw2 : gw3;
    const float* gb   = which == 0 ? gb1 : which == 1 ? gb2 : gb3;

    const int ng = blockIdx.x;
    const int b  = blockIdx.y;
    const int c0 = ng * 32;
    const int g  = ng >> 2;
    const int f0 = g * 64;

    extern __shared__ unsigned char smq[];
    __half* ys  = (__half*)smq;                    // [32][YSS]
    __half* xt  = (__half*)(smq + XT_OFF);         // [64][XTS]
    __half* wsh = (__half*)(smq + WS_OFF);         // [32][72]
    float*  bsf = (float*)(smq + BS_OFF);          // 32 bias, 32 gw, 32 gb
    float*  gwf = bsf + 32;
    float*  gbf = bsf + 64;
    float*  red = (float*)(smq + RED_OFF);         // 256
    float*  stats = red + 256;                     // 2
    const unsigned sq = (unsigned)__cvta_generic_to_shared(smq);

    const int t = threadIdx.x, lane = t & 31, wrp = t >> 5;
    const int gid = lane >> 2, tig = lane & 3;
    const int lq = lane >> 3, lr = lane & 7;

    // weights fp32 -> fp16 smem
    for (int i = t; i < 2048; i += 256) {
        int c = i >> 6, f = i & 63;
        wsh[c * 72 + f] = __float2half_rn(w[(size_t)(c0 + c) * 64 + f]);
    }
    if (t < 32) { bsf[t] = bias[c0 + t]; gwf[t] = gw[c0 + t]; gbf[t] = gb[c0 + t]; }

    const float* xb = x + (size_t)b * CIN * PDIM + (size_t)f0 * PDIM;
    float sum = 0.f, sumsq = 0.f;

    const unsigned aB = sq + WS_OFF + (((lq & 1) << 3) + lr) * 144 + (lq >> 1) * 16;
    const unsigned bB = sq + XT_OFF + (((lq & 1) << 3) + lr) * 528 +
                        ((lq >> 1) << 3) * 2 + wrp * 64;   // warp p-base = wrp*32

    for (int pt = 0; pt < 8; pt++) {
        __syncthreads();
        // stage x tile [64f][256p] fp32->fp16
        #pragma unroll
        for (int q = 0; q < 32; q++) {
            int idx = t + 256 * q;
            int r = idx >> 7, p2 = idx & 127;
            float2 v = *(const float2*)(xb + (size_t)r * PDIM + pt * 256 + 2 * p2);
            *(__half2*)(xt + r * XTS + 2 * p2) = __floats2half2_rn(v.x, v.y);
        }
        __syncthreads();

        float acc[2][4][4];
        #pragma unroll
        for (int mt = 0; mt < 2; mt++)
            #pragma unroll
            for (int pg = 0; pg < 4; pg++)
                #pragma unroll
                for (int r = 0; r < 4; r++) acc[mt][pg][r] = 0.f;

        #pragma unroll
        for (int kk = 0; kk < 4; kk++) {
            unsigned a0[4], a1[4], b0[4], b1[4];
            ldsm4(a0, aB + kk * 32);
            ldsm4(a1, aB + 16 * 144 + kk * 32);
            ldsm4t(b0, bB + kk * 8448);           // p 0-15 of warp range
            ldsm4t(b1, bB + kk * 8448 + 32);      // p 16-31
            #pragma unroll
            for (int pg = 0; pg < 4; pg++) {
                const unsigned* bf = (pg < 2) ? b0 : b1;
                unsigned bb[2] = {bf[2 * (pg & 1)], bf[2 * (pg & 1) + 1]};
                mma_fp16(acc[0][pg], a0, bb);
                mma_fp16(acc[1][pg], a1, bb);
            }
        }

        // bias + stats + store y to smem
        #pragma unroll
        for (int mt = 0; mt < 2; mt++) {
            const float bc0 = bsf[mt * 16 + gid], bc1 = bsf[mt * 16 + gid + 8];
            #pragma unroll
            for (int pg = 0; pg < 4; pg++) {
                float v0 = acc[mt][pg][0] + bc0, v1 = acc[mt][pg][1] + bc0;
                float v2 = acc[mt][pg][2] + bc1, v3 = acc[mt][pg][3] + bc1;
                sum += v0 + v1 + v2 + v3;
                sumsq += v0 * v0 + v1 * v1 + v2 * v2 + v3 * v3;
                int p = pt * 256 + wrp * 32 + pg * 8 + 2 * tig;
                *(__half2*)&ys[(mt * 16 + gid) * YSS + p]     = __floats2half2_rn(v0, v1);
                *(__half2*)&ys[(mt * 16 + gid + 8) * YSS + p] = __floats2half2_rn(v2, v3);
            }
        }
    }

    // GroupNorm stats
    __syncthreads();
    red[t] = sum; __syncthreads();
    for (int s = 128; s > 0; s >>= 1) { if (t < s) red[t] += red[t + s]; __syncthreads(); }
    if (t == 0) stats[0] = red[0] * (1.0f / 65536.0f);
    __syncthreads();
    red[t] = sumsq; __syncthreads();
    for (int s = 128; s > 0; s >>= 1) { if (t < s) red[t] += red[t + s]; __syncthreads(); }
    if (t == 0) {
        float mu = stats[0];
        float var = red[0] * (1.0f / 65536.0f) - mu * mu;
        stats[1] = rsqrtf(var + 1e-5f);
    }
    __syncthreads();
    const float mu = stats[0], inv = stats[1];

    const int h = ng >> 2;
    const int bh = b * Hh + h;
    const int c0loc = c0 & 127;
    const int ngl = ng & 3;

    if (which == 0) {
        // Q tiles: [bh][jt][c=128 rows][8 j2-quads]
        uint4* qdst = g_Qt + (size_t)(bh * 32) * 1024;
        #pragma unroll
        for (int q = 0; q < 32; q++) {
            int idx = t + 256 * q;
            int qd = idx & 7, cl = (idx >> 3) & 31, jt = idx >> 8;
            int p0 = jt * 64 + qd * 8;
            const float gwc = gwf[cl] * inv;
            const float gbc = gbf[cl] - mu * gwc;
            unsigned hv[4];
            #pragma unroll
            for (int k = 0; k < 4; k++) {
                __half2 y2 = *(__half2*)&ys[cl * YSS + p0 + 2 * k];
                float z0 = __half2float(y2.x) * gwc + gbc;
                float z1 = __half2float(y2.y) * gwc + gbc;
                z0 = (z0 >= 0.f) ? z0 : 0.1f * z0;
                z1 = (z1 >= 0.f) ? z1 : 0.1f * z1;
                hv[k] = packh2(z0, z1);
            }
            qdst[(size_t)jt * 1024 + (c0loc + cl) * 8 + qd] =
                make_uint4(hv[0], hv[1], hv[2], hv[3]);
        }
    } else {
        // K/V tiles: 64-row p-tiles. K pre-scaled by scale*log2(e) (commutes
        // with LeakyReLU since positive; folded into affine coefficients).
        const float ksc = (which == 1) ? 0.12753102198074527f : 1.0f;
        uint4* dst = ((which == 1) ? g_Kt : g_Vt) + (size_t)(bh * 32) * 1024;
        #pragma unroll
        for (int q = 0; q < 16; q++) {
            int idx = t + 256 * q;
            int qd = idx & 3;
            int p = (idx >> 2) * 2;
            int ptile = p >> 6, r = p & 63;
            unsigned ha[4], hb[4];
            #pragma unroll
            for (int k2 = 0; k2 < 4; k2++) {
                int ca = qd * 8 + 2 * k2;
                const float gwa = gwf[ca] * inv * ksc;
                const float gba = gbf[ca] * ksc - mu * gwa;
                const float gwb = gwf[ca + 1] * inv * ksc;
                const float gbb = gbf[ca + 1] * ksc - mu * gwb;
                __half2 ya = *(__half2*)&ys[ca * YSS + p];
                __half2 yb = *(__half2*)&ys[(ca + 1) * YSS + p];
                float za0 = __half2float(ya.x) * gwa + gba;
                float za1 = __half2float(yb.x) * gwb + gbb;
                float zb0 = __half2float(ya.y) * gwa + gba;
                float zb1 = __half2float(yb.y) * gwb + gbb;
                za0 = (za0 >= 0.f) ? za0 : 0.1f * za0;
                za1 = (za1 >= 0.f) ? za1 : 0.1f * za1;
                zb0 = (zb0 >= 0.f) ? zb0 : 0.1f * zb0;
                zb1 = (zb1 >= 0.f) ? zb1 : 0.1f * zb1;
                ha[k2] = packh2(za0, za1);
                hb[k2] = packh2(zb0, zb1);
            }
            size_t tb = (size_t)ptile * 1024;
            dst[tb + r * 16 + ngl * 4 + qd]       = make_uint4(ha[0], ha[1], ha[2], ha[3]);
            dst[tb + (r + 1) * 16 + ngl * 4 + qd] = make_uint4(hb[0], hb[1], hb[2], hb[3]);
        }
    }
}

// ---------------------------------------------------------------------------
// Kernel 2: fused flash attention, single-pass fp16 mma.sync, no-max softmax.
// K pre-scaled in producer (accS already in log2 domain). K A-frags hoisted
// to registers. Row-sum l computed by MMA against constant ones B-frag
// (every output column = row sum -> no shuffles, no FADD chain).
// ---------------------------------------------------------------------------
#define SV     17408
#define SV_BUF 17408
#define SQ     52224
#define SQ_BUF 18432
#define SMEM_BYTES 89088

__global__ void __launch_bounds__(128, 2) flash_kernel(float* __restrict__ out)
{
    extern __shared__ unsigned char sm[];
    const unsigned sb = (unsigned)__cvta_generic_to_shared(sm);
    const int t = threadIdx.x, lane = t & 31, wrp = t >> 5;
    const int gid = lane >> 2, tig = lane & 3;
    const int it = blockIdx.x, bh = blockIdx.y;
    const int b = bh >> 3, h = bh & 7;
    const int i0 = it * 64;

    {
        const uint4* src = g_Kt + (size_t)(bh * 32 + it) * 1024;
        #pragma unroll
        for (int qq = 0; qq < 8; qq++) {
            int ch = t + 128 * qq;
            int i = ch >> 4, qd = ch & 15;
            cp16(sb + i * 272 + qd * 16, src + ch);
        }
    }
    auto stage_vq = [&](int jt, int buf) {
        const uint4* vs = g_Vt + (size_t)(bh * 32 + jt) * 1024;
        #pragma unroll
        for (int qq = 0; qq < 8; qq++) {
            int ch = t + 128 * qq;
            int j = ch >> 4, qd = ch & 15;
            cp16(sb + SV + buf * SV_BUF + j * 272 + qd * 16, vs + ch);
        }
        const uint4* qs = g_Qt + (size_t)(bh * 32 + jt) * 1024;
        #pragma unroll
        for (int qq = 0; qq < 8; qq++) {
            int ch = t + 128 * qq;
            int cr = ch >> 3, qd = ch & 7;
            cp16(sb + SQ + buf * SQ_BUF + cr * 144 + qd * 16, qs + ch);
        }
    };
    stage_vq(0, 0);
    asm volatile("cp.async.commit_group;" ::: "memory");
    asm volatile("cp.async.wait_group 0;" ::: "memory");
    __syncthreads();

    const int lq = lane >> 3, lr = lane & 7;
    const unsigned aOff = (wrp * 16 + ((lq & 1) << 3) + lr) * 272 + (lq >> 1) * 16;
    const unsigned bRow = ((lq >> 1) << 3) + lr;
    const unsigned bHlf = (lq & 1) * 16;

    // hoist K A-frags for all 8 k-steps (K resident, never changes)
    unsigned ahf[8][4];
    #pragma unroll
    for (int kk = 0; kk < 8; kk++) ldsm4(ahf[kk], sb + aOff + kk * 32);

    float accO[16][4];
    #pragma unroll
    for (int nf = 0; nf < 16; nf++)
        #pragma unroll
        for (int r = 0; r < 4; r++) accO[nf][r] = 0.f;
    float accL[4] = {0.f, 0.f, 0.f, 0.f};
    const unsigned ONESB = 0x3C003C00u;   // (1.0h, 1.0h)

    for (int jt = 0; jt < 32; jt++) {
        const int cur = jt & 1;
        if (jt < 31) {
            stage_vq(jt + 1, cur ^ 1);
            asm volatile("cp.async.commit_group;" ::: "memory");
        }

        float accS[8][4];
        #pragma unroll
        for (int nf = 0; nf < 8; nf++)
            #pragma unroll
            for (int r = 0; r < 4; r++) accS[nf][r] = 0.f;

        const unsigned vB = sb + SV + cur * SV_BUF + bRow * 272 + bHlf;
        #pragma unroll
        for (int kk = 0; kk < 8; kk++) {
            unsigned bhf[4][4];
            #pragma unroll
            for (int g2 = 0; g2 < 4; g2++)
                ldsm4(bhf[g2], vB + g2 * (16 * 272) + kk * 32);
            #pragma unroll
            for (int nf = 0; nf < 8; nf++) {
                unsigned bb[2] = {bhf[nf >> 1][2 * (nf & 1)], bhf[nf >> 1][2 * (nf & 1) + 1]};
                mma_fp16(accS[nf], ahf[kk], bb);
            }
        }

        // e = 2^S (K pre-scaled; softmax shift-invariance makes no-max exact)
        #pragma unroll
        for (int nf = 0; nf < 8; nf++) {
            accS[nf][0] = ex2(accS[nf][0]);
            accS[nf][1] = ex2(accS[nf][1]);
            accS[nf][2] = ex2(accS[nf][2]);
            accS[nf][3] = ex2(accS[nf][3]);
        }

        // P -> fp16 A-frags
        unsigned pa[4][4];
        #pragma unroll
        for (int kj = 0; kj < 4; kj++) {
            pa[kj][0] = packh2(accS[2 * kj][0], accS[2 * kj][1]);
            pa[kj][1] = packh2(accS[2 * kj][2], accS[2 * kj][3]);
            pa[kj][2] = packh2(accS[2 * kj + 1][0], accS[2 * kj + 1][1]);
            pa[kj][3] = packh2(accS[2 * kj + 1][2], accS[2 * kj + 1][3]);
        }

        // row sums via MMA against constant ones (no LDSM, no FADD chain)
        {
            unsigned bb[2] = {ONESB, ONESB};
            #pragma unroll
            for (int kj = 0; kj < 4; kj++)
                mma_fp16(accL, pa[kj], bb);
        }

        // O += P * Q
        const unsigned qB = sb + SQ + cur * SQ_BUF + bRow * 144 + bHlf;
        #pragma unroll
        for (int kj = 0; kj < 4; kj++) {
            unsigned qf[8][4];
            #pragma unroll
            for (int g2 = 0; g2 < 8; g2++)
                ldsm4(qf[g2], qB + g2 * (16 * 144) + kj * 32);
            #pragma unroll
            for (int nf = 0; nf < 16; nf++) {
                unsigned bb[2] = {qf[nf >> 1][2 * (nf & 1)], qf[nf >> 1][2 * (nf & 1) + 1]};
                mma_fp16(accO[nf], pa[kj], bb);
            }
        }

        asm volatile("cp.async.wait_group 0;" ::: "memory");
        __syncthreads();
    }

    // epilogue: accL[0] = row sum for row gid, accL[2] for row gid+8
    const float inv0 = 1.0f / accL[0], inv1 = 1.0f / accL[2];
    float* Ob = out + ((size_t)b * COUT + h * 128) * PDIM;
    const int ir0 = i0 + wrp * 16 + gid;
    #pragma unroll
    for (int nf = 0; nf < 16; nf++) {
        const int c = nf * 8 + 2 * tig;
        Ob[(size_t)c * PDIM + ir0]           = accO[nf][0] * inv0;
        Ob[(size_t)(c + 1) * PDIM + ir0]     = accO[nf][1] * inv0;
        Ob[(size_t)c * PDIM + ir0 + 8]       = accO[nf][2] * inv1;
        Ob[(size_t)(c + 1) * PDIM + ir0 + 8] = accO[nf][3] * inv1;
    }
}

// ---------------------------------------------------------------------------
extern "C" void kernel_launch(void* const* d_in, const int* in_sizes, int n_in,
                              void* d_out, int out_size)
{
    const float* x   = (const float*)d_in[0];
    const float* wq  = (const float*)d_in[1];
    const float* bq  = (const float*)d_in[2];
    const float* gw1 = (const float*)d_in[3];
    const float* gb1 = (const float*)d_in[4];
    const float* wk  = (const float*)d_in[5];
    const float* bk  = (const float*)d_in[6];
    const float* gw2 = (const float*)d_in[7];
    const float* gb2 = (const float*)d_in[8];
    const float* wv  = (const float*)d_in[9];
    const float* bv  = (const float*)d_in[10];
    const float* gw3 = (const float*)d_in[11];
    const float* gb3 = (const float*)d_in[12];
    float* out = (float*)d_out;

    static int smem_set = 0;
    if (!smem_set) {
        cudaFuncSetAttribute(flash_kernel,
                             cudaFuncAttributeMaxDynamicSharedMemorySize,
                             SMEM_BYTES);
        cudaFuncSetAttribute(qkv_gn_kernel,
                             cudaFuncAttributeMaxDynamicSharedMemorySize,
                             SMEM1_BYTES);
        smem_set = 1;
    }

    dim3 g1(NG, B_, 3);
    qkv_gn_kernel<<<g1, 256, SMEM1_BYTES>>>(x, wq, bq, gw1, gb1, wk, bk, gw2, gb2,
                                            wv, bv, gw3, gb3);

    dim3 gf(PDIM / 64, B_ * Hh);
    flash_kernel<<<gf, 128, SMEM_BYTES>>>(out);
}

// round 15
// speedup vs baseline: 10.4210x; 1.0136x over previous
#include <cuda_runtime.h>
#include <cuda_fp16.h>
#include <stdint.h>

#define B_    8
#define CIN   512
#define COUT  1024
#define PDIM  2048
#define Hh    8
#define NG    32

// ------------------------- device scratch (static) -------------------------
// fp16 tile buffers (ldmatrix-friendly row layouts), 64-row p-tiles
__device__ uint4 g_Kt[(size_t)B_ * Hh * 32 * 1024];   // [bh][it64] rows i(64), 16 c2-quads (pre-scaled)
__device__ uint4 g_Vt[(size_t)B_ * Hh * 32 * 1024];   // [bh][jt]   rows j(64), 16 c2-quads
__device__ uint4 g_Qt[(size_t)B_ * Hh * 32 * 1024];   // [bh][jt]   rows c(128), 8 j2-quads

// ------------------------------- helpers -----------------------------------
__device__ __forceinline__ unsigned packh2(float a, float b) {
    __half2 h = __floats2half2_rn(a, b);
    return *reinterpret_cast<unsigned*>(&h);
}
__device__ __forceinline__ unsigned h2ex2(unsigned x) {
    unsigned r;
    asm("ex2.approx.f16x2 %0, %1;" : "=r"(r) : "r"(x));
    return r;
}
__device__ __forceinline__ void cp16(unsigned s, const void* g) {
    asm volatile("cp.async.cg.shared.global [%0], [%1], 16;" :: "r"(s), "l"(g));
}
__device__ __forceinline__ void ldsm4(unsigned (&d)[4], unsigned addr) {
    asm volatile("ldmatrix.sync.aligned.m8n8.x4.shared.b16 {%0,%1,%2,%3}, [%4];"
                 : "=r"(d[0]), "=r"(d[1]), "=r"(d[2]), "=r"(d[3]) : "r"(addr));
}
__device__ __forceinline__ void ldsm4t(unsigned (&d)[4], unsigned addr) {
    asm volatile("ldmatrix.sync.aligned.m8n8.x4.trans.shared.b16 {%0,%1,%2,%3}, [%4];"
                 : "=r"(d[0]), "=r"(d[1]), "=r"(d[2]), "=r"(d[3]) : "r"(addr));
}
__device__ __forceinline__ void mma_fp16(float (&c)[4], const unsigned (&a)[4],
                                          const unsigned (&b)[2]) {
    asm volatile(
        "mma.sync.aligned.m16n8k16.row.col.f32.f16.f16.f32 "
        "{%0,%1,%2,%3}, {%4,%5,%6,%7}, {%8,%9}, {%0,%1,%2,%3};\n"
        : "+f"(c[0]), "+f"(c[1]), "+f"(c[2]), "+f"(c[3])
        : "r"(a[0]), "r"(a[1]), "r"(a[2]), "r"(a[3]), "r"(b[0]), "r"(b[1]));
}

// ---------------------------------------------------------------------------
// Kernel 1: grouped 1x1 conv (fp16 tensor-core GEMM) + GroupNorm + LeakyReLU
// -> fp16 tiles. K branch pre-scaled by scale*log2(e).
// ---------------------------------------------------------------------------
#define YSS     2050
#define XTS     264
#define XT_OFF  131200
#define WS_OFF  164992
#define BS_OFF  169600
#define RED_OFF 169984
#define SMEM1_BYTES 171040

__global__ __launch_bounds__(256, 1) void qkv_gn_kernel(
    const float* __restrict__ x,
    const float* __restrict__ wq, const float* __restrict__ bq_,
    const float* __restrict__ gw1, const float* __restrict__ gb1,
    const float* __restrict__ wk, const float* __restrict__ bk_,
    const float* __restrict__ gw2, const float* __restrict__ gb2,
    const float* __restrict__ wv, const float* __restrict__ bv_,
    const float* __restrict__ gw3, const float* __restrict__ gb3)
{
    const int which = blockIdx.z;
    const float* w    = which == 0 ? wq  : which == 1 ? wk  : wv;
    const float* bias = which == 0 ? bq_ : which == 1 ? bk_ : bv_;
    const float* gw   = which == 0 ? gw1 : which == 1 ? gw2 : gw3;
    const float* gb   = which == 0 ? gb1 : which == 1 ? gb2 : gb3;

    const int ng = blockIdx.x;
    const int b  = blockIdx.y;
    const int c0 = ng * 32;
    const int g  = ng >> 2;
    const int f0 = g * 64;

    extern __shared__ unsigned char smq[];
    __half* ys  = (__half*)smq;
    __half* xt  = (__half*)(smq + XT_OFF);
    __half* wsh = (__half*)(smq + WS_OFF);
    float*  bsf = (float*)(smq + BS_OFF);
    float*  gwf = bsf + 32;
    float*  gbf = bsf + 64;
    float*  red = (float*)(smq + RED_OFF);
    float*  stats = red + 256;
    const unsigned sq = (unsigned)__cvta_generic_to_shared(smq);

    const int t = threadIdx.x, lane = t & 31, wrp = t >> 5;
    const int gid = lane >> 2, tig = lane & 3;
    const int lq = lane >> 3, lr = lane & 7;

    for (int i = t; i < 2048; i += 256) {
        int c = i >> 6, f = i & 63;
        wsh[c * 72 + f] = __float2half_rn(w[(size_t)(c0 + c) * 64 + f]);
    }
    if (t < 32) { bsf[t] = bias[c0 + t]; gwf[t] = gw[c0 + t]; gbf[t] = gb[c0 + t]; }

    const float* xb = x + (size_t)b * CIN * PDIM + (size_t)f0 * PDIM;
    float sum = 0.f, sumsq = 0.f;

    const unsigned aB = sq + WS_OFF + (((lq & 1) << 3) + lr) * 144 + (lq >> 1) * 16;
    const unsigned bB = sq + XT_OFF + (((lq & 1) << 3) + lr) * 528 +
                        ((lq >> 1) << 3) * 2 + wrp * 64;

    for (int pt = 0; pt < 8; pt++) {
        __syncthreads();
        #pragma unroll
        for (int q = 0; q < 32; q++) {
            int idx = t + 256 * q;
            int r = idx >> 7, p2 = idx & 127;
            float2 v = *(const float2*)(xb + (size_t)r * PDIM + pt * 256 + 2 * p2);
            *(__half2*)(xt + r * XTS + 2 * p2) = __floats2half2_rn(v.x, v.y);
        }
        __syncthreads();

        float acc[2][4][4];
        #pragma unroll
        for (int mt = 0; mt < 2; mt++)
            #pragma unroll
            for (int pg = 0; pg < 4; pg++)
                #pragma unroll
                for (int r = 0; r < 4; r++) acc[mt][pg][r] = 0.f;

        #pragma unroll
        for (int kk = 0; kk < 4; kk++) {
            unsigned a0[4], a1[4], b0[4], b1[4];
            ldsm4(a0, aB + kk * 32);
            ldsm4(a1, aB + 16 * 144 + kk * 32);
            ldsm4t(b0, bB + kk * 8448);
            ldsm4t(b1, bB + kk * 8448 + 32);
            #pragma unroll
            for (int pg = 0; pg < 4; pg++) {
                const unsigned* bf = (pg < 2) ? b0 : b1;
                unsigned bb[2] = {bf[2 * (pg & 1)], bf[2 * (pg & 1) + 1]};
                mma_fp16(acc[0][pg], a0, bb);
                mma_fp16(acc[1][pg], a1, bb);
            }
        }

        #pragma unroll
        for (int mt = 0; mt < 2; mt++) {
            const float bc0 = bsf[mt * 16 + gid], bc1 = bsf[mt * 16 + gid + 8];
            #pragma unroll
            for (int pg = 0; pg < 4; pg++) {
                float v0 = acc[mt][pg][0] + bc0, v1 = acc[mt][pg][1] + bc0;
                float v2 = acc[mt][pg][2] + bc1, v3 = acc[mt][pg][3] + bc1;
                sum += v0 + v1 + v2 + v3;
                sumsq += v0 * v0 + v1 * v1 + v2 * v2 + v3 * v3;
                int p = pt * 256 + wrp * 32 + pg * 8 + 2 * tig;
                *(__half2*)&ys[(mt * 16 + gid) * YSS + p]     = __floats2half2_rn(v0, v1);
                *(__half2*)&ys[(mt * 16 + gid + 8) * YSS + p] = __floats2half2_rn(v2, v3);
            }
        }
    }

    __syncthreads();
    red[t] = sum; __syncthreads();
    for (int s = 128; s > 0; s >>= 1) { if (t < s) red[t] += red[t + s]; __syncthreads(); }
    if (t == 0) stats[0] = red[0] * (1.0f / 65536.0f);
    __syncthreads();
    red[t] = sumsq; __syncthreads();
    for (int s = 128; s > 0; s >>= 1) { if (t < s) red[t] += red[t + s]; __syncthreads(); }
    if (t == 0) {
        float mu = stats[0];
        float var = red[0] * (1.0f / 65536.0f) - mu * mu;
        stats[1] = rsqrtf(var + 1e-5f);
    }
    __syncthreads();
    const float mu = stats[0], inv = stats[1];

    const int h = ng >> 2;
    const int bh = b * Hh + h;
    const int c0loc = c0 & 127;
    const int ngl = ng & 3;

    if (which == 0) {
        uint4* qdst = g_Qt + (size_t)(bh * 32) * 1024;
        #pragma unroll
        for (int q = 0; q < 32; q++) {
            int idx = t + 256 * q;
            int qd = idx & 7, cl = (idx >> 3) & 31, jt = idx >> 8;
            int p0 = jt * 64 + qd * 8;
            const float gwc = gwf[cl] * inv;
            const float gbc = gbf[cl] - mu * gwc;
            unsigned hv[4];
            #pragma unroll
            for (int k = 0; k < 4; k++) {
                __half2 y2 = *(__half2*)&ys[cl * YSS + p0 + 2 * k];
                float z0 = __half2float(y2.x) * gwc + gbc;
                float z1 = __half2float(y2.y) * gwc + gbc;
                z0 = (z0 >= 0.f) ? z0 : 0.1f * z0;
                z1 = (z1 >= 0.f) ? z1 : 0.1f * z1;
                hv[k] = packh2(z0, z1);
            }
            qdst[(size_t)jt * 1024 + (c0loc + cl) * 8 + qd] =
                make_uint4(hv[0], hv[1], hv[2], hv[3]);
        }
    } else {
        const float ksc = (which == 1) ? 0.12753102198074527f : 1.0f;
        uint4* dst = ((which == 1) ? g_Kt : g_Vt) + (size_t)(bh * 32) * 1024;
        #pragma unroll
        for (int q = 0; q < 16; q++) {
            int idx = t + 256 * q;
            int qd = idx & 3;
            int p = (idx >> 2) * 2;
            int ptile = p >> 6, r = p & 63;
            unsigned ha[4], hb[4];
            #pragma unroll
            for (int k2 = 0; k2 < 4; k2++) {
                int ca = qd * 8 + 2 * k2;
                const float gwa = gwf[ca] * inv * ksc;
                const float gba = gbf[ca] * ksc - mu * gwa;
                const float gwb = gwf[ca + 1] * inv * ksc;
                const float gbb = gbf[ca + 1] * ksc - mu * gwb;
                __half2 ya = *(__half2*)&ys[ca * YSS + p];
                __half2 yb = *(__half2*)&ys[(ca + 1) * YSS + p];
                float za0 = __half2float(ya.x) * gwa + gba;
                float za1 = __half2float(yb.x) * gwb + gbb;
                float zb0 = __half2float(ya.y) * gwa + gba;
                float zb1 = __half2float(yb.y) * gwb + gbb;
                za0 = (za0 >= 0.f) ? za0 : 0.1f * za0;
                za1 = (za1 >= 0.f) ? za1 : 0.1f * za1;
                zb0 = (zb0 >= 0.f) ? zb0 : 0.1f * zb0;
                zb1 = (zb1 >= 0.f) ? zb1 : 0.1f * zb1;
                ha[k2] = packh2(za0, za1);
                hb[k2] = packh2(zb0, zb1);
            }
            size_t tb = (size_t)ptile * 1024;
            dst[tb + r * 16 + ngl * 4 + qd]       = make_uint4(ha[0], ha[1], ha[2], ha[3]);
            dst[tb + (r + 1) * 16 + ngl * 4 + qd] = make_uint4(hb[0], hb[1], hb[2], hb[3]);
        }
    }
}

// ---------------------------------------------------------------------------
// Kernel 2: fused flash attention. fp16x2 exp (ex2.approx.f16x2 on packed
// pairs — no fp32 exp, no separate pack). Q frags prefetched before softmax
// and double-buffered across kj. l via ones-MMA. K A-frags hoisted.
// ---------------------------------------------------------------------------
#define SV     17408
#define SV_BUF 17408
#define SQ     52224
#define SQ_BUF 18432
#define SMEM_BYTES 89088

__global__ void __launch_bounds__(128, 2) flash_kernel(float* __restrict__ out)
{
    extern __shared__ unsigned char sm[];
    const unsigned sb = (unsigned)__cvta_generic_to_shared(sm);
    const int t = threadIdx.x, lane = t & 31, wrp = t >> 5;
    const int gid = lane >> 2, tig = lane & 3;
    const int it = blockIdx.x, bh = blockIdx.y;
    const int b = bh >> 3, h = bh & 7;
    const int i0 = it * 64;

    {
        const uint4* src = g_Kt + (size_t)(bh * 32 + it) * 1024;
        #pragma unroll
        for (int qq = 0; qq < 8; qq++) {
            int ch = t + 128 * qq;
            int i = ch >> 4, qd = ch & 15;
            cp16(sb + i * 272 + qd * 16, src + ch);
        }
    }
    auto stage_vq = [&](int jt, int buf) {
        const uint4* vs = g_Vt + (size_t)(bh * 32 + jt) * 1024;
        #pragma unroll
        for (int qq = 0; qq < 8; qq++) {
            int ch = t + 128 * qq;
            int j = ch >> 4, qd = ch & 15;
            cp16(sb + SV + buf * SV_BUF + j * 272 + qd * 16, vs + ch);
        }
        const uint4* qs = g_Qt + (size_t)(bh * 32 + jt) * 1024;
        #pragma unroll
        for (int qq = 0; qq < 8; qq++) {
            int ch = t + 128 * qq;
            int cr = ch >> 3, qd = ch & 7;
            cp16(sb + SQ + buf * SQ_BUF + cr * 144 + qd * 16, qs + ch);
        }
    };
    stage_vq(0, 0);
    asm volatile("cp.async.commit_group;" ::: "memory");
    asm volatile("cp.async.wait_group 0;" ::: "memory");
    __syncthreads();

    const int lq = lane >> 3, lr = lane & 7;
    const unsigned aOff = (wrp * 16 + ((lq & 1) << 3) + lr) * 272 + (lq >> 1) * 16;
    const unsigned bRow = ((lq >> 1) << 3) + lr;
    const unsigned bHlf = (lq & 1) * 16;

    // hoist K A-frags for all 8 k-steps (K resident, never changes)
    unsigned ahf[8][4];
    #pragma unroll
    for (int kk = 0; kk < 8; kk++) ldsm4(ahf[kk], sb + aOff + kk * 32);

    float accO[16][4];
    #pragma unroll
    for (int nf = 0; nf < 16; nf++)
        #pragma unroll
        for (int r = 0; r < 4; r++) accO[nf][r] = 0.f;
    float accL[4] = {0.f, 0.f, 0.f, 0.f};
    const unsigned ONESB = 0x3C003C00u;   // (1.0h, 1.0h)

    for (int jt = 0; jt < 32; jt++) {
        const int cur = jt & 1;
        if (jt < 31) {
            stage_vq(jt + 1, cur ^ 1);
            asm volatile("cp.async.commit_group;" ::: "memory");
        }

        float accS[8][4];
        #pragma unroll
        for (int nf = 0; nf < 8; nf++)
            #pragma unroll
            for (int r = 0; r < 4; r++) accS[nf][r] = 0.f;

        const unsigned vB = sb + SV + cur * SV_BUF + bRow * 272 + bHlf;
        #pragma unroll
        for (int kk = 0; kk < 8; kk++) {
            unsigned bhf[4][4];
            #pragma unroll
            for (int g2 = 0; g2 < 4; g2++)
                ldsm4(bhf[g2], vB + g2 * (16 * 272) + kk * 32);
            #pragma unroll
            for (int nf = 0; nf < 8; nf++) {
                unsigned bb[2] = {bhf[nf >> 1][2 * (nf & 1)], bhf[nf >> 1][2 * (nf & 1) + 1]};
                mma_fp16(accS[nf], ahf[kk], bb);
            }
        }

        // prefetch Q frags for kj=0 BEFORE softmax (fills MUFU window)
        const unsigned qB = sb + SQ + cur * SQ_BUF + bRow * 144 + bHlf;
        unsigned qf[2][8][4];
        #pragma unroll
        for (int g2 = 0; g2 < 8; g2++)
            ldsm4(qf[0][g2], qB + g2 * (16 * 144));

        // P = 2^S in fp16x2: pack fp32 pair -> f16x2, one f16x2 ex2 per pair
        unsigned pa[4][4];
        #pragma unroll
        for (int kj = 0; kj < 4; kj++) {
            pa[kj][0] = h2ex2(packh2(accS[2 * kj][0], accS[2 * kj][1]));
            pa[kj][1] = h2ex2(packh2(accS[2 * kj][2], accS[2 * kj][3]));
            pa[kj][2] = h2ex2(packh2(accS[2 * kj + 1][0], accS[2 * kj + 1][1]));
            pa[kj][3] = h2ex2(packh2(accS[2 * kj + 1][2], accS[2 * kj + 1][3]));
        }

        // row sums via MMA against constant ones
        {
            unsigned bb[2] = {ONESB, ONESB};
            #pragma unroll
            for (int kj = 0; kj < 4; kj++)
                mma_fp16(accL, pa[kj], bb);
        }

        // O += P * Q, Q frags double-buffered across kj
        #pragma unroll
        for (int kj = 0; kj < 4; kj++) {
            const int qc = kj & 1;
            if (kj < 3) {
                #pragma unroll
                for (int g2 = 0; g2 < 8; g2++)
                    ldsm4(qf[qc ^ 1][g2], qB + g2 * (16 * 144) + (kj + 1) * 32);
            }
            #pragma unroll
            for (int nf = 0; nf < 16; nf++) {
                unsigned bb[2] = {qf[qc][nf >> 1][2 * (nf & 1)],
                                  qf[qc][nf >> 1][2 * (nf & 1) + 1]};
                mma_fp16(accO[nf], pa[kj], bb);
            }
        }

        asm volatile("cp.async.wait_group 0;" ::: "memory");
        __syncthreads();
    }

    const float inv0 = 1.0f / accL[0], inv1 = 1.0f / accL[2];
    float* Ob = out + ((size_t)b * COUT + h * 128) * PDIM;
    const int ir0 = i0 + wrp * 16 + gid;
    #pragma unroll
    for (int nf = 0; nf < 16; nf++) {
        const int c = nf * 8 + 2 * tig;
        Ob[(size_t)c * PDIM + ir0]           = accO[nf][0] * inv0;
        Ob[(size_t)(c + 1) * PDIM + ir0]     = accO[nf][1] * inv0;
        Ob[(size_t)c * PDIM + ir0 + 8]       = accO[nf][2] * inv1;
        Ob[(size_t)(c + 1) * PDIM + ir0 + 8] = accO[nf][3] * inv1;
    }
}

// ---------------------------------------------------------------------------
extern "C" void kernel_launch(void* const* d_in, const int* in_sizes, int n_in,
                              void* d_out, int out_size)
{
    const float* x   = (const float*)d_in[0];
    const float* wq  = (const float*)d_in[1];
    const float* bq  = (const float*)d_in[2];
    const float* gw1 = (const float*)d_in[3];
    const float* gb1 = (const float*)d_in[4];
    const float* wk  = (const float*)d_in[5];
    const float* bk  = (const float*)d_in[6];
    const float* gw2 = (const float*)d_in[7];
    const float* gb2 = (const float*)d_in[8];
    const float* wv  = (const float*)d_in[9];
    const float* bv  = (const float*)d_in[10];
    const float* gw3 = (const float*)d_in[11];
    const float* gb3 = (const float*)d_in[12];
    float* out = (float*)d_out;

    static int smem_set = 0;
    if (!smem_set) {
        cudaFuncSetAttribute(flash_kernel,
                             cudaFuncAttributeMaxDynamicSharedMemorySize,
                             SMEM_BYTES);
        cudaFuncSetAttribute(qkv_gn_kernel,
                             cudaFuncAttributeMaxDynamicSharedMemorySize,
                             SMEM1_BYTES);
        smem_set = 1;
    }

    dim3 g1(NG, B_, 3);
    qkv_gn_kernel<<<g1, 256, SMEM1_BYTES>>>(x, wq, bq, gw1, gb1, wk, bk, gw2, gb2,
                                            wv, bv, gw3, gb3);

    dim3 gf(PDIM / 64, B_ * Hh);
    flash_kernel<<<gf, 128, SMEM_BYTES>>>(out);
}

// round 16
// speedup vs baseline: 10.5160x; 1.0091x over previous
#include <cuda_runtime.h>
#include <cuda_fp16.h>
#include <stdint.h>

#define B_    8
#define CIN   512
#define COUT  1024
#define PDIM  2048
#define Hh    8
#define NG    32

// ------------------------- device scratch (static) -------------------------
// fp16 tile buffers (ldmatrix-friendly row layouts), 64-row p-tiles
__device__ uint4 g_Kt[(size_t)B_ * Hh * 32 * 1024];   // [bh][it64] rows i(64), 16 c2-quads (pre-scaled)
__device__ uint4 g_Vt[(size_t)B_ * Hh * 32 * 1024];   // [bh][jt]   rows j(64), 16 c2-quads
__device__ uint4 g_Qt[(size_t)B_ * Hh * 32 * 1024];   // [bh][jt]   rows c(128), 8 j2-quads

// ------------------------------- helpers -----------------------------------
__device__ __forceinline__ unsigned packh2(float a, float b) {
    __half2 h = __floats2half2_rn(a, b);
    return *reinterpret_cast<unsigned*>(&h);
}
__device__ __forceinline__ unsigned h2ex2(unsigned x) {
    unsigned r;
    asm("ex2.approx.f16x2 %0, %1;" : "=r"(r) : "r"(x));
    return r;
}
__device__ __forceinline__ void cp16(unsigned s, const void* g) {
    asm volatile("cp.async.cg.shared.global [%0], [%1], 16;" :: "r"(s), "l"(g));
}
__device__ __forceinline__ void ldsm4(unsigned (&d)[4], unsigned addr) {
    asm volatile("ldmatrix.sync.aligned.m8n8.x4.shared.b16 {%0,%1,%2,%3}, [%4];"
                 : "=r"(d[0]), "=r"(d[1]), "=r"(d[2]), "=r"(d[3]) : "r"(addr));
}
__device__ __forceinline__ void ldsm4t(unsigned (&d)[4], unsigned addr) {
    asm volatile("ldmatrix.sync.aligned.m8n8.x4.trans.shared.b16 {%0,%1,%2,%3}, [%4];"
                 : "=r"(d[0]), "=r"(d[1]), "=r"(d[2]), "=r"(d[3]) : "r"(addr));
}
__device__ __forceinline__ void mma_fp16(float (&c)[4], const unsigned (&a)[4],
                                          const unsigned (&b)[2]) {
    asm volatile(
        "mma.sync.aligned.m16n8k16.row.col.f32.f16.f16.f32 "
        "{%0,%1,%2,%3}, {%4,%5,%6,%7}, {%8,%9}, {%0,%1,%2,%3};\n"
        : "+f"(c[0]), "+f"(c[1]), "+f"(c[2]), "+f"(c[3])
        : "r"(a[0]), "r"(a[1]), "r"(a[2]), "r"(a[3]), "r"(b[0]), "r"(b[1]));
}

// ---------------------------------------------------------------------------
// Kernel 1: grouped 1x1 conv (fp16 tensor-core GEMM) + GroupNorm + LeakyReLU
// -> fp16 tiles. K branch pre-scaled by scale*log2(e). (unchanged)
// ---------------------------------------------------------------------------
#define YSS     2050
#define XTS     264
#define XT_OFF  131200
#define WS_OFF  164992
#define BS_OFF  169600
#define RED_OFF 169984
#define SMEM1_BYTES 171040

__global__ __launch_bounds__(256, 1) void qkv_gn_kernel(
    const float* __restrict__ x,
    const float* __restrict__ wq, const float* __restrict__ bq_,
    const float* __restrict__ gw1, const float* __restrict__ gb1,
    const float* __restrict__ wk, const float* __restrict__ bk_,
    const float* __restrict__ gw2, const float* __restrict__ gb2,
    const float* __restrict__ wv, const float* __restrict__ bv_,
    const float* __restrict__ gw3, const float* __restrict__ gb3)
{
    const int which = blockIdx.z;
    const float* w    = which == 0 ? wq  : which == 1 ? wk  : wv;
    const float* bias = which == 0 ? bq_ : which == 1 ? bk_ : bv_;
    const float* gw   = which == 0 ? gw1 : which == 1 ? gw2 : gw3;
    const float* gb   = which == 0 ? gb1 : which == 1 ? gb2 : gb3;

    const int ng = blockIdx.x;
    const int b  = blockIdx.y;
    const int c0 = ng * 32;
    const int g  = ng >> 2;
    const int f0 = g * 64;

    extern __shared__ unsigned char smq[];
    __half* ys  = (__half*)smq;
    __half* xt  = (__half*)(smq + XT_OFF);
    __half* wsh = (__half*)(smq + WS_OFF);
    float*  bsf = (float*)(smq + BS_OFF);
    float*  gwf = bsf + 32;
    float*  gbf = bsf + 64;
    float*  red = (float*)(smq + RED_OFF);
    float*  stats = red + 256;
    const unsigned sq = (unsigned)__cvta_generic_to_shared(smq);

    const int t = threadIdx.x, lane = t & 31, wrp = t >> 5;
    const int gid = lane >> 2, tig = lane & 3;
    const int lq = lane >> 3, lr = lane & 7;

    for (int i = t; i < 2048; i += 256) {
        int c = i >> 6, f = i & 63;
        wsh[c * 72 + f] = __float2half_rn(w[(size_t)(c0 + c) * 64 + f]);
    }
    if (t < 32) { bsf[t] = bias[c0 + t]; gwf[t] = gw[c0 + t]; gbf[t] = gb[c0 + t]; }

    const float* xb = x + (size_t)b * CIN * PDIM + (size_t)f0 * PDIM;
    float sum = 0.f, sumsq = 0.f;

    const unsigned aB = sq + WS_OFF + (((lq & 1) << 3) + lr) * 144 + (lq >> 1) * 16;
    const unsigned bB = sq + XT_OFF + (((lq & 1) << 3) + lr) * 528 +
                        ((lq >> 1) << 3) * 2 + wrp * 64;

    for (int pt = 0; pt < 8; pt++) {
        __syncthreads();
        #pragma unroll
        for (int q = 0; q < 32; q++) {
            int idx = t + 256 * q;
            int r = idx >> 7, p2 = idx & 127;
            float2 v = *(const float2*)(xb + (size_t)r * PDIM + pt * 256 + 2 * p2);
            *(__half2*)(xt + r * XTS + 2 * p2) = __floats2half2_rn(v.x, v.y);
        }
        __syncthreads();

        float acc[2][4][4];
        #pragma unroll
        for (int mt = 0; mt < 2; mt++)
            #pragma unroll
            for (int pg = 0; pg < 4; pg++)
                #pragma unroll
                for (int r = 0; r < 4; r++) acc[mt][pg][r] = 0.f;

        #pragma unroll
        for (int kk = 0; kk < 4; kk++) {
            unsigned a0[4], a1[4], b0[4], b1[4];
            ldsm4(a0, aB + kk * 32);
            ldsm4(a1, aB + 16 * 144 + kk * 32);
            ldsm4t(b0, bB + kk * 8448);
            ldsm4t(b1, bB + kk * 8448 + 32);
            #pragma unroll
            for (int pg = 0; pg < 4; pg++) {
                const unsigned* bf = (pg < 2) ? b0 : b1;
                unsigned bb[2] = {bf[2 * (pg & 1)], bf[2 * (pg & 1) + 1]};
                mma_fp16(acc[0][pg], a0, bb);
                mma_fp16(acc[1][pg], a1, bb);
            }
        }

        #pragma unroll
        for (int mt = 0; mt < 2; mt++) {
            const float bc0 = bsf[mt * 16 + gid], bc1 = bsf[mt * 16 + gid + 8];
            #pragma unroll
            for (int pg = 0; pg < 4; pg++) {
                float v0 = acc[mt][pg][0] + bc0, v1 = acc[mt][pg][1] + bc0;
                float v2 = acc[mt][pg][2] + bc1, v3 = acc[mt][pg][3] + bc1;
                sum += v0 + v1 + v2 + v3;
                sumsq += v0 * v0 + v1 * v1 + v2 * v2 + v3 * v3;
                int p = pt * 256 + wrp * 32 + pg * 8 + 2 * tig;
                *(__half2*)&ys[(mt * 16 + gid) * YSS + p]     = __floats2half2_rn(v0, v1);
                *(__half2*)&ys[(mt * 16 + gid + 8) * YSS + p] = __floats2half2_rn(v2, v3);
            }
        }
    }

    __syncthreads();
    red[t] = sum; __syncthreads();
    for (int s = 128; s > 0; s >>= 1) { if (t < s) red[t] += red[t + s]; __syncthreads(); }
    if (t == 0) stats[0] = red[0] * (1.0f / 65536.0f);
    __syncthreads();
    red[t] = sumsq; __syncthreads();
    for (int s = 128; s > 0; s >>= 1) { if (t < s) red[t] += red[t + s]; __syncthreads(); }
    if (t == 0) {
        float mu = stats[0];
        float var = red[0] * (1.0f / 65536.0f) - mu * mu;
        stats[1] = rsqrtf(var + 1e-5f);
    }
    __syncthreads();
    const float mu = stats[0], inv = stats[1];

    const int h = ng >> 2;
    const int bh = b * Hh + h;
    const int c0loc = c0 & 127;
    const int ngl = ng & 3;

    if (which == 0) {
        uint4* qdst = g_Qt + (size_t)(bh * 32) * 1024;
        #pragma unroll
        for (int q = 0; q < 32; q++) {
            int idx = t + 256 * q;
            int qd = idx & 7, cl = (idx >> 3) & 31, jt = idx >> 8;
            int p0 = jt * 64 + qd * 8;
            const float gwc = gwf[cl] * inv;
            const float gbc = gbf[cl] - mu * gwc;
            unsigned hv[4];
            #pragma unroll
            for (int k = 0; k < 4; k++) {
                __half2 y2 = *(__half2*)&ys[cl * YSS + p0 + 2 * k];
                float z0 = __half2float(y2.x) * gwc + gbc;
                float z1 = __half2float(y2.y) * gwc + gbc;
                z0 = (z0 >= 0.f) ? z0 : 0.1f * z0;
                z1 = (z1 >= 0.f) ? z1 : 0.1f * z1;
                hv[k] = packh2(z0, z1);
            }
            qdst[(size_t)jt * 1024 + (c0loc + cl) * 8 + qd] =
                make_uint4(hv[0], hv[1], hv[2], hv[3]);
        }
    } else {
        const float ksc = (which == 1) ? 0.12753102198074527f : 1.0f;
        uint4* dst = ((which == 1) ? g_Kt : g_Vt) + (size_t)(bh * 32) * 1024;
        #pragma unroll
        for (int q = 0; q < 16; q++) {
            int idx = t + 256 * q;
            int qd = idx & 3;
            int p = (idx >> 2) * 2;
            int ptile = p >> 6, r = p & 63;
            unsigned ha[4], hb[4];
            #pragma unroll
            for (int k2 = 0; k2 < 4; k2++) {
                int ca = qd * 8 + 2 * k2;
                const float gwa = gwf[ca] * inv * ksc;
                const float gba = gbf[ca] * ksc - mu * gwa;
                const float gwb = gwf[ca + 1] * inv * ksc;
                const float gbb = gbf[ca + 1] * ksc - mu * gwb;
                __half2 ya = *(__half2*)&ys[ca * YSS + p];
                __half2 yb = *(__half2*)&ys[(ca + 1) * YSS + p];
                float za0 = __half2float(ya.x) * gwa + gba;
                float za1 = __half2float(yb.x) * gwb + gbb;
                float zb0 = __half2float(ya.y) * gwa + gba;
                float zb1 = __half2float(yb.y) * gwb + gbb;
                za0 = (za0 >= 0.f) ? za0 : 0.1f * za0;
                za1 = (za1 >= 0.f) ? za1 : 0.1f * za1;
                zb0 = (zb0 >= 0.f) ? zb0 : 0.1f * zb0;
                zb1 = (zb1 >= 0.f) ? zb1 : 0.1f * zb1;
                ha[k2] = packh2(za0, za1);
                hb[k2] = packh2(zb0, zb1);
            }
            size_t tb = (size_t)ptile * 1024;
            dst[tb + r * 16 + ngl * 4 + qd]       = make_uint4(ha[0], ha[1], ha[2], ha[3]);
            dst[tb + (r + 1) * 16 + ngl * 4 + qd] = make_uint4(hb[0], hb[1], hb[2], hb[3]);
        }
    }
}

// ---------------------------------------------------------------------------
// Kernel 2: fused flash attention, 3 CTAs/SM.
// V double-buffered; Q SINGLE-buffered with deferred prefetch (issued after
// the end-of-tile sync, awaited just before the O-phase — hidden under the
// next tile's S+softmax). Commit-group ladder:
//   top of t (t<31): commit V(t+1); wait_group 2  -> V(t) ready
//   pre-O          : wait_group 1 (t<31) / 0      -> Q(t) ready
//   after sync     : commit Q(t+1)
// smem 69KB -> 3 CTAs/SM; launch_bounds(128,3) caps regs at 170.
// ---------------------------------------------------------------------------
#define SV     17408
#define SV_BUF 17408
#define SQ     52224
#define SMEM_BYTES 70656

__global__ void __launch_bounds__(128, 3) flash_kernel(float* __restrict__ out)
{
    extern __shared__ unsigned char sm[];
    const unsigned sb = (unsigned)__cvta_generic_to_shared(sm);
    const int t = threadIdx.x, lane = t & 31, wrp = t >> 5;
    const int gid = lane >> 2, tig = lane & 3;
    const int it = blockIdx.x, bh = blockIdx.y;
    const int b = bh >> 3, h = bh & 7;
    const int i0 = it * 64;

    // resident K staging (17KB)
    {
        const uint4* src = g_Kt + (size_t)(bh * 32 + it) * 1024;
        #pragma unroll
        for (int qq = 0; qq < 8; qq++) {
            int ch = t + 128 * qq;
            int i = ch >> 4, qd = ch & 15;
            cp16(sb + i * 272 + qd * 16, src + ch);
        }
    }
    auto stage_v = [&](int jt, int buf) {
        const uint4* vs = g_Vt + (size_t)(bh * 32 + jt) * 1024;
        #pragma unroll
        for (int qq = 0; qq < 8; qq++) {
            int ch = t + 128 * qq;
            int j = ch >> 4, qd = ch & 15;
            cp16(sb + SV + buf * SV_BUF + j * 272 + qd * 16, vs + ch);
        }
    };
    auto stage_q = [&](int jt) {
        const uint4* qs = g_Qt + (size_t)(bh * 32 + jt) * 1024;
        #pragma unroll
        for (int qq = 0; qq < 8; qq++) {
            int ch = t + 128 * qq;
            int cr = ch >> 3, qd = ch & 7;
            cp16(sb + SQ + cr * 144 + qd * 16, qs + ch);
        }
    };
    stage_v(0, 0);
    stage_q(0);
    asm volatile("cp.async.commit_group;" ::: "memory");
    asm volatile("cp.async.wait_group 0;" ::: "memory");
    __syncthreads();

    const int lq = lane >> 3, lr = lane & 7;
    const unsigned aOff = (wrp * 16 + ((lq & 1) << 3) + lr) * 272 + (lq >> 1) * 16;
    const unsigned bRow = ((lq >> 1) << 3) + lr;
    const unsigned bHlf = (lq & 1) * 16;

    // hoist K A-frags (K resident, never changes)
    unsigned ahf[8][4];
    #pragma unroll
    for (int kk = 0; kk < 8; kk++) ldsm4(ahf[kk], sb + aOff + kk * 32);

    float accO[16][4];
    #pragma unroll
    for (int nf = 0; nf < 16; nf++)
        #pragma unroll
        for (int r = 0; r < 4; r++) accO[nf][r] = 0.f;
    float accL[4] = {0.f, 0.f, 0.f, 0.f};
    const unsigned ONESB = 0x3C003C00u;   // (1.0h, 1.0h)
    const unsigned qB = sb + SQ + bRow * 144 + bHlf;

    for (int jt = 0; jt < 32; jt++) {
        const int cur = jt & 1;
        if (jt < 31) {
            stage_v(jt + 1, cur ^ 1);
            asm volatile("cp.async.commit_group;" ::: "memory");
            asm volatile("cp.async.wait_group 2;" ::: "memory");
        } else {
            asm volatile("cp.async.wait_group 1;" ::: "memory");
        }

        float accS[8][4];
        #pragma unroll
        for (int nf = 0; nf < 8; nf++)
            #pragma unroll
            for (int r = 0; r < 4; r++) accS[nf][r] = 0.f;

        const unsigned vB = sb + SV + cur * SV_BUF + bRow * 272 + bHlf;
        #pragma unroll
        for (int kk = 0; kk < 8; kk++) {
            unsigned bhf[4][4];
            #pragma unroll
            for (int g2 = 0; g2 < 4; g2++)
                ldsm4(bhf[g2], vB + g2 * (16 * 272) + kk * 32);
            #pragma unroll
            for (int nf = 0; nf < 8; nf++) {
                unsigned bb[2] = {bhf[nf >> 1][2 * (nf & 1)], bhf[nf >> 1][2 * (nf & 1) + 1]};
                mma_fp16(accS[nf], ahf[kk], bb);
            }
        }

        // P = 2^S in fp16x2
        unsigned pa[4][4];
        #pragma unroll
        for (int kj = 0; kj < 4; kj++) {
            pa[kj][0] = h2ex2(packh2(accS[2 * kj][0], accS[2 * kj][1]));
            pa[kj][1] = h2ex2(packh2(accS[2 * kj][2], accS[2 * kj][3]));
            pa[kj][2] = h2ex2(packh2(accS[2 * kj + 1][0], accS[2 * kj + 1][1]));
            pa[kj][3] = h2ex2(packh2(accS[2 * kj + 1][2], accS[2 * kj + 1][3]));
        }

        // row sums via ones-MMA
        {
            unsigned bb[2] = {ONESB, ONESB};
            #pragma unroll
            for (int kj = 0; kj < 4; kj++)
                mma_fp16(accL, pa[kj], bb);
        }

        // Q(t) ready?
        if (jt < 31) {
            asm volatile("cp.async.wait_group 1;" ::: "memory");
        } else {
            asm volatile("cp.async.wait_group 0;" ::: "memory");
        }

        // O += P * Q
        #pragma unroll
        for (int kj = 0; kj < 4; kj++) {
            unsigned qf[8][4];
            #pragma unroll
            for (int g2 = 0; g2 < 8; g2++)
                ldsm4(qf[g2], qB + g2 * (16 * 144) + kj * 32);
            #pragma unroll
            for (int nf = 0; nf < 16; nf++) {
                unsigned bb[2] = {qf[nf >> 1][2 * (nf & 1)], qf[nf >> 1][2 * (nf & 1) + 1]};
                mma_fp16(accO[nf], pa[kj], bb);
            }
        }

        __syncthreads();
        if (jt < 31) {
            stage_q(jt + 1);
            asm volatile("cp.async.commit_group;" ::: "memory");
        }
    }

    const float inv0 = 1.0f / accL[0], inv1 = 1.0f / accL[2];
    float* Ob = out + ((size_t)b * COUT + h * 128) * PDIM;
    const int ir0 = i0 + wrp * 16 + gid;
    #pragma unroll
    for (int nf = 0; nf < 16; nf++) {
        const int c = nf * 8 + 2 * tig;
        Ob[(size_t)c * PDIM + ir0]           = accO[nf][0] * inv0;
        Ob[(size_t)(c + 1) * PDIM + ir0]     = accO[nf][1] * inv0;
        Ob[(size_t)c * PDIM + ir0 + 8]       = accO[nf][2] * inv1;
        Ob[(size_t)(c + 1) * PDIM + ir0 + 8] = accO[nf][3] * inv1;
    }
}

// ---------------------------------------------------------------------------
extern "C" void kernel_launch(void* const* d_in, const int* in_sizes, int n_in,
                              void* d_out, int out_size)
{
    const float* x   = (const float*)d_in[0];
    const float* wq  = (const float*)d_in[1];
    const float* bq  = (const float*)d_in[2];
    const float* gw1 = (const float*)d_in[3];
    const float* gb1 = (const float*)d_in[4];
    const float* wk  = (const float*)d_in[5];
    const float* bk  = (const float*)d_in[6];
    const float* gw2 = (const float*)d_in[7];
    const float* gb2 = (const float*)d_in[8];
    const float* wv  = (const float*)d_in[9];
    const float* bv  = (const float*)d_in[10];
    const float* gw3 = (const float*)d_in[11];
    const float* gb3 = (const float*)d_in[12];
    float* out = (float*)d_out;

    static int smem_set = 0;
    if (!smem_set) {
        cudaFuncSetAttribute(flash_kernel,
                             cudaFuncAttributeMaxDynamicSharedMemorySize,
                             SMEM_BYTES);
        cudaFuncSetAttribute(qkv_gn_kernel,
                             cudaFuncAttributeMaxDynamicSharedMemorySize,
                             SMEM1_BYTES);
        smem_set = 1;
    }

    dim3 g1(NG, B_, 3);
    qkv_gn_kernel<<<g1, 256, SMEM1_BYTES>>>(x, wq, bq, gw1, gb1, wk, bk, gw2, gb2,
                                            wv, bv, gw3, gb3);

    dim3 gf(PDIM / 64, B_ * Hh);
    flash_kernel<<<gf, 128, SMEM_BYTES>>>(out);
}

// round 17
// speedup vs baseline: 10.9303x; 1.0394x over previous
#include <cuda_runtime.h>
#include <cuda_fp16.h>
#include <stdint.h>

#define B_    8
#define CIN   512
#define COUT  1024
#define PDIM  2048
#define Hh    8
#define NG    32

// ------------------------- device scratch (static) -------------------------
// fp16 tile buffers (ldmatrix-friendly row layouts), 64-row p-tiles
__device__ uint4 g_Kt[(size_t)B_ * Hh * 32 * 1024];   // [bh][it64] rows i(64), 16 c2-quads (pre-scaled)
__device__ uint4 g_Vt[(size_t)B_ * Hh * 32 * 1024];   // [bh][jt]   rows j(64), 16 c2-quads
__device__ uint4 g_Qt[(size_t)B_ * Hh * 32 * 1024];   // [bh][jt]   rows c(128), 8 j2-quads

// ------------------------------- helpers -----------------------------------
__device__ __forceinline__ unsigned packh2(float a, float b) {
    __half2 h = __floats2half2_rn(a, b);
    return *reinterpret_cast<unsigned*>(&h);
}
__device__ __forceinline__ unsigned h2ex2(unsigned x) {
    unsigned r;
    asm("ex2.approx.f16x2 %0, %1;" : "=r"(r) : "r"(x));
    return r;
}
__device__ __forceinline__ void cp16(unsigned s, const void* g) {
    asm volatile("cp.async.cg.shared.global [%0], [%1], 16;" :: "r"(s), "l"(g));
}
__device__ __forceinline__ void ldsm4(unsigned (&d)[4], unsigned addr) {
    asm volatile("ldmatrix.sync.aligned.m8n8.x4.shared.b16 {%0,%1,%2,%3}, [%4];"
                 : "=r"(d[0]), "=r"(d[1]), "=r"(d[2]), "=r"(d[3]) : "r"(addr));
}
__device__ __forceinline__ void ldsm4t(unsigned (&d)[4], unsigned addr) {
    asm volatile("ldmatrix.sync.aligned.m8n8.x4.trans.shared.b16 {%0,%1,%2,%3}, [%4];"
                 : "=r"(d[0]), "=r"(d[1]), "=r"(d[2]), "=r"(d[3]) : "r"(addr));
}
__device__ __forceinline__ void mma_fp16(float (&c)[4], const unsigned (&a)[4],
                                          const unsigned (&b)[2]) {
    asm volatile(
        "mma.sync.aligned.m16n8k16.row.col.f32.f16.f16.f32 "
        "{%0,%1,%2,%3}, {%4,%5,%6,%7}, {%8,%9}, {%0,%1,%2,%3};\n"
        : "+f"(c[0]), "+f"(c[1]), "+f"(c[2]), "+f"(c[3])
        : "r"(a[0]), "r"(a[1]), "r"(a[2]), "r"(a[3]), "r"(b[0]), "r"(b[1]));
}

// ---------------------------------------------------------------------------
// Kernel 1: grouped 1x1 conv (fp16 tensor-core GEMM) + GroupNorm + LeakyReLU
// -> fp16 tiles. K branch pre-scaled by scale*log2(e).
// Round-17: float4 staging (16 LDG.128 + 16 STS.64 per thread) with
// register-prefetch of x(pt+1) overlapping the MMA phase of pt.
// ---------------------------------------------------------------------------
#define YSS     2050
#define XTS     264
#define XT_OFF  131200
#define WS_OFF  164992
#define BS_OFF  169600
#define RED_OFF 169984
#define SMEM1_BYTES 171040

__global__ __launch_bounds__(256, 1) void qkv_gn_kernel(
    const float* __restrict__ x,
    const float* __restrict__ wq, const float* __restrict__ bq_,
    const float* __restrict__ gw1, const float* __restrict__ gb1,
    const float* __restrict__ wk, const float* __restrict__ bk_,
    const float* __restrict__ gw2, const float* __restrict__ gb2,
    const float* __restrict__ wv, const float* __restrict__ bv_,
    const float* __restrict__ gw3, const float* __restrict__ gb3)
{
    const int which = blockIdx.z;
    const float* w    = which == 0 ? wq  : which == 1 ? wk  : wv;
    const float* bias = which == 0 ? bq_ : which == 1 ? bk_ : bv_;
    const float* gw   = which == 0 ? gw1 : which == 1 ? gw2 : gw3;
    const float* gb   = which == 0 ? gb1 : which == 1 ? gb2 : gb3;

    const int ng = blockIdx.x;
    const int b  = blockIdx.y;
    const int c0 = ng * 32;
    const int g  = ng >> 2;
    const int f0 = g * 64;

    extern __shared__ unsigned char smq[];
    __half* ys  = (__half*)smq;
    __half* xt  = (__half*)(smq + XT_OFF);
    __half* wsh = (__half*)(smq + WS_OFF);
    float*  bsf = (float*)(smq + BS_OFF);
    float*  gwf = bsf + 32;
    float*  gbf = bsf + 64;
    float*  red = (float*)(smq + RED_OFF);
    float*  stats = red + 256;
    const unsigned sq = (unsigned)__cvta_generic_to_shared(smq);

    const int t = threadIdx.x, lane = t & 31, wrp = t >> 5;
    const int gid = lane >> 2, tig = lane & 3;
    const int lq = lane >> 3, lr = lane & 7;

    for (int i = t; i < 2048; i += 256) {
        int c = i >> 6, f = i & 63;
        wsh[c * 72 + f] = __float2half_rn(w[(size_t)(c0 + c) * 64 + f]);
    }
    if (t < 32) { bsf[t] = bias[c0 + t]; gwf[t] = gw[c0 + t]; gbf[t] = gb[c0 + t]; }

    const float* xb = x + (size_t)b * CIN * PDIM + (size_t)f0 * PDIM;
    float sum = 0.f, sumsq = 0.f;

    const unsigned aB = sq + WS_OFF + (((lq & 1) << 3) + lr) * 144 + (lq >> 1) * 16;
    const unsigned bB = sq + XT_OFF + (((lq & 1) << 3) + lr) * 528 +
                        ((lq >> 1) << 3) * 2 + wrp * 64;

    // x-tile staging: thread t owns 16 float4 slots (64 rows x 64 float4)
    const int sr_ = t >> 6;            // unused helper silencing
    (void)sr_;
    float4 xr[16];
    auto load_x = [&](int pt) {
        #pragma unroll
        for (int q = 0; q < 16; q++) {
            int s = t + 256 * q;
            int r = s >> 6, c4 = s & 63;
            xr[q] = *(const float4*)(xb + (size_t)r * PDIM + pt * 256 + 4 * c4);
        }
    };
    load_x(0);

    for (int pt = 0; pt < 8; pt++) {
        __syncthreads();   // xt free (previous MMA phase done)
        #pragma unroll
        for (int q = 0; q < 16; q++) {
            int s = t + 256 * q;
            int r = s >> 6, c4 = s & 63;
            __half2 h0 = __floats2half2_rn(xr[q].x, xr[q].y);
            __half2 h1 = __floats2half2_rn(xr[q].z, xr[q].w);
            uint2 u;
            u.x = *(unsigned*)&h0;
            u.y = *(unsigned*)&h1;
            *(uint2*)(xt + r * XTS + 4 * c4) = u;
        }
        __syncthreads();   // xt ready
        if (pt < 7) load_x(pt + 1);   // gmem loads overlap MMA below

        float acc[2][4][4];
        #pragma unroll
        for (int mt = 0; mt < 2; mt++)
            #pragma unroll
            for (int pg = 0; pg < 4; pg++)
                #pragma unroll
                for (int r = 0; r < 4; r++) acc[mt][pg][r] = 0.f;

        #pragma unroll
        for (int kk = 0; kk < 4; kk++) {
            unsigned a0[4], a1[4], b0[4], b1[4];
            ldsm4(a0, aB + kk * 32);
            ldsm4(a1, aB + 16 * 144 + kk * 32);
            ldsm4t(b0, bB + kk * 8448);
            ldsm4t(b1, bB + kk * 8448 + 32);
            #pragma unroll
            for (int pg = 0; pg < 4; pg++) {
                const unsigned* bf = (pg < 2) ? b0 : b1;
                unsigned bb[2] = {bf[2 * (pg & 1)], bf[2 * (pg & 1) + 1]};
                mma_fp16(acc[0][pg], a0, bb);
                mma_fp16(acc[1][pg], a1, bb);
            }
        }

        #pragma unroll
        for (int mt = 0; mt < 2; mt++) {
            const float bc0 = bsf[mt * 16 + gid], bc1 = bsf[mt * 16 + gid + 8];
            #pragma unroll
            for (int pg = 0; pg < 4; pg++) {
                float v0 = acc[mt][pg][0] + bc0, v1 = acc[mt][pg][1] + bc0;
                float v2 = acc[mt][pg][2] + bc1, v3 = acc[mt][pg][3] + bc1;
                sum += v0 + v1 + v2 + v3;
                sumsq += v0 * v0 + v1 * v1 + v2 * v2 + v3 * v3;
                int p = pt * 256 + wrp * 32 + pg * 8 + 2 * tig;
                *(__half2*)&ys[(mt * 16 + gid) * YSS + p]     = __floats2half2_rn(v0, v1);
                *(__half2*)&ys[(mt * 16 + gid + 8) * YSS + p] = __floats2half2_rn(v2, v3);
            }
        }
    }

    __syncthreads();
    red[t] = sum; __syncthreads();
    for (int s = 128; s > 0; s >>= 1) { if (t < s) red[t] += red[t + s]; __syncthreads(); }
    if (t == 0) stats[0] = red[0] * (1.0f / 65536.0f);
    __syncthreads();
    red[t] = sumsq; __syncthreads();
    for (int s = 128; s > 0; s >>= 1) { if (t < s) red[t] += red[t + s]; __syncthreads(); }
    if (t == 0) {
        float mu = stats[0];
        float var = red[0] * (1.0f / 65536.0f) - mu * mu;
        stats[1] = rsqrtf(var + 1e-5f);
    }
    __syncthreads();
    const float mu = stats[0], inv = stats[1];

    const int h = ng >> 2;
    const int bh = b * Hh + h;
    const int c0loc = c0 & 127;
    const int ngl = ng & 3;

    if (which == 0) {
        uint4* qdst = g_Qt + (size_t)(bh * 32) * 1024;
        #pragma unroll
        for (int q = 0; q < 32; q++) {
            int idx = t + 256 * q;
            int qd = idx & 7, cl = (idx >> 3) & 31, jt = idx >> 8;
            int p0 = jt * 64 + qd * 8;
            const float gwc = gwf[cl] * inv;
            const float gbc = gbf[cl] - mu * gwc;
            unsigned hv[4];
            #pragma unroll
            for (int k = 0; k < 4; k++) {
                __half2 y2 = *(__half2*)&ys[cl * YSS + p0 + 2 * k];
                float z0 = __half2float(y2.x) * gwc + gbc;
                float z1 = __half2float(y2.y) * gwc + gbc;
                z0 = (z0 >= 0.f) ? z0 : 0.1f * z0;
                z1 = (z1 >= 0.f) ? z1 : 0.1f * z1;
                hv[k] = packh2(z0, z1);
            }
            qdst[(size_t)jt * 1024 + (c0loc + cl) * 8 + qd] =
                make_uint4(hv[0], hv[1], hv[2], hv[3]);
        }
    } else {
        const float ksc = (which == 1) ? 0.12753102198074527f : 1.0f;
        uint4* dst = ((which == 1) ? g_Kt : g_Vt) + (size_t)(bh * 32) * 1024;
        #pragma unroll
        for (int q = 0; q < 16; q++) {
            int idx = t + 256 * q;
            int qd = idx & 3;
            int p = (idx >> 2) * 2;
            int ptile = p >> 6, r = p & 63;
            unsigned ha[4], hb[4];
            #pragma unroll
            for (int k2 = 0; k2 < 4; k2++) {
                int ca = qd * 8 + 2 * k2;
                const float gwa = gwf[ca] * inv * ksc;
                const float gba = gbf[ca] * ksc - mu * gwa;
                const float gwb = gwf[ca + 1] * inv * ksc;
                const float gbb = gbf[ca + 1] * ksc - mu * gwb;
                __half2 ya = *(__half2*)&ys[ca * YSS + p];
                __half2 yb = *(__half2*)&ys[(ca + 1) * YSS + p];
                float za0 = __half2float(ya.x) * gwa + gba;
                float za1 = __half2float(yb.x) * gwb + gbb;
                float zb0 = __half2float(ya.y) * gwa + gba;
                float zb1 = __half2float(yb.y) * gwb + gbb;
                za0 = (za0 >= 0.f) ? za0 : 0.1f * za0;
                za1 = (za1 >= 0.f) ? za1 : 0.1f * za1;
                zb0 = (zb0 >= 0.f) ? zb0 : 0.1f * zb0;
                zb1 = (zb1 >= 0.f) ? zb1 : 0.1f * zb1;
                ha[k2] = packh2(za0, za1);
                hb[k2] = packh2(zb0, zb1);
            }
            size_t tb = (size_t)ptile * 1024;
            dst[tb + r * 16 + ngl * 4 + qd]       = make_uint4(ha[0], ha[1], ha[2], ha[3]);
            dst[tb + (r + 1) * 16 + ngl * 4 + qd] = make_uint4(hb[0], hb[1], hb[2], hb[3]);
        }
    }
}

// ---------------------------------------------------------------------------
// Kernel 2: fused flash attention, 3 CTAs/SM (unchanged from round 16).
// ---------------------------------------------------------------------------
#define SV     17408
#define SV_BUF 17408
#define SQ     52224
#define SMEM_BYTES 70656

__global__ void __launch_bounds__(128, 3) flash_kernel(float* __restrict__ out)
{
    extern __shared__ unsigned char sm[];
    const unsigned sb = (unsigned)__cvta_generic_to_shared(sm);
    const int t = threadIdx.x, lane = t & 31, wrp = t >> 5;
    const int gid = lane >> 2, tig = lane & 3;
    const int it = blockIdx.x, bh = blockIdx.y;
    const int b = bh >> 3, h = bh & 7;
    const int i0 = it * 64;

    // resident K staging (17KB)
    {
        const uint4* src = g_Kt + (size_t)(bh * 32 + it) * 1024;
        #pragma unroll
        for (int qq = 0; qq < 8; qq++) {
            int ch = t + 128 * qq;
            int i = ch >> 4, qd = ch & 15;
            cp16(sb + i * 272 + qd * 16, src + ch);
        }
    }
    auto stage_v = [&](int jt, int buf) {
        const uint4* vs = g_Vt + (size_t)(bh * 32 + jt) * 1024;
        #pragma unroll
        for (int qq = 0; qq < 8; qq++) {
            int ch = t + 128 * qq;
            int j = ch >> 4, qd = ch & 15;
            cp16(sb + SV + buf * SV_BUF + j * 272 + qd * 16, vs + ch);
        }
    };
    auto stage_q = [&](int jt) {
        const uint4* qs = g_Qt + (size_t)(bh * 32 + jt) * 1024;
        #pragma unroll
        for (int qq = 0; qq < 8; qq++) {
            int ch = t + 128 * qq;
            int cr = ch >> 3, qd = ch & 7;
            cp16(sb + SQ + cr * 144 + qd * 16, qs + ch);
        }
    };
    stage_v(0, 0);
    stage_q(0);
    asm volatile("cp.async.commit_group;" ::: "memory");
    asm volatile("cp.async.wait_group 0;" ::: "memory");
    __syncthreads();

    const int lq = lane >> 3, lr = lane & 7;
    const unsigned aOff = (wrp * 16 + ((lq & 1) << 3) + lr) * 272 + (lq >> 1) * 16;
    const unsigned bRow = ((lq >> 1) << 3) + lr;
    const unsigned bHlf = (lq & 1) * 16;

    unsigned ahf[8][4];
    #pragma unroll
    for (int kk = 0; kk < 8; kk++) ldsm4(ahf[kk], sb + aOff + kk * 32);

    float accO[16][4];
    #pragma unroll
    for (int nf = 0; nf < 16; nf++)
        #pragma unroll
        for (int r = 0; r < 4; r++) accO[nf][r] = 0.f;
    float accL[4] = {0.f, 0.f, 0.f, 0.f};
    const unsigned ONESB = 0x3C003C00u;
    const unsigned qB = sb + SQ + bRow * 144 + bHlf;

    for (int jt = 0; jt < 32; jt++) {
        const int cur = jt & 1;
        if (jt < 31) {
            stage_v(jt + 1, cur ^ 1);
            asm volatile("cp.async.commit_group;" ::: "memory");
            asm volatile("cp.async.wait_group 2;" ::: "memory");
        } else {
            asm volatile("cp.async.wait_group 1;" ::: "memory");
        }

        float accS[8][4];
        #pragma unroll
        for (int nf = 0; nf < 8; nf++)
            #pragma unroll
            for (int r = 0; r < 4; r++) accS[nf][r] = 0.f;

        const unsigned vB = sb + SV + cur * SV_BUF + bRow * 272 + bHlf;
        #pragma unroll
        for (int kk = 0; kk < 8; kk++) {
            unsigned bhf[4][4];
            #pragma unroll
            for (int g2 = 0; g2 < 4; g2++)
                ldsm4(bhf[g2], vB + g2 * (16 * 272) + kk * 32);
            #pragma unroll
            for (int nf = 0; nf < 8; nf++) {
                unsigned bb[2] = {bhf[nf >> 1][2 * (nf & 1)], bhf[nf >> 1][2 * (nf & 1) + 1]};
                mma_fp16(accS[nf], ahf[kk], bb);
            }
        }

        unsigned pa[4][4];
        #pragma unroll
        for (int kj = 0; kj < 4; kj++) {
            pa[kj][0] = h2ex2(packh2(accS[2 * kj][0], accS[2 * kj][1]));
            pa[kj][1] = h2ex2(packh2(accS[2 * kj][2], accS[2 * kj][3]));
            pa[kj][2] = h2ex2(packh2(accS[2 * kj + 1][0], accS[2 * kj + 1][1]));
            pa[kj][3] = h2ex2(packh2(accS[2 * kj + 1][2], accS[2 * kj + 1][3]));
        }

        {
            unsigned bb[2] = {ONESB, ONESB};
            #pragma unroll
            for (int kj = 0; kj < 4; kj++)
                mma_fp16(accL, pa[kj], bb);
        }

        if (jt < 31) {
            asm volatile("cp.async.wait_group 1;" ::: "memory");
        } else {
            asm volatile("cp.async.wait_group 0;" ::: "memory");
        }

        #pragma unroll
        for (int kj = 0; kj < 4; kj++) {
            unsigned qf[8][4];
            #pragma unroll
            for (int g2 = 0; g2 < 8; g2++)
                ldsm4(qf[g2], qB + g2 * (16 * 144) + kj * 32);
            #pragma unroll
            for (int nf = 0; nf < 16; nf++) {
                unsigned bb[2] = {qf[nf >> 1][2 * (nf & 1)], qf[nf >> 1][2 * (nf & 1) + 1]};
                mma_fp16(accO[nf], pa[kj], bb);
            }
        }

        __syncthreads();
        if (jt < 31) {
            stage_q(jt + 1);
            asm volatile("cp.async.commit_group;" ::: "memory");
        }
    }

    const float inv0 = 1.0f / accL[0], inv1 = 1.0f / accL[2];
    float* Ob = out + ((size_t)b * COUT + h * 128) * PDIM;
    const int ir0 = i0 + wrp * 16 + gid;
    #pragma unroll
    for (int nf = 0; nf < 16; nf++) {
        const int c = nf * 8 + 2 * tig;
        Ob[(size_t)c * PDIM + ir0]           = accO[nf][0] * inv0;
        Ob[(size_t)(c + 1) * PDIM + ir0]     = accO[nf][1] * inv0;
        Ob[(size_t)c * PDIM + ir0 + 8]       = accO[nf][2] * inv1;
        Ob[(size_t)(c + 1) * PDIM + ir0 + 8] = accO[nf][3] * inv1;
    }
}

// ---------------------------------------------------------------------------
extern "C" void kernel_launch(void* const* d_in, const int* in_sizes, int n_in,
                              void* d_out, int out_size)
{
    const float* x   = (const float*)d_in[0];
    const float* wq  = (const float*)d_in[1];
    const float* bq  = (const float*)d_in[2];
    const float* gw1 = (const float*)d_in[3];
    const float* gb1 = (const float*)d_in[4];
    const float* wk  = (const float*)d_in[5];
    const float* bk  = (const float*)d_in[6];
    const float* gw2 = (const float*)d_in[7];
    const float* gb2 = (const float*)d_in[8];
    const float* wv  = (const float*)d_in[9];
    const float* bv  = (const float*)d_in[10];
    const float* gw3 = (const float*)d_in[11];
    const float* gb3 = (const float*)d_in[12];
    float* out = (float*)d_out;

    static int smem_set = 0;
    if (!smem_set) {
        cudaFuncSetAttribute(flash_kernel,
                             cudaFuncAttributeMaxDynamicSharedMemorySize,
                             SMEM_BYTES);
        cudaFuncSetAttribute(qkv_gn_kernel,
                             cudaFuncAttributeMaxDynamicSharedMemorySize,
                             SMEM1_BYTES);
        smem_set = 1;
    }

    dim3 g1(NG, B_, 3);
    qkv_gn_kernel<<<g1, 256, SMEM1_BYTES>>>(x, wq, bq, gw1, gb1, wk, bk, gw2, gb2,
                                            wv, bv, gw3, gb3);

    dim3 gf(PDIM / 64, B_ * Hh);
    flash_kernel<<<gf, 128, SMEM_BYTES>>>(out);
}